// round 1
// baseline (speedup 1.0000x reference)
#include <cuda_runtime.h>
#include <math.h>
#include <stdint.h>

// ---------------------------------------------------------------------------
// GriffinTemporalBlock: B=16, T=1024, D=1024, H=4096
// Round 0 baseline: fp32 SIMT GEMM (128x128x8 tiles) + fused epilogues,
// conv/elementwise/scan kernels. Scratch in __device__ globals.
// ---------------------------------------------------------------------------

constexpr int B = 16;
constexpr int T = 1024;
constexpr int D = 1024;
constexpr int H = 4096;
constexpr int M = B * T;               // 16384 rows
constexpr float EPS = 1.1920929e-07f;
constexpr float C_EXP = 8.0f;

// ----- scratch (static device globals; no allocations) ---------------------
__device__ float  g_normed[(size_t)M * D];
__device__ float  g_b1   [(size_t)M * D];
__device__ float  g_conv [(size_t)M * D];
__device__ float  g_r    [(size_t)M * D];
__device__ float  g_i    [(size_t)M * D];
__device__ float2 g_au   [(size_t)M * D];
__device__ float  g_b1out[(size_t)M * D];
__device__ float  g_b2   [(size_t)M * D];
__device__ float  g_x1   [(size_t)M * D];
__device__ float  g_n2   [(size_t)M * D];
__device__ float  g_g    [(size_t)M * H];   // gelu(n2@Wg^T), then act = that * (n2@Wu^T)

// ---------------------------------------------------------------------------
// RMSNorm: one block per row of D=1024, 256 threads, float4 per thread.
// ---------------------------------------------------------------------------
__global__ void rmsnorm_kernel(const float* __restrict__ x,
                               const float* __restrict__ w,
                               float* __restrict__ out) {
    int row = blockIdx.x;
    int tid = threadIdx.x;
    const float4* xr = reinterpret_cast<const float4*>(x + (size_t)row * D);
    float4 v = xr[tid];
    float s = v.x * v.x + v.y * v.y + v.z * v.z + v.w * v.w;
    #pragma unroll
    for (int o = 16; o > 0; o >>= 1) s += __shfl_xor_sync(0xffffffffu, s, o);
    __shared__ float sm[8];
    if ((tid & 31) == 0) sm[tid >> 5] = s;
    __syncthreads();
    float tot = 0.f;
    #pragma unroll
    for (int i = 0; i < 8; i++) tot += sm[i];
    float scale = rsqrtf(tot * (1.0f / D) + EPS);
    const float4* wr = reinterpret_cast<const float4*>(w);
    float4 wv = wr[tid];
    float4 o;
    o.x = v.x * scale * wv.x;
    o.y = v.y * scale * wv.y;
    o.z = v.z * scale * wv.z;
    o.w = v.w * scale * wv.w;
    reinterpret_cast<float4*>(out + (size_t)row * D)[tid] = o;
}

// ---------------------------------------------------------------------------
// Generic NT GEMM: C[m,n] = epi( sum_k A[m,k]*(A2?A2[m,k]:1)*W[n,k] + bias[n] )
// then RESOP with res[m,n].  A: MxK row-major. W: NxK row-major.
// BM=BN=128, BK=8, 256 threads, 8x8 per-thread microtile.
// ACT: 0 none, 1 sigmoid, 2 gelu(exact).  RESOP: 0 none, 1 add, 2 mul.
// ---------------------------------------------------------------------------
__device__ __forceinline__ float act_sigmoid(float x) { return 1.0f / (1.0f + expf(-x)); }
__device__ __forceinline__ float act_gelu(float x)    { return 0.5f * x * (1.0f + erff(x * 0.70710678118654752f)); }

template <int ACT, int RESOP, bool HAS_BIAS, bool HAS_A2>
__global__ void __launch_bounds__(256)
gemm_nt(const float* __restrict__ A, const float* __restrict__ A2,
        const float* __restrict__ W, const float* __restrict__ bias,
        const float* __restrict__ res, float* __restrict__ C,
        int N, int K) {
    __shared__ float As[8][128];
    __shared__ float Bs[8][128];

    int tid  = threadIdx.x;
    int lrow = tid >> 1;            // 0..127
    int lcol = (tid & 1) << 2;      // 0 or 4

    const float* Ap  = A + (size_t)(blockIdx.y * 128 + lrow) * K + lcol;
    const float* A2p = HAS_A2 ? (A2 + (size_t)(blockIdx.y * 128 + lrow) * K + lcol) : nullptr;
    const float* Bp  = W + (size_t)(blockIdx.x * 128 + lrow) * K + lcol;

    int tx = tid & 15;              // N direction
    int ty = tid >> 4;              // M direction

    float acc[8][8];
    #pragma unroll
    for (int i = 0; i < 8; i++)
        #pragma unroll
        for (int j = 0; j < 8; j++) acc[i][j] = 0.f;

    for (int k0 = 0; k0 < K; k0 += 8) {
        float4 av = *reinterpret_cast<const float4*>(Ap + k0);
        float4 bv = *reinterpret_cast<const float4*>(Bp + k0);
        if (HAS_A2) {
            float4 a2 = *reinterpret_cast<const float4*>(A2p + k0);
            av.x *= a2.x; av.y *= a2.y; av.z *= a2.z; av.w *= a2.w;
        }
        As[lcol + 0][lrow] = av.x;
        As[lcol + 1][lrow] = av.y;
        As[lcol + 2][lrow] = av.z;
        As[lcol + 3][lrow] = av.w;
        Bs[lcol + 0][lrow] = bv.x;
        Bs[lcol + 1][lrow] = bv.y;
        Bs[lcol + 2][lrow] = bv.z;
        Bs[lcol + 3][lrow] = bv.w;
        __syncthreads();

        #pragma unroll
        for (int kk = 0; kk < 8; kk++) {
            float4 a0 = *reinterpret_cast<const float4*>(&As[kk][ty * 8]);
            float4 a1 = *reinterpret_cast<const float4*>(&As[kk][ty * 8 + 4]);
            float4 b0 = *reinterpret_cast<const float4*>(&Bs[kk][tx * 8]);
            float4 b1 = *reinterpret_cast<const float4*>(&Bs[kk][tx * 8 + 4]);
            float ar[8] = {a0.x, a0.y, a0.z, a0.w, a1.x, a1.y, a1.z, a1.w};
            float br[8] = {b0.x, b0.y, b0.z, b0.w, b1.x, b1.y, b1.z, b1.w};
            #pragma unroll
            for (int i = 0; i < 8; i++)
                #pragma unroll
                for (int j = 0; j < 8; j++)
                    acc[i][j] = fmaf(ar[i], br[j], acc[i][j]);
        }
        __syncthreads();
    }

    int crow0 = blockIdx.y * 128 + ty * 8;
    int ccol0 = blockIdx.x * 128 + tx * 8;
    #pragma unroll
    for (int i = 0; i < 8; i++) {
        #pragma unroll
        for (int j = 0; j < 8; j++) {
            float v = acc[i][j];
            if (HAS_BIAS) v += bias[ccol0 + j];
            if (ACT == 1) v = act_sigmoid(v);
            if (ACT == 2) v = act_gelu(v);
            size_t idx = (size_t)(crow0 + i) * N + (ccol0 + j);
            if (RESOP == 1) v += res[idx];
            if (RESOP == 2) v *= res[idx];
            C[idx] = v;
        }
    }
}

// ---------------------------------------------------------------------------
// Depthwise causal conv over time, K=4, with conv_buf history (3 steps).
// b1_conv[b,t,d] = conv_b[d] + sum_k padded[b,t+k,d]*conv_w[d,k]
// padded[j] = conv_buf[b,j] if j<3 else b1[b,j-3]
// ---------------------------------------------------------------------------
__global__ void conv_kernel(const float* __restrict__ conv_buf,
                            const float* __restrict__ conv_w,
                            const float* __restrict__ conv_b) {
    size_t g = (size_t)blockIdx.x * blockDim.x + threadIdx.x;
    int d = (int)(g % D);
    int m = (int)(g / D);
    int b = m / T;
    int t = m % T;
    float4 cw = reinterpret_cast<const float4*>(conv_w)[d];
    float wk[4] = {cw.x, cw.y, cw.z, cw.w};
    float acc = conv_b[d];
    #pragma unroll
    for (int k = 0; k < 4; k++) {
        int j = t + k;
        float src = (j < 3) ? conv_buf[((size_t)b * 3 + j) * D + d]
                            : g_b1[((size_t)b * T + (j - 3)) * D + d];
        acc = fmaf(src, wk[k], acc);
    }
    g_conv[g] = acc;
}

// new_conv_buf = b1[:, T-3:T, :]
__global__ void convbuf_out_kernel(float* __restrict__ out) {
    int idx = blockIdx.x * blockDim.x + threadIdx.x;   // B*3*D = 49152
    int d = idx % D;
    int j = (idx / D) % 3;
    int b = idx / (3 * D);
    out[idx] = g_b1[((size_t)b * T + (T - 3 + j)) * D + d];
}

// ---------------------------------------------------------------------------
// a = exp(C_EXP * r * log_sigmoid(log_lambda[d]));
// gate = sqrt(max((1-a)(1+a), 1e-6)); u = gate * (i * conv)
// ---------------------------------------------------------------------------
__global__ void au_kernel(const float* __restrict__ log_lambda) {
    size_t g = (size_t)blockIdx.x * blockDim.x + threadIdx.x;
    int d = (int)(g % D);
    float ll = log_lambda[d];
    float ls = -log1pf(expf(-ll));          // log_sigmoid(ll), ll >= 0
    float r = g_r[g];
    float i = g_i[g];
    float c = g_conv[g];
    float a = expf(C_EXP * r * ls);
    float gate = sqrtf(fmaxf((1.0f - a) * (1.0f + a), 1e-6f));
    g_au[g] = make_float2(a, gate * (i * c));
}

// ---------------------------------------------------------------------------
// Sequential scan: h = a*h + u over T per (b,d) chain. 16384 chains.
// ---------------------------------------------------------------------------
__global__ void scan_kernel(const float* __restrict__ h0, float* __restrict__ out_h) {
    int g = blockIdx.x * blockDim.x + threadIdx.x;   // 0..B*D
    int d = g % D;
    int b = g / D;
    float h = h0[g];
    const float2* au = g_au + (size_t)b * T * D + d;
    float* o = g_b1out + (size_t)b * T * D + d;
    #pragma unroll 4
    for (int t = 0; t < T; t++) {
        float2 v = au[(size_t)t * D];
        h = fmaf(v.x, h, v.y);
        o[(size_t)t * D] = h;
    }
    out_h[g] = h;
}

// ---------------------------------------------------------------------------
// Launch
// ---------------------------------------------------------------------------
extern "C" void kernel_launch(void* const* d_in, const int* in_sizes, int n_in,
                              void* d_out, int out_size) {
    const float* x_seq     = (const float*)d_in[0];
    const float* h0        = (const float*)d_in[1];
    const float* conv_buf  = (const float*)d_in[2];
    const float* norm1_w   = (const float*)d_in[3];
    const float* W1        = (const float*)d_in[4];
    const float* conv_w    = (const float*)d_in[5];
    const float* conv_b    = (const float*)d_in[6];
    const float* Wa        = (const float*)d_in[7];
    const float* ba        = (const float*)d_in[8];
    const float* Wx        = (const float*)d_in[9];
    const float* bx        = (const float*)d_in[10];
    const float* log_lambda= (const float*)d_in[11];
    const float* W2        = (const float*)d_in[12];
    const float* Wout      = (const float*)d_in[13];
    const float* norm2_w   = (const float*)d_in[14];
    const float* Wg        = (const float*)d_in[15];
    const float* Wu        = (const float*)d_in[16];
    const float* Wo        = (const float*)d_in[17];

    float* out_x2 = (float*)d_out;
    float* out_h  = out_x2 + (size_t)M * D;          // 16777216
    float* out_cb = out_h + (size_t)B * D;           // + 16384

    float *p_normed, *p_b1, *p_conv, *p_r, *p_i, *p_b1out, *p_b2, *p_x1, *p_n2, *p_g;
    cudaGetSymbolAddress((void**)&p_normed, g_normed);
    cudaGetSymbolAddress((void**)&p_b1,     g_b1);
    cudaGetSymbolAddress((void**)&p_conv,   g_conv);
    cudaGetSymbolAddress((void**)&p_r,      g_r);
    cudaGetSymbolAddress((void**)&p_i,      g_i);
    cudaGetSymbolAddress((void**)&p_b1out,  g_b1out);
    cudaGetSymbolAddress((void**)&p_b2,     g_b2);
    cudaGetSymbolAddress((void**)&p_x1,     g_x1);
    cudaGetSymbolAddress((void**)&p_n2,     g_n2);
    cudaGetSymbolAddress((void**)&p_g,      g_g);

    dim3 gemmGridD(D / 128, M / 128);   // (8, 128)
    dim3 gemmGridH(H / 128, M / 128);   // (32, 128)
    int ewBlocks = (int)(((size_t)M * D) / 256);

    // 1. normed = rmsnorm(x_seq, norm1_w)
    rmsnorm_kernel<<<M, 256>>>(x_seq, norm1_w, p_normed);

    // 2. b1 = normed @ W1^T
    gemm_nt<0, 0, false, false><<<gemmGridD, 256>>>(p_normed, nullptr, W1, nullptr, nullptr, p_b1, D, D);

    // 3. depthwise conv + conv_buf output
    conv_kernel<<<ewBlocks, 256>>>(conv_buf, conv_w, conv_b);
    convbuf_out_kernel<<<(B * 3 * D) / 256, 256>>>(out_cb);

    // 4. r = sigmoid(conv @ Wa^T + ba), i = sigmoid(conv @ Wx^T + bx)
    gemm_nt<1, 0, true, false><<<gemmGridD, 256>>>(p_conv, nullptr, Wa, ba, nullptr, p_r, D, D);
    gemm_nt<1, 0, true, false><<<gemmGridD, 256>>>(p_conv, nullptr, Wx, bx, nullptr, p_i, D, D);

    // 5. a/u elementwise
    au_kernel<<<ewBlocks, 256>>>(log_lambda);

    // 6. scan -> b1out, new_h
    scan_kernel<<<(B * D) / 256, 256>>>(h0, out_h);

    // 7. b2 = gelu(normed @ W2^T)
    gemm_nt<2, 0, false, false><<<gemmGridD, 256>>>(p_normed, nullptr, W2, nullptr, nullptr, p_b2, D, D);

    // 8+9. x1 = x_seq + (b1out * b2) @ Wout^T
    gemm_nt<0, 1, false, true><<<gemmGridD, 256>>>(p_b1out, p_b2, Wout, nullptr, x_seq, p_x1, D, D);

    // 10. n2 = rmsnorm(x1, norm2_w)
    rmsnorm_kernel<<<M, 256>>>(p_x1, norm2_w, p_n2);

    // 11. g = gelu(n2 @ Wg^T); act = g * (n2 @ Wu^T)  (in-place into g_g)
    gemm_nt<2, 0, false, false><<<gemmGridH, 256>>>(p_n2, nullptr, Wg, nullptr, nullptr, p_g, H, D);
    gemm_nt<0, 2, false, false><<<gemmGridH, 256>>>(p_n2, nullptr, Wu, nullptr, p_g, p_g, H, D);

    // 12. x2 = x1 + act @ Wo^T
    gemm_nt<0, 1, false, false><<<gemmGridD, 256>>>(p_g, nullptr, Wo, nullptr, p_x1, out_x2, D, H);
}

// round 4
// speedup vs baseline: 2.3475x; 2.3475x over previous
#include <cuda_runtime.h>
#include <cuda_bf16.h>
#include <math.h>
#include <stdint.h>

// ---------------------------------------------------------------------------
// GriffinTemporalBlock on GB300 (sm_103 plain target — no tcgen05 available).
// GEMMs via mma.sync.m16n8k16 bf16 with 3-term error compensation:
//   A = Ahi + Alo, B = Bhi + Blo (bf16 splits of fp32)
//   acc += Ahi*Bhi + Ahi*Blo + Alo*Bhi      (lo*lo ~ 2^-18, dropped)
// B=16, T=1024, D=1024, H=4096.
// ---------------------------------------------------------------------------

constexpr int B = 16;
constexpr int T = 1024;
constexpr int D = 1024;
constexpr int H = 4096;
constexpr int M = B * T;               // 16384
constexpr float EPS = 1.1920929e-07f;
constexpr float C_EXP = 8.0f;

// ----- scratch (static device globals) -------------------------------------
__device__ __nv_bfloat16 g_normed_p[(size_t)M * 2 * D];
__device__ __nv_bfloat16 g_conv_p  [(size_t)M * 2 * D];
__device__ __nv_bfloat16 g_prod_p  [(size_t)M * 2 * D];
__device__ __nv_bfloat16 g_n2_p    [(size_t)M * 2 * D];
__device__ __nv_bfloat16 g_act_p   [(size_t)M * 2 * H];

__device__ __nv_bfloat16 g_w1p  [(size_t)D * 2 * D];
__device__ __nv_bfloat16 g_wap  [(size_t)D * 2 * D];
__device__ __nv_bfloat16 g_wxp  [(size_t)D * 2 * D];
__device__ __nv_bfloat16 g_w2p  [(size_t)D * 2 * D];
__device__ __nv_bfloat16 g_woutp[(size_t)D * 2 * D];
__device__ __nv_bfloat16 g_wgp  [(size_t)H * 2 * D];
__device__ __nv_bfloat16 g_wup  [(size_t)H * 2 * D];
__device__ __nv_bfloat16 g_wop  [(size_t)D * 2 * H];

__device__ float  g_b1   [(size_t)M * D];
__device__ float  g_conv [(size_t)M * D];
__device__ float  g_r    [(size_t)M * D];
__device__ float  g_i    [(size_t)M * D];
__device__ float2 g_au   [(size_t)M * D];
__device__ float  g_b1out[(size_t)M * D];
__device__ float  g_b2   [(size_t)M * D];
__device__ float  g_x1   [(size_t)M * D];
__device__ float  g_g    [(size_t)M * H];

// ---------------------------------------------------------------------------
// helpers
// ---------------------------------------------------------------------------
__device__ __forceinline__ uint32_t smem_u32(const void* p) {
    uint32_t a;
    asm("{ .reg .u64 t; cvta.to.shared.u64 t, %1; cvt.u32.u64 %0, t; }"
        : "=r"(a) : "l"(p));
    return a;
}

#define CP_ASYNC16(dst, src) \
    asm volatile("cp.async.cg.shared.global [%0], [%1], 16;" :: "r"(dst), "l"(src) : "memory")
#define CP_COMMIT() asm volatile("cp.async.commit_group;" ::: "memory")
#define CP_WAIT2()  asm volatile("cp.async.wait_group 2;" ::: "memory")

#define LDSM4(R, addr) \
    asm volatile("ldmatrix.sync.aligned.m8n8.x4.shared.b16 {%0,%1,%2,%3}, [%4];" \
        : "=r"((R)[0]), "=r"((R)[1]), "=r"((R)[2]), "=r"((R)[3]) : "r"(addr))

#define MMA_BF16(d, a, b0v, b1v) \
    asm volatile("mma.sync.aligned.m16n8k16.row.col.f32.bf16.bf16.f32 " \
        "{%0,%1,%2,%3}, {%4,%5,%6,%7}, {%8,%9}, {%0,%1,%2,%3};" \
        : "+f"((d)[0]), "+f"((d)[1]), "+f"((d)[2]), "+f"((d)[3]) \
        : "r"((a)[0]), "r"((a)[1]), "r"((a)[2]), "r"((a)[3]), "r"(b0v), "r"(b1v))

__device__ __forceinline__ void split_bf(float x, __nv_bfloat16& h, __nv_bfloat16& l) {
    h = __float2bfloat16(x);
    l = __float2bfloat16(x - __bfloat162float(h));
}

__device__ __forceinline__ float act_sigmoid(float x) { return 1.0f / (1.0f + expf(-x)); }
__device__ __forceinline__ float act_gelu(float x)    { return 0.5f * x * (1.0f + erff(x * 0.70710678118654752f)); }

// ---------------------------------------------------------------------------
// mma.sync GEMM: C[m,n] = epi( A[m,:] . W[n,:] ), pair inputs.
// A pair layout [m][2K]: hi at k, lo at K+k.  W same.
// Block 128x128, BK=32, 256 threads (8 warps, 64x32 warp tiles),
// 4-stage cp.async pipeline, SW128-swizzled smem tiles (128B rows):
//   stage tile: 128 rows x 8 chunks(16B): chunks 0-3 = hi k0..k0+31,
//               chunks 4-7 = lo.  A tile 16KB + B tile 16KB per stage.
// ---------------------------------------------------------------------------
constexpr int STAGE_BYTES = 32768;                 // A(16K) + B(16K)
constexpr int SMEM_BYTES  = 4 * STAGE_BYTES;       // 131072

__device__ __forceinline__ void produce_stage(uint32_t sb,
        const __nv_bfloat16* Ab, const __nv_bfloat16* Bb,
        int K, int j, int tid) {
    int k0 = j * 32;
    int ld = 2 * K;
    uint32_t stage = sb + (uint32_t)(j & 3) * STAGE_BYTES;
    #pragma unroll
    for (int ch = 0; ch < 8; ch++) {
        int c = tid + (ch << 8);                   // 0..2047
        int r = (c & 1023) >> 3;                   // row 0..127
        int q = c & 7;                             // 16B chunk 0..7
        int koff = (q < 4) ? (k0 + q * 8) : (K + k0 + (q - 4) * 8);
        const __nv_bfloat16* g = ((c < 1024) ? Ab : Bb) + (size_t)r * ld + koff;
        uint32_t off = (uint32_t)(r * 128 + q * 16);
        off ^= (off >> 3) & 0x70;                  // SW128
        uint32_t s = stage + ((c < 1024) ? 0u : 16384u) + off;
        CP_ASYNC16(s, g);
    }
    CP_COMMIT();
}

template <int ACT, int RESOP, bool BIAS, bool OUTPAIR>
__global__ void __launch_bounds__(256)
gemm_mma(const __nv_bfloat16* __restrict__ A, const __nv_bfloat16* __restrict__ Bw,
         int K, int iters,
         const float* __restrict__ bias, const float* __restrict__ res,
         float* __restrict__ Cf, __nv_bfloat16* __restrict__ Cp,
         int N, int pairK) {
    extern __shared__ char smem[];
    uint32_t sb = smem_u32(smem);
    int tid = threadIdx.x;
    int wid = tid >> 5, lid = tid & 31;
    int wm = wid >> 2, wn = wid & 3;               // warp grid 2x4
    int lr = lid & 15, lc = lid >> 4;

    int bm = blockIdx.y, bn = blockIdx.x;
    const __nv_bfloat16* Ab = A  + (size_t)(bm * 128) * (2 * K);
    const __nv_bfloat16* Bb = Bw + (size_t)(bn * 128) * (2 * K);

    float acc[4][4][4];
    #pragma unroll
    for (int i = 0; i < 4; i++)
        #pragma unroll
        for (int j = 0; j < 4; j++)
            #pragma unroll
            for (int q = 0; q < 4; q++) acc[i][j][q] = 0.f;

    produce_stage(sb, Ab, Bb, K, 0, tid);
    produce_stage(sb, Ab, Bb, K, 1, tid);
    produce_stage(sb, Ab, Bb, K, 2, tid);

    for (int it = 0; it < iters; ++it) {
        CP_WAIT2();
        __syncthreads();
        uint32_t sa  = sb + (uint32_t)(it & 3) * STAGE_BYTES;
        uint32_t sbt = sa + 16384;

        #pragma unroll
        for (int kk = 0; kk < 2; kk++) {
            uint32_t a[2][4][4];                    // [part][mf][reg]
            uint32_t bb[2][2][4];                   // [part][nf2][reg]
            #pragma unroll
            for (int p = 0; p < 2; p++) {
                int chunk = p * 4 + kk * 2 + lc;
                #pragma unroll
                for (int mf = 0; mf < 4; mf++) {
                    int row = wm * 64 + mf * 16 + lr;
                    uint32_t addr = sa + (uint32_t)(row * 128)
                                  + (uint32_t)((chunk ^ (row & 7)) * 16);
                    LDSM4(a[p][mf], addr);
                }
                #pragma unroll
                for (int nf2 = 0; nf2 < 2; nf2++) {
                    int row = wn * 32 + nf2 * 16 + lr;
                    uint32_t addr = sbt + (uint32_t)(row * 128)
                                  + (uint32_t)((chunk ^ (row & 7)) * 16);
                    LDSM4(bb[p][nf2], addr);
                }
            }
            #pragma unroll
            for (int mf = 0; mf < 4; mf++) {
                #pragma unroll
                for (int nf = 0; nf < 4; nf++) {
                    int n2 = nf >> 1, sel = nf & 1;
                    MMA_BF16(acc[mf][nf], a[0][mf], bb[0][n2][sel], bb[0][n2][2 + sel]); // hi*hi
                    MMA_BF16(acc[mf][nf], a[0][mf], bb[1][n2][sel], bb[1][n2][2 + sel]); // hi*lo
                    MMA_BF16(acc[mf][nf], a[1][mf], bb[0][n2][sel], bb[0][n2][2 + sel]); // lo*hi
                }
            }
        }
        __syncthreads();
        int j = it + 3;
        if (j < iters) produce_stage(sb, Ab, Bb, K, j, tid);
        else           CP_COMMIT();
    }

    // epilogue: c fragment -> lane holds (row=l>>2 [+8], cols (l&3)*2, +1)
    int er = lid >> 2;
    int ec = (lid & 3) * 2;
    #pragma unroll
    for (int mf = 0; mf < 4; mf++) {
        #pragma unroll
        for (int nf = 0; nf < 4; nf++) {
            float* cc = acc[mf][nf];
            int row0 = bm * 128 + wm * 64 + mf * 16 + er;
            int col  = bn * 128 + wn * 32 + nf * 8 + ec;
            #pragma unroll
            for (int half = 0; half < 2; half++) {
                int row = row0 + half * 8;
                float v0 = cc[half * 2 + 0];
                float v1 = cc[half * 2 + 1];
                if (BIAS) { v0 += bias[col]; v1 += bias[col + 1]; }
                if (ACT == 1) { v0 = act_sigmoid(v0); v1 = act_sigmoid(v1); }
                if (ACT == 2) { v0 = act_gelu(v0);    v1 = act_gelu(v1); }
                if (RESOP == 1) {
                    float2 rv = *reinterpret_cast<const float2*>(res + (size_t)row * N + col);
                    v0 += rv.x; v1 += rv.y;
                }
                if (RESOP == 2) {
                    float2 rv = *reinterpret_cast<const float2*>(res + (size_t)row * N + col);
                    v0 *= rv.x; v1 *= rv.y;
                }
                if (OUTPAIR) {
                    __nv_bfloat16 h0, l0, h1, l1;
                    split_bf(v0, h0, l0);
                    split_bf(v1, h1, l1);
                    *reinterpret_cast<__nv_bfloat162*>(
                        Cp + (size_t)row * 2 * pairK + col) = __nv_bfloat162(h0, h1);
                    *reinterpret_cast<__nv_bfloat162*>(
                        Cp + (size_t)row * 2 * pairK + pairK + col) = __nv_bfloat162(l0, l1);
                } else {
                    *reinterpret_cast<float2*>(Cf + (size_t)row * N + col) = make_float2(v0, v1);
                }
            }
        }
    }
}

// ---------------------------------------------------------------------------
// RMSNorm -> bf16 pair output ([row][2D]: hi cols 0..D-1, lo cols D..2D-1)
// ---------------------------------------------------------------------------
__global__ void rmsnorm_pair_kernel(const float* __restrict__ x,
                                    const float* __restrict__ w,
                                    __nv_bfloat16* __restrict__ outp) {
    int row = blockIdx.x;
    int tid = threadIdx.x;
    const float4* xr = reinterpret_cast<const float4*>(x + (size_t)row * D);
    float4 v = xr[tid];
    float s = v.x * v.x + v.y * v.y + v.z * v.z + v.w * v.w;
    #pragma unroll
    for (int o = 16; o > 0; o >>= 1) s += __shfl_xor_sync(0xffffffffu, s, o);
    __shared__ float sm[8];
    if ((tid & 31) == 0) sm[tid >> 5] = s;
    __syncthreads();
    float tot = 0.f;
    #pragma unroll
    for (int i = 0; i < 8; i++) tot += sm[i];
    float scale = rsqrtf(tot * (1.0f / D) + EPS);
    float4 wv = reinterpret_cast<const float4*>(w)[tid];
    float o[4] = { v.x * scale * wv.x, v.y * scale * wv.y,
                   v.z * scale * wv.z, v.w * scale * wv.w };
    __nv_bfloat16 h[4], l[4];
    #pragma unroll
    for (int i = 0; i < 4; i++) split_bf(o[i], h[i], l[i]);
    __nv_bfloat162* hp = reinterpret_cast<__nv_bfloat162*>(outp + (size_t)row * 2 * D + tid * 4);
    __nv_bfloat162* lp = reinterpret_cast<__nv_bfloat162*>(outp + (size_t)row * 2 * D + D + tid * 4);
    hp[0] = __nv_bfloat162(h[0], h[1]); hp[1] = __nv_bfloat162(h[2], h[3]);
    lp[0] = __nv_bfloat162(l[0], l[1]); lp[1] = __nv_bfloat162(l[2], l[3]);
}

// Weight fp32 [N][K] -> bf16 pair [N][2K]
__global__ void wpair_kernel(const float* __restrict__ W,
                             __nv_bfloat16* __restrict__ out, int K) {
    size_t g = (size_t)blockIdx.x * blockDim.x + threadIdx.x;
    int k = (int)(g % K);
    size_t n = g / K;
    __nv_bfloat16 h, l;
    split_bf(W[g], h, l);
    out[n * 2 * K + k] = h;
    out[n * 2 * K + K + k] = l;
}

// ---------------------------------------------------------------------------
// Depthwise causal conv (K=4) -> fp32 conv + bf16 pair
// ---------------------------------------------------------------------------
__global__ void conv_kernel(const float* __restrict__ conv_buf,
                            const float* __restrict__ conv_w,
                            const float* __restrict__ conv_b) {
    size_t g = (size_t)blockIdx.x * blockDim.x + threadIdx.x;
    int d = (int)(g % D);
    int m = (int)(g / D);
    int b = m / T;
    int t = m % T;
    float4 cw = reinterpret_cast<const float4*>(conv_w)[d];
    float wk[4] = { cw.x, cw.y, cw.z, cw.w };
    float acc = conv_b[d];
    #pragma unroll
    for (int k = 0; k < 4; k++) {
        int j = t + k;
        float src = (j < 3) ? conv_buf[((size_t)b * 3 + j) * D + d]
                            : g_b1[((size_t)b * T + (j - 3)) * D + d];
        acc = fmaf(src, wk[k], acc);
    }
    g_conv[g] = acc;
    __nv_bfloat16 h, l;
    split_bf(acc, h, l);
    g_conv_p[(size_t)m * 2 * D + d] = h;
    g_conv_p[(size_t)m * 2 * D + D + d] = l;
}

__global__ void convbuf_out_kernel(float* __restrict__ out) {
    int idx = blockIdx.x * blockDim.x + threadIdx.x;
    int d = idx % D;
    int j = (idx / D) % 3;
    int b = idx / (3 * D);
    out[idx] = g_b1[((size_t)b * T + (T - 3 + j)) * D + d];
}

__global__ void au_kernel(const float* __restrict__ log_lambda) {
    size_t g = (size_t)blockIdx.x * blockDim.x + threadIdx.x;
    int d = (int)(g % D);
    float ll = log_lambda[d];
    float ls = -log1pf(expf(-ll));
    float r = g_r[g];
    float i = g_i[g];
    float c = g_conv[g];
    float a = expf(C_EXP * r * ls);
    float gate = sqrtf(fmaxf((1.0f - a) * (1.0f + a), 1e-6f));
    g_au[g] = make_float2(a, gate * (i * c));
}

__global__ void scan_kernel(const float* __restrict__ h0, float* __restrict__ out_h) {
    int g = blockIdx.x * blockDim.x + threadIdx.x;
    int d = g % D;
    int b = g / D;
    float h = h0[g];
    const float2* au = g_au + (size_t)b * T * D + d;
    float* o = g_b1out + (size_t)b * T * D + d;
    #pragma unroll 4
    for (int t = 0; t < T; t++) {
        float2 v = au[(size_t)t * D];
        h = fmaf(v.x, h, v.y);
        o[(size_t)t * D] = h;
    }
    out_h[g] = h;
}

// prod = b1out * b2 -> bf16 pair
__global__ void prod_pair_kernel() {
    size_t g = (size_t)blockIdx.x * blockDim.x + threadIdx.x;
    int d = (int)(g % D);
    size_t m = g / D;
    float p = g_b1out[g] * g_b2[g];
    __nv_bfloat16 h, l;
    split_bf(p, h, l);
    g_prod_p[m * 2 * D + d] = h;
    g_prod_p[m * 2 * D + D + d] = l;
}

// ---------------------------------------------------------------------------
// Launch
// ---------------------------------------------------------------------------
extern "C" void kernel_launch(void* const* d_in, const int* in_sizes, int n_in,
                              void* d_out, int out_size) {
    const float* x_seq      = (const float*)d_in[0];
    const float* h0         = (const float*)d_in[1];
    const float* conv_buf   = (const float*)d_in[2];
    const float* norm1_w    = (const float*)d_in[3];
    const float* W1         = (const float*)d_in[4];
    const float* conv_w     = (const float*)d_in[5];
    const float* conv_b     = (const float*)d_in[6];
    const float* Wa         = (const float*)d_in[7];
    const float* ba         = (const float*)d_in[8];
    const float* Wx         = (const float*)d_in[9];
    const float* bx         = (const float*)d_in[10];
    const float* log_lambda = (const float*)d_in[11];
    const float* W2         = (const float*)d_in[12];
    const float* Wout       = (const float*)d_in[13];
    const float* norm2_w    = (const float*)d_in[14];
    const float* Wg         = (const float*)d_in[15];
    const float* Wu         = (const float*)d_in[16];
    const float* Wo         = (const float*)d_in[17];

    float* out_x2 = (float*)d_out;
    float* out_h  = out_x2 + (size_t)M * D;
    float* out_cb = out_h + (size_t)B * D;

    __nv_bfloat16 *p_normed, *p_convp, *p_prodp, *p_n2p, *p_actp;
    __nv_bfloat16 *p_w1, *p_wa, *p_wx, *p_w2, *p_wout, *p_wg, *p_wu, *p_wo;
    float *p_b1, *p_r, *p_i, *p_b1out, *p_b2, *p_x1, *p_g;
    cudaGetSymbolAddress((void**)&p_normed, g_normed_p);
    cudaGetSymbolAddress((void**)&p_convp,  g_conv_p);
    cudaGetSymbolAddress((void**)&p_prodp,  g_prod_p);
    cudaGetSymbolAddress((void**)&p_n2p,    g_n2_p);
    cudaGetSymbolAddress((void**)&p_actp,   g_act_p);
    cudaGetSymbolAddress((void**)&p_w1,     g_w1p);
    cudaGetSymbolAddress((void**)&p_wa,     g_wap);
    cudaGetSymbolAddress((void**)&p_wx,     g_wxp);
    cudaGetSymbolAddress((void**)&p_w2,     g_w2p);
    cudaGetSymbolAddress((void**)&p_wout,   g_woutp);
    cudaGetSymbolAddress((void**)&p_wg,     g_wgp);
    cudaGetSymbolAddress((void**)&p_wu,     g_wup);
    cudaGetSymbolAddress((void**)&p_wo,     g_wop);
    cudaGetSymbolAddress((void**)&p_b1,     g_b1);
    cudaGetSymbolAddress((void**)&p_r,      g_r);
    cudaGetSymbolAddress((void**)&p_i,      g_i);
    cudaGetSymbolAddress((void**)&p_b1out,  g_b1out);
    cudaGetSymbolAddress((void**)&p_b2,     g_b2);
    cudaGetSymbolAddress((void**)&p_x1,     g_x1);
    cudaGetSymbolAddress((void**)&p_g,      g_g);

    auto kPlain  = gemm_mma<0, 0, false, false>;
    auto kSig    = gemm_mma<1, 0, true,  false>;
    auto kGelu   = gemm_mma<2, 0, false, false>;
    auto kAdd    = gemm_mma<0, 1, false, false>;
    auto kMulPr  = gemm_mma<0, 2, false, true>;
    cudaFuncSetAttribute(kPlain, cudaFuncAttributeMaxDynamicSharedMemorySize, SMEM_BYTES);
    cudaFuncSetAttribute(kSig,   cudaFuncAttributeMaxDynamicSharedMemorySize, SMEM_BYTES);
    cudaFuncSetAttribute(kGelu,  cudaFuncAttributeMaxDynamicSharedMemorySize, SMEM_BYTES);
    cudaFuncSetAttribute(kAdd,   cudaFuncAttributeMaxDynamicSharedMemorySize, SMEM_BYTES);
    cudaFuncSetAttribute(kMulPr, cudaFuncAttributeMaxDynamicSharedMemorySize, SMEM_BYTES);

    dim3 gD(D / 128, M / 128);     // (8, 128)
    dim3 gH(H / 128, M / 128);     // (32, 128)
    int ewBlocks = (int)(((size_t)M * D) / 256);

    // weight pair conversions
    wpair_kernel<<<(D * D) / 256, 256>>>(W1,   p_w1,  D);
    wpair_kernel<<<(D * D) / 256, 256>>>(Wa,   p_wa,  D);
    wpair_kernel<<<(D * D) / 256, 256>>>(Wx,   p_wx,  D);
    wpair_kernel<<<(D * D) / 256, 256>>>(W2,   p_w2,  D);
    wpair_kernel<<<(D * D) / 256, 256>>>(Wout, p_wout, D);
    wpair_kernel<<<(H * D) / 256, 256>>>(Wg,   p_wg,  D);
    wpair_kernel<<<(H * D) / 256, 256>>>(Wu,   p_wu,  D);
    wpair_kernel<<<(D * H) / 256, 256>>>(Wo,   p_wo,  H);

    // 1. normed (pair)
    rmsnorm_pair_kernel<<<M, 256>>>(x_seq, norm1_w, p_normed);

    // 2. b1 = normed @ W1^T  (fp32 out)
    kPlain<<<gD, 256, SMEM_BYTES>>>(p_normed, p_w1, D, 32,
                                    nullptr, nullptr, p_b1, nullptr, D, 0);

    // 3. conv + conv_buf
    conv_kernel<<<ewBlocks, 256>>>(conv_buf, conv_w, conv_b);
    convbuf_out_kernel<<<(B * 3 * D) / 256, 256>>>(out_cb);

    // 4. r, i
    kSig<<<gD, 256, SMEM_BYTES>>>(p_convp, p_wa, D, 32,
                                  ba, nullptr, p_r, nullptr, D, 0);
    kSig<<<gD, 256, SMEM_BYTES>>>(p_convp, p_wx, D, 32,
                                  bx, nullptr, p_i, nullptr, D, 0);

    // 5-6. a/u + scan
    au_kernel<<<ewBlocks, 256>>>(log_lambda);
    scan_kernel<<<(B * D) / 256, 256>>>(h0, out_h);

    // 7. b2 = gelu(normed @ W2^T)
    kGelu<<<gD, 256, SMEM_BYTES>>>(p_normed, p_w2, D, 32,
                                   nullptr, nullptr, p_b2, nullptr, D, 0);

    // 8. prod pair; 9. x1 = x_seq + prod @ Wout^T
    prod_pair_kernel<<<ewBlocks, 256>>>();
    kAdd<<<gD, 256, SMEM_BYTES>>>(p_prodp, p_wout, D, 32,
                                  nullptr, x_seq, p_x1, nullptr, D, 0);

    // 10. n2 (pair)
    rmsnorm_pair_kernel<<<M, 256>>>(p_x1, norm2_w, p_n2p);

    // 11. g = gelu(n2 @ Wg^T); act = g * (n2 @ Wu^T) -> pair
    kGelu<<<gH, 256, SMEM_BYTES>>>(p_n2p, p_wg, D, 32,
                                   nullptr, nullptr, p_g, nullptr, H, 0);
    kMulPr<<<gH, 256, SMEM_BYTES>>>(p_n2p, p_wu, D, 32,
                                    nullptr, p_g, nullptr, p_actp, H, H);

    // 12. x2 = x1 + act @ Wo^T
    kAdd<<<gD, 256, SMEM_BYTES>>>(p_actp, p_wo, H, 128,
                                  nullptr, p_x1, out_x2, nullptr, D, 0);
}

// round 6
// speedup vs baseline: 3.3406x; 1.4231x over previous
#include <cuda_runtime.h>
#include <cuda_fp16.h>
#include <math.h>
#include <stdint.h>

// ---------------------------------------------------------------------------
// GriffinTemporalBlock on GB300 (classic mma.sync path; tcgen05 unavailable
// in this toolchain).  fp16 hi/lo split GEMMs:
//   2-term: acc += Ahi*Bhi + Alo*Bhi   (error = fp16 rounding of B ~2^-11)
//   3-term (Wa/Wx): + Ahi*Blo          (error ~2^-22)
// B=16, T=1024, D=1024, H=4096.
// ---------------------------------------------------------------------------

constexpr int B = 16;
constexpr int T = 1024;
constexpr int D = 1024;
constexpr int H = 4096;
constexpr int M = B * T;               // 16384
constexpr float EPS = 1.1920929e-07f;
constexpr float C_EXP = 8.0f;

// ----- scratch (static device globals) -------------------------------------
__device__ __half g_normed_p[(size_t)M * 2 * D];
__device__ __half g_conv_p  [(size_t)M * 2 * D];
__device__ __half g_prod_p  [(size_t)M * 2 * D];
__device__ __half g_n2_p    [(size_t)M * 2 * D];
__device__ __half g_act_p   [(size_t)M * 2 * H];

__device__ __half g_w1p  [(size_t)D * 2 * D];
__device__ __half g_wap  [(size_t)D * 2 * D];
__device__ __half g_wxp  [(size_t)D * 2 * D];
__device__ __half g_w2p  [(size_t)D * 2 * D];
__device__ __half g_woutp[(size_t)D * 2 * D];
__device__ __half g_wgp  [(size_t)H * 2 * D];
__device__ __half g_wup  [(size_t)H * 2 * D];
__device__ __half g_wop  [(size_t)D * 2 * H];

__device__ float  g_b1   [(size_t)M * D];
__device__ float  g_conv [(size_t)M * D];
__device__ float  g_r    [(size_t)M * D];
__device__ float  g_i    [(size_t)M * D];
__device__ float2 g_au   [(size_t)M * D];
__device__ float  g_b1out[(size_t)M * D];
__device__ float  g_b2   [(size_t)M * D];
__device__ float  g_x1   [(size_t)M * D];
__device__ float  g_g    [(size_t)M * H];

// ---------------------------------------------------------------------------
// helpers
// ---------------------------------------------------------------------------
__device__ __forceinline__ uint32_t smem_u32(const void* p) {
    uint32_t a;
    asm("{ .reg .u64 t; cvta.to.shared.u64 t, %1; cvt.u32.u64 %0, t; }"
        : "=r"(a) : "l"(p));
    return a;
}

#define CP_ASYNC16(dst, src) \
    asm volatile("cp.async.cg.shared.global [%0], [%1], 16;" :: "r"(dst), "l"(src) : "memory")
#define CP_COMMIT() asm volatile("cp.async.commit_group;" ::: "memory")
#define CP_WAIT2()  asm volatile("cp.async.wait_group 2;" ::: "memory")

#define LDSM4(R, addr) \
    asm volatile("ldmatrix.sync.aligned.m8n8.x4.shared.b16 {%0,%1,%2,%3}, [%4];" \
        : "=r"((R)[0]), "=r"((R)[1]), "=r"((R)[2]), "=r"((R)[3]) : "r"(addr))

#define MMA_F16(d, a, b0v, b1v) \
    asm volatile("mma.sync.aligned.m16n8k16.row.col.f32.f16.f16.f32 " \
        "{%0,%1,%2,%3}, {%4,%5,%6,%7}, {%8,%9}, {%0,%1,%2,%3};" \
        : "+f"((d)[0]), "+f"((d)[1]), "+f"((d)[2]), "+f"((d)[3]) \
        : "r"((a)[0]), "r"((a)[1]), "r"((a)[2]), "r"((a)[3]), "r"(b0v), "r"(b1v))

__device__ __forceinline__ void split_h(float x, __half& h, __half& l) {
    h = __float2half_rn(x);
    l = __float2half_rn(x - __half2float(h));
}

__device__ __forceinline__ float act_sigmoid(float x) { return 1.0f / (1.0f + expf(-x)); }
__device__ __forceinline__ float act_gelu(float x)    { return 0.5f * x * (1.0f + erff(x * 0.70710678118654752f)); }

// ---------------------------------------------------------------------------
// mma.sync GEMM, pair inputs ([row][2K]: hi at k, lo at K+k, fp16).
// Block 128x128, BK=32, 256 threads (8 warps, 64x32 warp tiles),
// 4-stage cp.async pipeline.
// A stage tile: 128 rows x 128B SW128 (chunks 0-3 hi, 4-7 lo) = 16KB.
// B stage tile: TERMS==3: like A (16KB).  TERMS==2: hi only,
//               128 rows x 64B SW64 = 8KB.
// ---------------------------------------------------------------------------
template <int TERMS> struct StageCfg {
    static constexpr int BBYTES = (TERMS == 3) ? 16384 : 8192;
    static constexpr int STAGE  = 16384 + BBYTES;
    static constexpr int SMEM   = 4 * STAGE;
    static constexpr int CHUNKS = 1024 + ((TERMS == 3) ? 1024 : 512);
};

template <int TERMS>
__device__ __forceinline__ void produce_stage(uint32_t sb,
        const __half* Ab, const __half* Bb,
        int K, int j, int tid) {
    using C = StageCfg<TERMS>;
    int k0 = j * 32;
    int ld = 2 * K;
    uint32_t stage = sb + (uint32_t)(j & 3) * C::STAGE;
    #pragma unroll
    for (int ch = 0; ch < C::CHUNKS / 256; ch++) {
        int c = tid + (ch << 8);
        if (c < 1024) {                           // A: row r, chunk q(0..7)
            int r = c >> 3, q = c & 7;
            int koff = (q < 4) ? (k0 + q * 8) : (K + k0 + (q - 4) * 8);
            uint32_t off = (uint32_t)(r * 128 + q * 16);
            off ^= (off >> 3) & 0x70;             // SW128
            CP_ASYNC16(stage + off, Ab + (size_t)r * ld + koff);
        } else if (TERMS == 3) {                  // B pair: same layout as A
            int cc = c - 1024;
            int r = cc >> 3, q = cc & 7;
            int koff = (q < 4) ? (k0 + q * 8) : (K + k0 + (q - 4) * 8);
            uint32_t off = (uint32_t)(r * 128 + q * 16);
            off ^= (off >> 3) & 0x70;
            CP_ASYNC16(stage + 16384u + off, Bb + (size_t)r * ld + koff);
        } else {                                  // B hi only: 64B rows, SW64
            int cc = c - 1024;                    // 0..511
            int r = cc >> 2, q = cc & 3;
            int qq = q ^ ((r >> 1) & 3);
            CP_ASYNC16(stage + 16384u + (uint32_t)(r * 64 + qq * 16),
                       Bb + (size_t)r * ld + k0 + q * 8);
        }
    }
    CP_COMMIT();
}

template <int TERMS, int ACT, int RESOP, bool BIAS, bool OUTPAIR>
__global__ void __launch_bounds__(256)
gemm_mma(const __half* __restrict__ A, const __half* __restrict__ Bw,
         int K, int iters,
         const float* __restrict__ bias, const float* __restrict__ res,
         float* __restrict__ Cf, __half* __restrict__ Cp,
         int N, int pairK) {
    using C = StageCfg<TERMS>;
    extern __shared__ char smem[];
    uint32_t sb = smem_u32(smem);
    int tid = threadIdx.x;
    int wid = tid >> 5, lid = tid & 31;
    int wm = wid >> 2, wn = wid & 3;               // warp grid 2x4
    int lr = lid & 15, lc = lid >> 4;

    int bm = blockIdx.y, bn = blockIdx.x;
    const __half* Ab = A  + (size_t)(bm * 128) * (2 * K);
    const __half* Bb = Bw + (size_t)(bn * 128) * (2 * K);

    float acc[4][4][4];
    #pragma unroll
    for (int i = 0; i < 4; i++)
        #pragma unroll
        for (int j = 0; j < 4; j++)
            #pragma unroll
            for (int q = 0; q < 4; q++) acc[i][j][q] = 0.f;

    produce_stage<TERMS>(sb, Ab, Bb, K, 0, tid);
    produce_stage<TERMS>(sb, Ab, Bb, K, 1, tid);
    produce_stage<TERMS>(sb, Ab, Bb, K, 2, tid);

    for (int it = 0; it < iters; ++it) {
        CP_WAIT2();
        __syncthreads();
        uint32_t sa  = sb + (uint32_t)(it & 3) * C::STAGE;
        uint32_t sbt = sa + 16384u;

        #pragma unroll
        for (int kk = 0; kk < 2; kk++) {
            uint32_t a[2][4][4];                    // [hi/lo][mf][reg]
            #pragma unroll
            for (int p = 0; p < 2; p++) {
                int chunk = p * 4 + kk * 2 + lc;
                #pragma unroll
                for (int mf = 0; mf < 4; mf++) {
                    int row = wm * 64 + mf * 16 + lr;
                    uint32_t addr = sa + (uint32_t)(row * 128)
                                  + (uint32_t)((chunk ^ (row & 7)) * 16);
                    LDSM4(a[p][mf], addr);
                }
            }
            if (TERMS == 3) {
                uint32_t bb[2][2][4];               // [hi/lo][nf2][reg]
                #pragma unroll
                for (int p = 0; p < 2; p++) {
                    int chunk = p * 4 + kk * 2 + lc;
                    #pragma unroll
                    for (int nf2 = 0; nf2 < 2; nf2++) {
                        int row = wn * 32 + nf2 * 16 + lr;
                        uint32_t addr = sbt + (uint32_t)(row * 128)
                                      + (uint32_t)((chunk ^ (row & 7)) * 16);
                        LDSM4(bb[p][nf2], addr);
                    }
                }
                #pragma unroll
                for (int mf = 0; mf < 4; mf++)
                    #pragma unroll
                    for (int nf = 0; nf < 4; nf++) {
                        int n2 = nf >> 1, sel = nf & 1;
                        MMA_F16(acc[mf][nf], a[0][mf], bb[0][n2][sel], bb[0][n2][2 + sel]);
                        MMA_F16(acc[mf][nf], a[0][mf], bb[1][n2][sel], bb[1][n2][2 + sel]);
                        MMA_F16(acc[mf][nf], a[1][mf], bb[0][n2][sel], bb[0][n2][2 + sel]);
                    }
            } else {
                uint32_t bb[2][4];                  // [nf2][reg], hi only
                int chunk = kk * 2 + lc;            // 0..3
                #pragma unroll
                for (int nf2 = 0; nf2 < 2; nf2++) {
                    int row = wn * 32 + nf2 * 16 + lr;
                    int qq = chunk ^ ((row >> 1) & 3);
                    uint32_t addr = sbt + (uint32_t)(row * 64 + qq * 16);
                    LDSM4(bb[nf2], addr);
                }
                #pragma unroll
                for (int mf = 0; mf < 4; mf++)
                    #pragma unroll
                    for (int nf = 0; nf < 4; nf++) {
                        int n2 = nf >> 1, sel = nf & 1;
                        MMA_F16(acc[mf][nf], a[0][mf], bb[n2][sel], bb[n2][2 + sel]);
                        MMA_F16(acc[mf][nf], a[1][mf], bb[n2][sel], bb[n2][2 + sel]);
                    }
            }
        }
        __syncthreads();
        int j = it + 3;
        if (j < iters) produce_stage<TERMS>(sb, Ab, Bb, K, j, tid);
        else           CP_COMMIT();
    }

    // epilogue
    int er = lid >> 2;
    int ec = (lid & 3) * 2;
    #pragma unroll
    for (int mf = 0; mf < 4; mf++) {
        #pragma unroll
        for (int nf = 0; nf < 4; nf++) {
            float* cc = acc[mf][nf];
            int row0 = bm * 128 + wm * 64 + mf * 16 + er;
            int col  = bn * 128 + wn * 32 + nf * 8 + ec;
            #pragma unroll
            for (int half = 0; half < 2; half++) {
                int row = row0 + half * 8;
                float v0 = cc[half * 2 + 0];
                float v1 = cc[half * 2 + 1];
                if (BIAS) { v0 += bias[col]; v1 += bias[col + 1]; }
                if (ACT == 1) { v0 = act_sigmoid(v0); v1 = act_sigmoid(v1); }
                if (ACT == 2) { v0 = act_gelu(v0);    v1 = act_gelu(v1); }
                if (RESOP == 1) {
                    float2 rv = *reinterpret_cast<const float2*>(res + (size_t)row * N + col);
                    v0 += rv.x; v1 += rv.y;
                }
                if (RESOP == 2) {
                    float2 rv = *reinterpret_cast<const float2*>(res + (size_t)row * N + col);
                    v0 *= rv.x; v1 *= rv.y;
                }
                if (OUTPAIR) {
                    __half h0, l0, h1, l1;
                    split_h(v0, h0, l0);
                    split_h(v1, h1, l1);
                    *reinterpret_cast<__half2*>(
                        Cp + (size_t)row * 2 * pairK + col) = __halves2half2(h0, h1);
                    *reinterpret_cast<__half2*>(
                        Cp + (size_t)row * 2 * pairK + pairK + col) = __halves2half2(l0, l1);
                } else {
                    *reinterpret_cast<float2*>(Cf + (size_t)row * N + col) = make_float2(v0, v1);
                }
            }
        }
    }
}

// ---------------------------------------------------------------------------
// RMSNorm -> fp16 pair output ([row][2D]: hi cols 0..D-1, lo cols D..2D-1)
// ---------------------------------------------------------------------------
__global__ void rmsnorm_pair_kernel(const float* __restrict__ x,
                                    const float* __restrict__ w,
                                    __half* __restrict__ outp) {
    int row = blockIdx.x;
    int tid = threadIdx.x;
    const float4* xr = reinterpret_cast<const float4*>(x + (size_t)row * D);
    float4 v = xr[tid];
    float s = v.x * v.x + v.y * v.y + v.z * v.z + v.w * v.w;
    #pragma unroll
    for (int o = 16; o > 0; o >>= 1) s += __shfl_xor_sync(0xffffffffu, s, o);
    __shared__ float sm[8];
    if ((tid & 31) == 0) sm[tid >> 5] = s;
    __syncthreads();
    float tot = 0.f;
    #pragma unroll
    for (int i = 0; i < 8; i++) tot += sm[i];
    float scale = rsqrtf(tot * (1.0f / D) + EPS);
    float4 wv = reinterpret_cast<const float4*>(w)[tid];
    float o[4] = { v.x * scale * wv.x, v.y * scale * wv.y,
                   v.z * scale * wv.z, v.w * scale * wv.w };
    __half h[4], l[4];
    #pragma unroll
    for (int i = 0; i < 4; i++) split_h(o[i], h[i], l[i]);
    __half2* hp = reinterpret_cast<__half2*>(outp + (size_t)row * 2 * D + tid * 4);
    __half2* lp = reinterpret_cast<__half2*>(outp + (size_t)row * 2 * D + D + tid * 4);
    hp[0] = __halves2half2(h[0], h[1]); hp[1] = __halves2half2(h[2], h[3]);
    lp[0] = __halves2half2(l[0], l[1]); lp[1] = __halves2half2(l[2], l[3]);
}

// Weight fp32 [N][K] -> fp16 pair [N][2K]
__global__ void wpair_kernel(const float* __restrict__ W,
                             __half* __restrict__ out, int K) {
    size_t g = (size_t)blockIdx.x * blockDim.x + threadIdx.x;
    int k = (int)(g % K);
    size_t n = g / K;
    __half h, l;
    split_h(W[g], h, l);
    out[n * 2 * K + k] = h;
    out[n * 2 * K + K + k] = l;
}

// ---------------------------------------------------------------------------
// Depthwise causal conv (K=4) -> fp32 conv + fp16 pair
// ---------------------------------------------------------------------------
__global__ void conv_kernel(const float* __restrict__ conv_buf,
                            const float* __restrict__ conv_w,
                            const float* __restrict__ conv_b) {
    size_t g = (size_t)blockIdx.x * blockDim.x + threadIdx.x;
    int d = (int)(g % D);
    int m = (int)(g / D);
    int b = m / T;
    int t = m % T;
    float4 cw = reinterpret_cast<const float4*>(conv_w)[d];
    float wk[4] = { cw.x, cw.y, cw.z, cw.w };
    float acc = conv_b[d];
    #pragma unroll
    for (int k = 0; k < 4; k++) {
        int j = t + k;
        float src = (j < 3) ? conv_buf[((size_t)b * 3 + j) * D + d]
                            : g_b1[((size_t)b * T + (j - 3)) * D + d];
        acc = fmaf(src, wk[k], acc);
    }
    g_conv[g] = acc;
    __half h, l;
    split_h(acc, h, l);
    g_conv_p[(size_t)m * 2 * D + d] = h;
    g_conv_p[(size_t)m * 2 * D + D + d] = l;
}

__global__ void convbuf_out_kernel(float* __restrict__ out) {
    int idx = blockIdx.x * blockDim.x + threadIdx.x;
    int d = idx % D;
    int j = (idx / D) % 3;
    int b = idx / (3 * D);
    out[idx] = g_b1[((size_t)b * T + (T - 3 + j)) * D + d];
}

__global__ void au_kernel(const float* __restrict__ log_lambda) {
    size_t g = (size_t)blockIdx.x * blockDim.x + threadIdx.x;
    int d = (int)(g % D);
    float ll = log_lambda[d];
    float ls = -log1pf(expf(-ll));
    float r = g_r[g];
    float i = g_i[g];
    float c = g_conv[g];
    float a = expf(C_EXP * r * ls);
    float gate = sqrtf(fmaxf((1.0f - a) * (1.0f + a), 1e-6f));
    g_au[g] = make_float2(a, gate * (i * c));
}

__global__ void scan_kernel(const float* __restrict__ h0, float* __restrict__ out_h) {
    int g = blockIdx.x * blockDim.x + threadIdx.x;
    int d = g % D;
    int b = g / D;
    float h = h0[g];
    const float2* au = g_au + (size_t)b * T * D + d;
    float* o = g_b1out + (size_t)b * T * D + d;
    #pragma unroll 4
    for (int t = 0; t < T; t++) {
        float2 v = au[(size_t)t * D];
        h = fmaf(v.x, h, v.y);
        o[(size_t)t * D] = h;
    }
    out_h[g] = h;
}

// prod = b1out * b2 -> fp16 pair
__global__ void prod_pair_kernel() {
    size_t g = (size_t)blockIdx.x * blockDim.x + threadIdx.x;
    int d = (int)(g % D);
    size_t m = g / D;
    float p = g_b1out[g] * g_b2[g];
    __half h, l;
    split_h(p, h, l);
    g_prod_p[m * 2 * D + d] = h;
    g_prod_p[m * 2 * D + D + d] = l;
}

// ---------------------------------------------------------------------------
// Launch
// ---------------------------------------------------------------------------
extern "C" void kernel_launch(void* const* d_in, const int* in_sizes, int n_in,
                              void* d_out, int out_size) {
    const float* x_seq      = (const float*)d_in[0];
    const float* h0         = (const float*)d_in[1];
    const float* conv_buf   = (const float*)d_in[2];
    const float* norm1_w    = (const float*)d_in[3];
    const float* W1         = (const float*)d_in[4];
    const float* conv_w     = (const float*)d_in[5];
    const float* conv_b     = (const float*)d_in[6];
    const float* Wa         = (const float*)d_in[7];
    const float* ba         = (const float*)d_in[8];
    const float* Wx         = (const float*)d_in[9];
    const float* bx         = (const float*)d_in[10];
    const float* log_lambda = (const float*)d_in[11];
    const float* W2         = (const float*)d_in[12];
    const float* Wout       = (const float*)d_in[13];
    const float* norm2_w    = (const float*)d_in[14];
    const float* Wg         = (const float*)d_in[15];
    const float* Wu         = (const float*)d_in[16];
    const float* Wo         = (const float*)d_in[17];

    float* out_x2 = (float*)d_out;
    float* out_h  = out_x2 + (size_t)M * D;
    float* out_cb = out_h + (size_t)B * D;

    __half *p_normed, *p_convp, *p_prodp, *p_n2p, *p_actp;
    __half *p_w1, *p_wa, *p_wx, *p_w2, *p_wout, *p_wg, *p_wu, *p_wo;
    float *p_b1, *p_r, *p_i, *p_b1out, *p_b2, *p_x1, *p_g;
    cudaGetSymbolAddress((void**)&p_normed, g_normed_p);
    cudaGetSymbolAddress((void**)&p_convp,  g_conv_p);
    cudaGetSymbolAddress((void**)&p_prodp,  g_prod_p);
    cudaGetSymbolAddress((void**)&p_n2p,    g_n2_p);
    cudaGetSymbolAddress((void**)&p_actp,   g_act_p);
    cudaGetSymbolAddress((void**)&p_w1,     g_w1p);
    cudaGetSymbolAddress((void**)&p_wa,     g_wap);
    cudaGetSymbolAddress((void**)&p_wx,     g_wxp);
    cudaGetSymbolAddress((void**)&p_w2,     g_w2p);
    cudaGetSymbolAddress((void**)&p_wout,   g_woutp);
    cudaGetSymbolAddress((void**)&p_wg,     g_wgp);
    cudaGetSymbolAddress((void**)&p_wu,     g_wup);
    cudaGetSymbolAddress((void**)&p_wo,     g_wop);
    cudaGetSymbolAddress((void**)&p_b1,     g_b1);
    cudaGetSymbolAddress((void**)&p_r,      g_r);
    cudaGetSymbolAddress((void**)&p_i,      g_i);
    cudaGetSymbolAddress((void**)&p_b1out,  g_b1out);
    cudaGetSymbolAddress((void**)&p_b2,     g_b2);
    cudaGetSymbolAddress((void**)&p_x1,     g_x1);
    cudaGetSymbolAddress((void**)&p_g,      g_g);

    auto k2Plain = gemm_mma<2, 0, 0, false, false>;
    auto k3Sig   = gemm_mma<3, 1, 0, true,  false>;
    auto k2Gelu  = gemm_mma<2, 2, 0, false, false>;
    auto k2Add   = gemm_mma<2, 0, 1, false, false>;
    auto k2MulPr = gemm_mma<2, 0, 2, false, true>;
    constexpr int SM2 = StageCfg<2>::SMEM;   // 98304
    constexpr int SM3 = StageCfg<3>::SMEM;   // 131072
    cudaFuncSetAttribute(k2Plain, cudaFuncAttributeMaxDynamicSharedMemorySize, SM2);
    cudaFuncSetAttribute(k3Sig,   cudaFuncAttributeMaxDynamicSharedMemorySize, SM3);
    cudaFuncSetAttribute(k2Gelu,  cudaFuncAttributeMaxDynamicSharedMemorySize, SM2);
    cudaFuncSetAttribute(k2Add,   cudaFuncAttributeMaxDynamicSharedMemorySize, SM2);
    cudaFuncSetAttribute(k2MulPr, cudaFuncAttributeMaxDynamicSharedMemorySize, SM2);

    dim3 gD(D / 128, M / 128);     // (8, 128)
    dim3 gH(H / 128, M / 128);     // (32, 128)
    int ewBlocks = (int)(((size_t)M * D) / 256);

    // Launch order puts the b1 GEMM at position 6 (ncu -s 5 -c 1 captures it).
    rmsnorm_pair_kernel<<<M, 256>>>(x_seq, norm1_w, p_normed);           // 1
    wpair_kernel<<<(D * D) / 256, 256>>>(W1, p_w1, D);                   // 2
    wpair_kernel<<<(D * D) / 256, 256>>>(Wa, p_wa, D);                   // 3
    wpair_kernel<<<(D * D) / 256, 256>>>(Wx, p_wx, D);                   // 4
    wpair_kernel<<<(D * D) / 256, 256>>>(W2, p_w2, D);                   // 5

    // 6: b1 = normed @ W1^T  (2-term)
    k2Plain<<<gD, 256, SM2>>>(p_normed, p_w1, D, 32,
                              nullptr, nullptr, p_b1, nullptr, D, 0);

    conv_kernel<<<ewBlocks, 256>>>(conv_buf, conv_w, conv_b);            // 7
    convbuf_out_kernel<<<(B * 3 * D) / 256, 256>>>(out_cb);              // 8

    // r, i  (3-term, recurrence-critical)
    k3Sig<<<gD, 256, SM3>>>(p_convp, p_wa, D, 32,
                            ba, nullptr, p_r, nullptr, D, 0);
    k3Sig<<<gD, 256, SM3>>>(p_convp, p_wx, D, 32,
                            bx, nullptr, p_i, nullptr, D, 0);

    au_kernel<<<ewBlocks, 256>>>(log_lambda);
    scan_kernel<<<(B * D) / 256, 256>>>(h0, out_h);

    wpair_kernel<<<(D * D) / 256, 256>>>(Wout, p_wout, D);
    wpair_kernel<<<(H * D) / 256, 256>>>(Wg,   p_wg,   D);
    wpair_kernel<<<(H * D) / 256, 256>>>(Wu,   p_wu,   D);
    wpair_kernel<<<(D * H) / 256, 256>>>(Wo,   p_wo,   H);

    // b2 = gelu(normed @ W2^T)
    k2Gelu<<<gD, 256, SM2>>>(p_normed, p_w2, D, 32,
                             nullptr, nullptr, p_b2, nullptr, D, 0);

    // prod pair; x1 = x_seq + prod @ Wout^T
    prod_pair_kernel<<<ewBlocks, 256>>>();
    k2Add<<<gD, 256, SM2>>>(p_prodp, p_wout, D, 32,
                            nullptr, x_seq, p_x1, nullptr, D, 0);

    // n2 (pair)
    rmsnorm_pair_kernel<<<M, 256>>>(p_x1, norm2_w, p_n2p);

    // g = gelu(n2 @ Wg^T); act = g * (n2 @ Wu^T) -> pair
    k2Gelu<<<gH, 256, SM2>>>(p_n2p, p_wg, D, 32,
                             nullptr, nullptr, p_g, nullptr, H, 0);
    k2MulPr<<<gH, 256, SM2>>>(p_n2p, p_wu, D, 32,
                              nullptr, p_g, nullptr, p_actp, H, H);

    // x2 = x1 + act @ Wo^T
    k2Add<<<gD, 256, SM2>>>(p_actp, p_wo, H, 128,
                            nullptr, p_x1, out_x2, nullptr, D, 0);
}

// round 7
// speedup vs baseline: 4.6471x; 1.3911x over previous
#include <cuda_runtime.h>
#include <cuda_fp16.h>
#include <math.h>
#include <stdint.h>

// ---------------------------------------------------------------------------
// GriffinTemporalBlock on GB300 (classic mma.sync fp16 path).
// Mixed-precision term schedule per GEMM (error budget vs 1e-3):
//   1-term (A_hi*B_hi)           : b2, Wout, Wg, Wu, Wo   (~3e-4)
//   2-term (+A_lo*B_hi)          : b1                      (~2e-4 via B only)
//   3-term (+A_hi*B_lo)          : r, i (feed exp(8 r ls) -> scan, critical)
// B=16, T=1024, D=1024, H=4096.
// ---------------------------------------------------------------------------

constexpr int B = 16;
constexpr int T = 1024;
constexpr int D = 1024;
constexpr int H = 4096;
constexpr int M = B * T;               // 16384
constexpr float EPS = 1.1920929e-07f;
constexpr float C_EXP = 8.0f;

// ----- scratch (static device globals) -------------------------------------
__device__ __half g_normed_p[(size_t)M * 2 * D];   // pair (b1 2-term, b2 reads hi)
__device__ __half g_conv_p  [(size_t)M * 2 * D];   // pair (r/i 3-term)
__device__ __half g_prod_h  [(size_t)M * D];       // hi only
__device__ __half g_n2_h    [(size_t)M * D];       // hi only
__device__ __half g_act_h   [(size_t)M * H];       // hi only

__device__ __half g_w1h  [(size_t)D * D];          // hi only (2-term B)
__device__ __half g_wap  [(size_t)D * 2 * D];      // pair (3-term)
__device__ __half g_wxp  [(size_t)D * 2 * D];      // pair (3-term)
__device__ __half g_w2h  [(size_t)D * D];
__device__ __half g_wouth[(size_t)D * D];
__device__ __half g_wgh  [(size_t)H * D];
__device__ __half g_wuh  [(size_t)H * D];
__device__ __half g_woh  [(size_t)D * H];

__device__ float  g_b1   [(size_t)M * D];
__device__ float  g_conv [(size_t)M * D];
__device__ float  g_r    [(size_t)M * D];
__device__ float  g_i    [(size_t)M * D];
__device__ float2 g_au   [(size_t)M * D];
__device__ float  g_b1out[(size_t)M * D];
__device__ float  g_b2   [(size_t)M * D];
__device__ float  g_x1   [(size_t)M * D];
__device__ float  g_g    [(size_t)M * H];

// ---------------------------------------------------------------------------
// helpers
// ---------------------------------------------------------------------------
__device__ __forceinline__ uint32_t smem_u32(const void* p) {
    uint32_t a;
    asm("{ .reg .u64 t; cvta.to.shared.u64 t, %1; cvt.u32.u64 %0, t; }"
        : "=r"(a) : "l"(p));
    return a;
}

#define CP_ASYNC16(dst, src) \
    asm volatile("cp.async.cg.shared.global [%0], [%1], 16;" :: "r"(dst), "l"(src) : "memory")
#define CP_COMMIT() asm volatile("cp.async.commit_group;" ::: "memory")
#define CP_WAIT2()  asm volatile("cp.async.wait_group 2;" ::: "memory")

#define LDSM4(R, addr) \
    asm volatile("ldmatrix.sync.aligned.m8n8.x4.shared.b16 {%0,%1,%2,%3}, [%4];" \
        : "=r"((R)[0]), "=r"((R)[1]), "=r"((R)[2]), "=r"((R)[3]) : "r"(addr))

#define MMA_F16(d, a, b0v, b1v) \
    asm volatile("mma.sync.aligned.m16n8k16.row.col.f32.f16.f16.f32 " \
        "{%0,%1,%2,%3}, {%4,%5,%6,%7}, {%8,%9}, {%0,%1,%2,%3};" \
        : "+f"((d)[0]), "+f"((d)[1]), "+f"((d)[2]), "+f"((d)[3]) \
        : "r"((a)[0]), "r"((a)[1]), "r"((a)[2]), "r"((a)[3]), "r"(b0v), "r"(b1v))

__device__ __forceinline__ void split_h(float x, __half& h, __half& l) {
    h = __float2half_rn(x);
    l = __float2half_rn(x - __half2float(h));
}

__device__ __forceinline__ float act_sigmoid(float x) { return 1.0f / (1.0f + expf(-x)); }
__device__ __forceinline__ float act_gelu(float x)    { return 0.5f * x * (1.0f + erff(x * 0.70710678118654752f)); }

// ---------------------------------------------------------------------------
// mma.sync GEMM.  A layout: pair [row][2K] (hi k, lo K+k) when TERMS>=2,
// hi-only [row][ldA] when TERMS==1.  B: pair when TERMS==3, else hi-only.
// Block 128x128, BK=32, 256 threads (8 warps, 64x32 tiles), 4-stage pipeline.
// Pair tiles: 128 rows x 128B SW128.  Hi tiles: 128 rows x 64B SW64.
// OUTMODE: 0 = fp32 to Cf (ld N), 2 = fp16 hi to Cp (ld ldOut).
// ---------------------------------------------------------------------------
template <int TERMS> struct StageCfg {
    static constexpr int ABYTES = (TERMS >= 2) ? 16384 : 8192;
    static constexpr int BBYTES = (TERMS == 3) ? 16384 : 8192;
    static constexpr int STAGE  = ABYTES + BBYTES;
    static constexpr int SMEM   = 4 * STAGE;
    static constexpr int ACH    = ABYTES / 16;
    static constexpr int CHUNKS = (ABYTES + BBYTES) / 16;
};

template <int TERMS>
__device__ __forceinline__ void produce_stage(uint32_t sb,
        const __half* Ab, const __half* Bb,
        int ldA, int ldB, int K, int j, int tid) {
    using C = StageCfg<TERMS>;
    int k0 = j * 32;
    uint32_t stage = sb + (uint32_t)(j & 3) * C::STAGE;
    #pragma unroll
    for (int ch = 0; ch < C::CHUNKS / 256; ch++) {
        int c = tid + (ch << 8);
        if (c < C::ACH) {
            if (TERMS >= 2) {                     // A pair, SW128
                int r = c >> 3, q = c & 7;
                int koff = (q < 4) ? (k0 + q * 8) : (K + k0 + (q - 4) * 8);
                uint32_t off = (uint32_t)(r * 128 + q * 16);
                off ^= (off >> 3) & 0x70;
                CP_ASYNC16(stage + off, Ab + (size_t)r * ldA + koff);
            } else {                              // A hi, SW64
                int r = c >> 2, q = c & 3;
                int qq = q ^ ((r >> 1) & 3);
                CP_ASYNC16(stage + (uint32_t)(r * 64 + qq * 16),
                           Ab + (size_t)r * ldA + k0 + q * 8);
            }
        } else {
            int cc = c - C::ACH;
            if (TERMS == 3) {                     // B pair, SW128
                int r = cc >> 3, q = cc & 7;
                int koff = (q < 4) ? (k0 + q * 8) : (K + k0 + (q - 4) * 8);
                uint32_t off = (uint32_t)(r * 128 + q * 16);
                off ^= (off >> 3) & 0x70;
                CP_ASYNC16(stage + (uint32_t)C::ABYTES + off,
                           Bb + (size_t)r * ldB + koff);
            } else {                              // B hi, SW64
                int r = cc >> 2, q = cc & 3;
                int qq = q ^ ((r >> 1) & 3);
                CP_ASYNC16(stage + (uint32_t)C::ABYTES + (uint32_t)(r * 64 + qq * 16),
                           Bb + (size_t)r * ldB + k0 + q * 8);
            }
        }
    }
    CP_COMMIT();
}

template <int TERMS, int ACT, int RESOP, bool BIAS, int OUTMODE>
__global__ void __launch_bounds__(256)
gemm_mma(const __half* __restrict__ A, const __half* __restrict__ Bw,
         int ldA, int ldB, int K, int iters,
         const float* __restrict__ bias, const float* __restrict__ res,
         float* __restrict__ Cf, __half* __restrict__ Cp,
         int N, int ldOut) {
    using C = StageCfg<TERMS>;
    extern __shared__ char smem[];
    uint32_t sb = smem_u32(smem);
    int tid = threadIdx.x;
    int wid = tid >> 5, lid = tid & 31;
    int wm = wid >> 2, wn = wid & 3;               // warp grid 2x4
    int lr = lid & 15, lc = lid >> 4;

    int bm = blockIdx.y, bn = blockIdx.x;
    const __half* Ab = A  + (size_t)(bm * 128) * ldA;
    const __half* Bb = Bw + (size_t)(bn * 128) * ldB;

    float acc[4][4][4];
    #pragma unroll
    for (int i = 0; i < 4; i++)
        #pragma unroll
        for (int j = 0; j < 4; j++)
            #pragma unroll
            for (int q = 0; q < 4; q++) acc[i][j][q] = 0.f;

    produce_stage<TERMS>(sb, Ab, Bb, ldA, ldB, K, 0, tid);
    produce_stage<TERMS>(sb, Ab, Bb, ldA, ldB, K, 1, tid);
    produce_stage<TERMS>(sb, Ab, Bb, ldA, ldB, K, 2, tid);

    for (int it = 0; it < iters; ++it) {
        CP_WAIT2();
        __syncthreads();
        uint32_t sa  = sb + (uint32_t)(it & 3) * C::STAGE;
        uint32_t sbt = sa + (uint32_t)C::ABYTES;

        #pragma unroll
        for (int kk = 0; kk < 2; kk++) {
            // ---- A fragments ----
            uint32_t a[(TERMS >= 2) ? 2 : 1][4][4];
            if (TERMS >= 2) {
                #pragma unroll
                for (int p = 0; p < 2; p++) {
                    int chunk = p * 4 + kk * 2 + lc;
                    #pragma unroll
                    for (int mf = 0; mf < 4; mf++) {
                        int row = wm * 64 + mf * 16 + lr;
                        uint32_t addr = sa + (uint32_t)(row * 128)
                                      + (uint32_t)((chunk ^ (row & 7)) * 16);
                        LDSM4(a[p][mf], addr);
                    }
                }
            } else {
                int chunk = kk * 2 + lc;
                #pragma unroll
                for (int mf = 0; mf < 4; mf++) {
                    int row = wm * 64 + mf * 16 + lr;
                    int qq = chunk ^ ((row >> 1) & 3);
                    LDSM4(a[0][mf], sa + (uint32_t)(row * 64 + qq * 16));
                }
            }
            // ---- B fragments + MMAs ----
            if (TERMS == 3) {
                uint32_t bb[2][2][4];
                #pragma unroll
                for (int p = 0; p < 2; p++) {
                    int chunk = p * 4 + kk * 2 + lc;
                    #pragma unroll
                    for (int nf2 = 0; nf2 < 2; nf2++) {
                        int row = wn * 32 + nf2 * 16 + lr;
                        uint32_t addr = sbt + (uint32_t)(row * 128)
                                      + (uint32_t)((chunk ^ (row & 7)) * 16);
                        LDSM4(bb[p][nf2], addr);
                    }
                }
                #pragma unroll
                for (int mf = 0; mf < 4; mf++)
                    #pragma unroll
                    for (int nf = 0; nf < 4; nf++) {
                        int n2 = nf >> 1, sel = nf & 1;
                        MMA_F16(acc[mf][nf], a[0][mf], bb[0][n2][sel], bb[0][n2][2 + sel]);
                        MMA_F16(acc[mf][nf], a[0][mf], bb[1][n2][sel], bb[1][n2][2 + sel]);
                        MMA_F16(acc[mf][nf], a[1][mf], bb[0][n2][sel], bb[0][n2][2 + sel]);
                    }
            } else {
                uint32_t bb[2][4];
                int chunk = kk * 2 + lc;
                #pragma unroll
                for (int nf2 = 0; nf2 < 2; nf2++) {
                    int row = wn * 32 + nf2 * 16 + lr;
                    int qq = chunk ^ ((row >> 1) & 3);
                    LDSM4(bb[nf2], sbt + (uint32_t)(row * 64 + qq * 16));
                }
                #pragma unroll
                for (int mf = 0; mf < 4; mf++)
                    #pragma unroll
                    for (int nf = 0; nf < 4; nf++) {
                        int n2 = nf >> 1, sel = nf & 1;
                        MMA_F16(acc[mf][nf], a[0][mf], bb[n2][sel], bb[n2][2 + sel]);
                        if (TERMS == 2)
                            MMA_F16(acc[mf][nf], a[1][mf], bb[n2][sel], bb[n2][2 + sel]);
                    }
            }
        }
        __syncthreads();
        int j = it + 3;
        if (j < iters) produce_stage<TERMS>(sb, Ab, Bb, ldA, ldB, K, j, tid);
        else           CP_COMMIT();
    }

    // epilogue
    int er = lid >> 2;
    int ec = (lid & 3) * 2;
    #pragma unroll
    for (int mf = 0; mf < 4; mf++) {
        #pragma unroll
        for (int nf = 0; nf < 4; nf++) {
            float* cc = acc[mf][nf];
            int row0 = bm * 128 + wm * 64 + mf * 16 + er;
            int col  = bn * 128 + wn * 32 + nf * 8 + ec;
            #pragma unroll
            for (int half = 0; half < 2; half++) {
                int row = row0 + half * 8;
                float v0 = cc[half * 2 + 0];
                float v1 = cc[half * 2 + 1];
                if (BIAS) { v0 += bias[col]; v1 += bias[col + 1]; }
                if (ACT == 1) { v0 = act_sigmoid(v0); v1 = act_sigmoid(v1); }
                if (ACT == 2) { v0 = act_gelu(v0);    v1 = act_gelu(v1); }
                if (RESOP == 1) {
                    float2 rv = *reinterpret_cast<const float2*>(res + (size_t)row * N + col);
                    v0 += rv.x; v1 += rv.y;
                }
                if (RESOP == 2) {
                    float2 rv = *reinterpret_cast<const float2*>(res + (size_t)row * N + col);
                    v0 *= rv.x; v1 *= rv.y;
                }
                if (OUTMODE == 2) {
                    *reinterpret_cast<__half2*>(Cp + (size_t)row * ldOut + col) =
                        __halves2half2(__float2half_rn(v0), __float2half_rn(v1));
                } else {
                    *reinterpret_cast<float2*>(Cf + (size_t)row * N + col) = make_float2(v0, v1);
                }
            }
        }
    }
}

// ---------------------------------------------------------------------------
// RMSNorm writers
// ---------------------------------------------------------------------------
__global__ void rmsnorm_pair_kernel(const float* __restrict__ x,
                                    const float* __restrict__ w,
                                    __half* __restrict__ outp) {
    int row = blockIdx.x;
    int tid = threadIdx.x;
    const float4* xr = reinterpret_cast<const float4*>(x + (size_t)row * D);
    float4 v = xr[tid];
    float s = v.x * v.x + v.y * v.y + v.z * v.z + v.w * v.w;
    #pragma unroll
    for (int o = 16; o > 0; o >>= 1) s += __shfl_xor_sync(0xffffffffu, s, o);
    __shared__ float sm[8];
    if ((tid & 31) == 0) sm[tid >> 5] = s;
    __syncthreads();
    float tot = 0.f;
    #pragma unroll
    for (int i = 0; i < 8; i++) tot += sm[i];
    float scale = rsqrtf(tot * (1.0f / D) + EPS);
    float4 wv = reinterpret_cast<const float4*>(w)[tid];
    float o[4] = { v.x * scale * wv.x, v.y * scale * wv.y,
                   v.z * scale * wv.z, v.w * scale * wv.w };
    __half h[4], l[4];
    #pragma unroll
    for (int i = 0; i < 4; i++) split_h(o[i], h[i], l[i]);
    __half2* hp = reinterpret_cast<__half2*>(outp + (size_t)row * 2 * D + tid * 4);
    __half2* lp = reinterpret_cast<__half2*>(outp + (size_t)row * 2 * D + D + tid * 4);
    hp[0] = __halves2half2(h[0], h[1]); hp[1] = __halves2half2(h[2], h[3]);
    lp[0] = __halves2half2(l[0], l[1]); lp[1] = __halves2half2(l[2], l[3]);
}

__global__ void rmsnorm_hi_kernel(const float* __restrict__ x,
                                  const float* __restrict__ w,
                                  __half* __restrict__ outh) {
    int row = blockIdx.x;
    int tid = threadIdx.x;
    const float4* xr = reinterpret_cast<const float4*>(x + (size_t)row * D);
    float4 v = xr[tid];
    float s = v.x * v.x + v.y * v.y + v.z * v.z + v.w * v.w;
    #pragma unroll
    for (int o = 16; o > 0; o >>= 1) s += __shfl_xor_sync(0xffffffffu, s, o);
    __shared__ float sm[8];
    if ((tid & 31) == 0) sm[tid >> 5] = s;
    __syncthreads();
    float tot = 0.f;
    #pragma unroll
    for (int i = 0; i < 8; i++) tot += sm[i];
    float scale = rsqrtf(tot * (1.0f / D) + EPS);
    float4 wv = reinterpret_cast<const float4*>(w)[tid];
    __half2* hp = reinterpret_cast<__half2*>(outh + (size_t)row * D + tid * 4);
    hp[0] = __halves2half2(__float2half_rn(v.x * scale * wv.x),
                           __float2half_rn(v.y * scale * wv.y));
    hp[1] = __halves2half2(__float2half_rn(v.z * scale * wv.z),
                           __float2half_rn(v.w * scale * wv.w));
}

// Weight fp32 [N][K] -> fp16 pair [N][2K]
__global__ void wpair_kernel(const float* __restrict__ W,
                             __half* __restrict__ out, int K) {
    size_t g = (size_t)blockIdx.x * blockDim.x + threadIdx.x;
    int k = (int)(g % K);
    size_t n = g / K;
    __half h, l;
    split_h(W[g], h, l);
    out[n * 2 * K + k] = h;
    out[n * 2 * K + K + k] = l;
}

// Weight fp32 -> fp16 hi-only (same shape)
__global__ void whi_kernel(const float* __restrict__ W,
                           __half* __restrict__ out) {
    size_t g = ((size_t)blockIdx.x * blockDim.x + threadIdx.x) * 4;
    float4 v = *reinterpret_cast<const float4*>(W + g);
    __half2* o = reinterpret_cast<__half2*>(out + g);
    o[0] = __halves2half2(__float2half_rn(v.x), __float2half_rn(v.y));
    o[1] = __halves2half2(__float2half_rn(v.z), __float2half_rn(v.w));
}

// ---------------------------------------------------------------------------
// Depthwise causal conv (K=4) -> fp32 conv + fp16 pair
// ---------------------------------------------------------------------------
__global__ void conv_kernel(const float* __restrict__ conv_buf,
                            const float* __restrict__ conv_w,
                            const float* __restrict__ conv_b) {
    size_t g = (size_t)blockIdx.x * blockDim.x + threadIdx.x;
    int d = (int)(g % D);
    int m = (int)(g / D);
    int b = m / T;
    int t = m % T;
    float4 cw = reinterpret_cast<const float4*>(conv_w)[d];
    float wk[4] = { cw.x, cw.y, cw.z, cw.w };
    float acc = conv_b[d];
    #pragma unroll
    for (int k = 0; k < 4; k++) {
        int j = t + k;
        float src = (j < 3) ? conv_buf[((size_t)b * 3 + j) * D + d]
                            : g_b1[((size_t)b * T + (j - 3)) * D + d];
        acc = fmaf(src, wk[k], acc);
    }
    g_conv[g] = acc;
    __half h, l;
    split_h(acc, h, l);
    g_conv_p[(size_t)m * 2 * D + d] = h;
    g_conv_p[(size_t)m * 2 * D + D + d] = l;
}

__global__ void convbuf_out_kernel(float* __restrict__ out) {
    int idx = blockIdx.x * blockDim.x + threadIdx.x;
    int d = idx % D;
    int j = (idx / D) % 3;
    int b = idx / (3 * D);
    out[idx] = g_b1[((size_t)b * T + (T - 3 + j)) * D + d];
}

__global__ void au_kernel(const float* __restrict__ log_lambda) {
    size_t g = (size_t)blockIdx.x * blockDim.x + threadIdx.x;
    int d = (int)(g % D);
    float ll = log_lambda[d];
    float ls = -log1pf(expf(-ll));
    float r = g_r[g];
    float i = g_i[g];
    float c = g_conv[g];
    float a = expf(C_EXP * r * ls);
    float gate = sqrtf(fmaxf((1.0f - a) * (1.0f + a), 1e-6f));
    g_au[g] = make_float2(a, gate * (i * c));
}

__global__ void scan_kernel(const float* __restrict__ h0, float* __restrict__ out_h) {
    int g = blockIdx.x * blockDim.x + threadIdx.x;
    int d = g % D;
    int b = g / D;
    float h = h0[g];
    const float2* au = g_au + (size_t)b * T * D + d;
    float* o = g_b1out + (size_t)b * T * D + d;
    #pragma unroll 4
    for (int t = 0; t < T; t++) {
        float2 v = au[(size_t)t * D];
        h = fmaf(v.x, h, v.y);
        o[(size_t)t * D] = h;
    }
    out_h[g] = h;
}

// prod = b1out * b2 -> fp16 hi
__global__ void prod_hi_kernel() {
    size_t g = ((size_t)blockIdx.x * blockDim.x + threadIdx.x) * 2;
    float2 a = *reinterpret_cast<const float2*>(g_b1out + g);
    float2 b = *reinterpret_cast<const float2*>(g_b2 + g);
    *reinterpret_cast<__half2*>(g_prod_h + g) =
        __halves2half2(__float2half_rn(a.x * b.x), __float2half_rn(a.y * b.y));
}

// ---------------------------------------------------------------------------
// Launch
// ---------------------------------------------------------------------------
extern "C" void kernel_launch(void* const* d_in, const int* in_sizes, int n_in,
                              void* d_out, int out_size) {
    const float* x_seq      = (const float*)d_in[0];
    const float* h0         = (const float*)d_in[1];
    const float* conv_buf   = (const float*)d_in[2];
    const float* norm1_w    = (const float*)d_in[3];
    const float* W1         = (const float*)d_in[4];
    const float* conv_w     = (const float*)d_in[5];
    const float* conv_b     = (const float*)d_in[6];
    const float* Wa         = (const float*)d_in[7];
    const float* ba         = (const float*)d_in[8];
    const float* Wx         = (const float*)d_in[9];
    const float* bx         = (const float*)d_in[10];
    const float* log_lambda = (const float*)d_in[11];
    const float* W2         = (const float*)d_in[12];
    const float* Wout       = (const float*)d_in[13];
    const float* norm2_w    = (const float*)d_in[14];
    const float* Wg         = (const float*)d_in[15];
    const float* Wu         = (const float*)d_in[16];
    const float* Wo         = (const float*)d_in[17];

    float* out_x2 = (float*)d_out;
    float* out_h  = out_x2 + (size_t)M * D;
    float* out_cb = out_h + (size_t)B * D;

    __half *p_normed, *p_convp, *p_prodh, *p_n2h, *p_acth;
    __half *p_w1, *p_wa, *p_wx, *p_w2, *p_wout, *p_wg, *p_wu, *p_wo;
    float *p_b1, *p_r, *p_i, *p_b1out, *p_b2, *p_x1, *p_g;
    cudaGetSymbolAddress((void**)&p_normed, g_normed_p);
    cudaGetSymbolAddress((void**)&p_convp,  g_conv_p);
    cudaGetSymbolAddress((void**)&p_prodh,  g_prod_h);
    cudaGetSymbolAddress((void**)&p_n2h,    g_n2_h);
    cudaGetSymbolAddress((void**)&p_acth,   g_act_h);
    cudaGetSymbolAddress((void**)&p_w1,     g_w1h);
    cudaGetSymbolAddress((void**)&p_wa,     g_wap);
    cudaGetSymbolAddress((void**)&p_wx,     g_wxp);
    cudaGetSymbolAddress((void**)&p_w2,     g_w2h);
    cudaGetSymbolAddress((void**)&p_wout,   g_wouth);
    cudaGetSymbolAddress((void**)&p_wg,     g_wgh);
    cudaGetSymbolAddress((void**)&p_wu,     g_wuh);
    cudaGetSymbolAddress((void**)&p_wo,     g_woh);
    cudaGetSymbolAddress((void**)&p_b1,     g_b1);
    cudaGetSymbolAddress((void**)&p_r,      g_r);
    cudaGetSymbolAddress((void**)&p_i,      g_i);
    cudaGetSymbolAddress((void**)&p_b1out,  g_b1out);
    cudaGetSymbolAddress((void**)&p_b2,     g_b2);
    cudaGetSymbolAddress((void**)&p_x1,     g_x1);
    cudaGetSymbolAddress((void**)&p_g,      g_g);

    auto k2Plain = gemm_mma<2, 0, 0, false, 0>;    // b1
    auto k3Sig   = gemm_mma<3, 1, 0, true,  0>;    // r, i
    auto k1Gelu  = gemm_mma<1, 2, 0, false, 0>;    // b2, g
    auto k1Add   = gemm_mma<1, 0, 1, false, 0>;    // x1, x2
    auto k1MulH  = gemm_mma<1, 0, 2, false, 2>;    // act (hi out)
    constexpr int SM1 = StageCfg<1>::SMEM;   // 65536
    constexpr int SM2 = StageCfg<2>::SMEM;   // 98304
    constexpr int SM3 = StageCfg<3>::SMEM;   // 131072
    cudaFuncSetAttribute(k2Plain, cudaFuncAttributeMaxDynamicSharedMemorySize, SM2);
    cudaFuncSetAttribute(k3Sig,   cudaFuncAttributeMaxDynamicSharedMemorySize, SM3);
    cudaFuncSetAttribute(k1Gelu,  cudaFuncAttributeMaxDynamicSharedMemorySize, SM1);
    cudaFuncSetAttribute(k1Add,   cudaFuncAttributeMaxDynamicSharedMemorySize, SM1);
    cudaFuncSetAttribute(k1MulH,  cudaFuncAttributeMaxDynamicSharedMemorySize, SM1);

    dim3 gD(D / 128, M / 128);     // (8, 128)
    dim3 gH(H / 128, M / 128);     // (32, 128)
    int ewBlocks = (int)(((size_t)M * D) / 256);

    // Launch order: b1 GEMM is launch #6 (ncu -s 5 -c 1 captures it).
    rmsnorm_pair_kernel<<<M, 256>>>(x_seq, norm1_w, p_normed);           // 1
    whi_kernel<<<(D * D) / 1024, 256>>>(W1, p_w1);                       // 2
    wpair_kernel<<<(D * D) / 256, 256>>>(Wa, p_wa, D);                   // 3
    wpair_kernel<<<(D * D) / 256, 256>>>(Wx, p_wx, D);                   // 4
    whi_kernel<<<(D * D) / 1024, 256>>>(W2, p_w2);                       // 5

    // 6: b1 = normed @ W1^T  (2-term)
    k2Plain<<<gD, 256, SM2>>>(p_normed, p_w1, 2 * D, D, D, 32,
                              nullptr, nullptr, p_b1, nullptr, D, 0);

    conv_kernel<<<ewBlocks, 256>>>(conv_buf, conv_w, conv_b);
    convbuf_out_kernel<<<(B * 3 * D) / 256, 256>>>(out_cb);

    // r, i  (3-term, recurrence-critical)
    k3Sig<<<gD, 256, SM3>>>(p_convp, p_wa, 2 * D, 2 * D, D, 32,
                            ba, nullptr, p_r, nullptr, D, 0);
    k3Sig<<<gD, 256, SM3>>>(p_convp, p_wx, 2 * D, 2 * D, D, 32,
                            bx, nullptr, p_i, nullptr, D, 0);

    au_kernel<<<ewBlocks, 256>>>(log_lambda);
    scan_kernel<<<(B * D) / 256, 256>>>(h0, out_h);

    whi_kernel<<<(D * D) / 1024, 256>>>(Wout, p_wout);
    whi_kernel<<<(H * D) / 1024, 256>>>(Wg,   p_wg);
    whi_kernel<<<(H * D) / 1024, 256>>>(Wu,   p_wu);
    whi_kernel<<<(D * H) / 1024, 256>>>(Wo,   p_wo);

    // b2 = gelu(normed @ W2^T)  (1-term; reads hi half of normed pair)
    k1Gelu<<<gD, 256, SM1>>>(p_normed, p_w2, 2 * D, D, D, 32,
                             nullptr, nullptr, p_b2, nullptr, D, 0);

    // prod hi; x1 = x_seq + prod @ Wout^T  (1-term)
    prod_hi_kernel<<<ewBlocks / 2, 256>>>();
    k1Add<<<gD, 256, SM1>>>(p_prodh, p_wout, D, D, D, 32,
                            nullptr, x_seq, p_x1, nullptr, D, 0);

    // n2 (hi only)
    rmsnorm_hi_kernel<<<M, 256>>>(p_x1, norm2_w, p_n2h);

    // g = gelu(n2 @ Wg^T); act = g * (n2 @ Wu^T) -> hi   (1-term)
    k1Gelu<<<gH, 256, SM1>>>(p_n2h, p_wg, D, D, D, 32,
                             nullptr, nullptr, p_g, nullptr, H, 0);
    k1MulH<<<gH, 256, SM1>>>(p_n2h, p_wu, D, D, D, 32,
                             nullptr, p_g, nullptr, p_acth, H, H);

    // x2 = x1 + act @ Wo^T  (1-term)
    k1Add<<<gD, 256, SM1>>>(p_acth, p_wo, H, H, H, 128,
                            nullptr, p_x1, out_x2, nullptr, D, 0);
}

// round 8
// speedup vs baseline: 5.1178x; 1.1013x over previous
#include <cuda_runtime.h>
#include <cuda_fp16.h>
#include <math.h>
#include <stdint.h>

// ---------------------------------------------------------------------------
// GriffinTemporalBlock on GB300 (classic mma.sync fp16 path).
// Term schedule: b1, r, i = 2-term (A pair exact, B hi); all MLP-side = 1-term.
// Fusions: b2-GEMM epilogue does gelu*b1out -> prod_h; g buffer fp16.
// B=16, T=1024, D=1024, H=4096.
// ---------------------------------------------------------------------------

constexpr int B = 16;
constexpr int T = 1024;
constexpr int D = 1024;
constexpr int H = 4096;
constexpr int M = B * T;               // 16384
constexpr float EPS = 1.1920929e-07f;
constexpr float C_EXP = 8.0f;

// ----- scratch (static device globals) -------------------------------------
__device__ __half g_normed_p[(size_t)M * 2 * D];   // pair (b1 2-term; b2 reads hi)
__device__ __half g_conv_p  [(size_t)M * 2 * D];   // pair (r/i 2-term A)
__device__ __half g_prod_h  [(size_t)M * D];       // gelu(b2)*b1out, hi
__device__ __half g_n2_h    [(size_t)M * D];
__device__ __half g_act_h   [(size_t)M * H];
__device__ __half g_gh      [(size_t)M * H];       // gelu(n2@Wg), fp16

__device__ __half g_w1h  [(size_t)D * D];
__device__ __half g_wah  [(size_t)D * D];
__device__ __half g_wxh  [(size_t)D * D];
__device__ __half g_w2h  [(size_t)D * D];
__device__ __half g_wouth[(size_t)D * D];
__device__ __half g_wgh  [(size_t)H * D];
__device__ __half g_wuh  [(size_t)H * D];
__device__ __half g_woh  [(size_t)D * H];

__device__ float  g_b1   [(size_t)M * D];
__device__ float  g_conv [(size_t)M * D];
__device__ float  g_r    [(size_t)M * D];
__device__ float  g_i    [(size_t)M * D];
__device__ float2 g_au   [(size_t)M * D];
__device__ float  g_b1out[(size_t)M * D];
__device__ float  g_x1   [(size_t)M * D];

// ---------------------------------------------------------------------------
// helpers
// ---------------------------------------------------------------------------
__device__ __forceinline__ uint32_t smem_u32(const void* p) {
    uint32_t a;
    asm("{ .reg .u64 t; cvta.to.shared.u64 t, %1; cvt.u32.u64 %0, t; }"
        : "=r"(a) : "l"(p));
    return a;
}

#define CP_ASYNC16(dst, src) \
    asm volatile("cp.async.cg.shared.global [%0], [%1], 16;" :: "r"(dst), "l"(src) : "memory")
#define CP_COMMIT() asm volatile("cp.async.commit_group;" ::: "memory")
#define CP_WAIT2()  asm volatile("cp.async.wait_group 2;" ::: "memory")

#define LDSM4(R, addr) \
    asm volatile("ldmatrix.sync.aligned.m8n8.x4.shared.b16 {%0,%1,%2,%3}, [%4];" \
        : "=r"((R)[0]), "=r"((R)[1]), "=r"((R)[2]), "=r"((R)[3]) : "r"(addr))

#define MMA_F16(d, a, b0v, b1v) \
    asm volatile("mma.sync.aligned.m16n8k16.row.col.f32.f16.f16.f32 " \
        "{%0,%1,%2,%3}, {%4,%5,%6,%7}, {%8,%9}, {%0,%1,%2,%3};" \
        : "+f"((d)[0]), "+f"((d)[1]), "+f"((d)[2]), "+f"((d)[3]) \
        : "r"((a)[0]), "r"((a)[1]), "r"((a)[2]), "r"((a)[3]), "r"(b0v), "r"(b1v))

__device__ __forceinline__ void split_h(float x, __half& h, __half& l) {
    h = __float2half_rn(x);
    l = __float2half_rn(x - __half2float(h));
}

__device__ __forceinline__ float act_sigmoid(float x) { return 1.0f / (1.0f + expf(-x)); }
__device__ __forceinline__ float act_gelu(float x)    { return 0.5f * x * (1.0f + erff(x * 0.70710678118654752f)); }

// ---------------------------------------------------------------------------
// mma.sync GEMM.  A: pair [row][2K] when TERMS==2, hi-only when TERMS==1.
// B: always hi-only here.  Block 128x128, BK=32, 8 warps, 4-stage pipeline.
// Pair tile: 128x128B SW128.  Hi tile: 128x64B SW64.
// OUTMODE: 0 = fp32 Cf (ld N), 2 = fp16 Cp (ld ldOut).
// RESHALF: res buffer is fp16 (ld N).
// ---------------------------------------------------------------------------
template <int TERMS> struct StageCfg {
    static constexpr int ABYTES = (TERMS >= 2) ? 16384 : 8192;
    static constexpr int BBYTES = 8192;
    static constexpr int STAGE  = ABYTES + BBYTES;
    static constexpr int SMEM   = 4 * STAGE;
    static constexpr int ACH    = ABYTES / 16;
    static constexpr int CHUNKS = (ABYTES + BBYTES) / 16;
};

template <int TERMS>
__device__ __forceinline__ void produce_stage(uint32_t sb,
        const __half* Ab, const __half* Bb,
        int ldA, int ldB, int K, int j, int tid) {
    using C = StageCfg<TERMS>;
    int k0 = j * 32;
    uint32_t stage = sb + (uint32_t)(j & 3) * C::STAGE;
    #pragma unroll
    for (int ch = 0; ch < C::CHUNKS / 256; ch++) {
        int c = tid + (ch << 8);
        if (c < C::ACH) {
            if (TERMS >= 2) {                     // A pair, SW128
                int r = c >> 3, q = c & 7;
                int koff = (q < 4) ? (k0 + q * 8) : (K + k0 + (q - 4) * 8);
                uint32_t off = (uint32_t)(r * 128 + q * 16);
                off ^= (off >> 3) & 0x70;
                CP_ASYNC16(stage + off, Ab + (size_t)r * ldA + koff);
            } else {                              // A hi, SW64
                int r = c >> 2, q = c & 3;
                int qq = q ^ ((r >> 1) & 3);
                CP_ASYNC16(stage + (uint32_t)(r * 64 + qq * 16),
                           Ab + (size_t)r * ldA + k0 + q * 8);
            }
        } else {                                  // B hi, SW64
            int cc = c - C::ACH;
            int r = cc >> 2, q = cc & 3;
            int qq = q ^ ((r >> 1) & 3);
            CP_ASYNC16(stage + (uint32_t)C::ABYTES + (uint32_t)(r * 64 + qq * 16),
                       Bb + (size_t)r * ldB + k0 + q * 8);
        }
    }
    CP_COMMIT();
}

template <int TERMS, int ACT, int RESOP, bool BIAS, int OUTMODE, bool RESHALF>
__global__ void __launch_bounds__(256)
gemm_mma(const __half* __restrict__ A, const __half* __restrict__ Bw,
         int ldA, int ldB, int K, int iters,
         const float* __restrict__ bias, const void* __restrict__ res,
         float* __restrict__ Cf, __half* __restrict__ Cp,
         int N, int ldOut) {
    using C = StageCfg<TERMS>;
    extern __shared__ char smem[];
    uint32_t sb = smem_u32(smem);
    int tid = threadIdx.x;
    int wid = tid >> 5, lid = tid & 31;
    int wm = wid >> 2, wn = wid & 3;               // warp grid 2x4
    int lr = lid & 15, lc = lid >> 4;

    int bm = blockIdx.y, bn = blockIdx.x;
    const __half* Ab = A  + (size_t)(bm * 128) * ldA;
    const __half* Bb = Bw + (size_t)(bn * 128) * ldB;

    float acc[4][4][4];
    #pragma unroll
    for (int i = 0; i < 4; i++)
        #pragma unroll
        for (int j = 0; j < 4; j++)
            #pragma unroll
            for (int q = 0; q < 4; q++) acc[i][j][q] = 0.f;

    produce_stage<TERMS>(sb, Ab, Bb, ldA, ldB, K, 0, tid);
    produce_stage<TERMS>(sb, Ab, Bb, ldA, ldB, K, 1, tid);
    produce_stage<TERMS>(sb, Ab, Bb, ldA, ldB, K, 2, tid);

    for (int it = 0; it < iters; ++it) {
        CP_WAIT2();
        __syncthreads();
        uint32_t sa  = sb + (uint32_t)(it & 3) * C::STAGE;
        uint32_t sbt = sa + (uint32_t)C::ABYTES;

        #pragma unroll
        for (int kk = 0; kk < 2; kk++) {
            uint32_t a[(TERMS >= 2) ? 2 : 1][4][4];
            if (TERMS >= 2) {
                #pragma unroll
                for (int p = 0; p < 2; p++) {
                    int chunk = p * 4 + kk * 2 + lc;
                    #pragma unroll
                    for (int mf = 0; mf < 4; mf++) {
                        int row = wm * 64 + mf * 16 + lr;
                        uint32_t addr = sa + (uint32_t)(row * 128)
                                      + (uint32_t)((chunk ^ (row & 7)) * 16);
                        LDSM4(a[p][mf], addr);
                    }
                }
            } else {
                int chunk = kk * 2 + lc;
                #pragma unroll
                for (int mf = 0; mf < 4; mf++) {
                    int row = wm * 64 + mf * 16 + lr;
                    int qq = chunk ^ ((row >> 1) & 3);
                    LDSM4(a[0][mf], sa + (uint32_t)(row * 64 + qq * 16));
                }
            }
            uint32_t bb[2][4];
            int chunk = kk * 2 + lc;
            #pragma unroll
            for (int nf2 = 0; nf2 < 2; nf2++) {
                int row = wn * 32 + nf2 * 16 + lr;
                int qq = chunk ^ ((row >> 1) & 3);
                LDSM4(bb[nf2], sbt + (uint32_t)(row * 64 + qq * 16));
            }
            #pragma unroll
            for (int mf = 0; mf < 4; mf++)
                #pragma unroll
                for (int nf = 0; nf < 4; nf++) {
                    int n2 = nf >> 1, sel = nf & 1;
                    MMA_F16(acc[mf][nf], a[0][mf], bb[n2][sel], bb[n2][2 + sel]);
                    if (TERMS >= 2)
                        MMA_F16(acc[mf][nf], a[1][mf], bb[n2][sel], bb[n2][2 + sel]);
                }
        }
        __syncthreads();
        int j = it + 3;
        if (j < iters) produce_stage<TERMS>(sb, Ab, Bb, ldA, ldB, K, j, tid);
        else           CP_COMMIT();
    }

    // epilogue
    int er = lid >> 2;
    int ec = (lid & 3) * 2;
    #pragma unroll
    for (int mf = 0; mf < 4; mf++) {
        #pragma unroll
        for (int nf = 0; nf < 4; nf++) {
            float* cc = acc[mf][nf];
            int row0 = bm * 128 + wm * 64 + mf * 16 + er;
            int col  = bn * 128 + wn * 32 + nf * 8 + ec;
            #pragma unroll
            for (int half = 0; half < 2; half++) {
                int row = row0 + half * 8;
                float v0 = cc[half * 2 + 0];
                float v1 = cc[half * 2 + 1];
                if (BIAS) { v0 += bias[col]; v1 += bias[col + 1]; }
                if (ACT == 1) { v0 = act_sigmoid(v0); v1 = act_sigmoid(v1); }
                if (ACT == 2) { v0 = act_gelu(v0);    v1 = act_gelu(v1); }
                if (RESOP != 0) {
                    float r0, r1;
                    if (RESHALF) {
                        __half2 rv = *reinterpret_cast<const __half2*>(
                            (const __half*)res + (size_t)row * N + col);
                        r0 = __half2float(__low2half(rv));
                        r1 = __half2float(__high2half(rv));
                    } else {
                        float2 rv = *reinterpret_cast<const float2*>(
                            (const float*)res + (size_t)row * N + col);
                        r0 = rv.x; r1 = rv.y;
                    }
                    if (RESOP == 1) { v0 += r0; v1 += r1; }
                    else            { v0 *= r0; v1 *= r1; }
                }
                if (OUTMODE == 2) {
                    *reinterpret_cast<__half2*>(Cp + (size_t)row * ldOut + col) =
                        __halves2half2(__float2half_rn(v0), __float2half_rn(v1));
                } else {
                    *reinterpret_cast<float2*>(Cf + (size_t)row * N + col) = make_float2(v0, v1);
                }
            }
        }
    }
}

// ---------------------------------------------------------------------------
// RMSNorm writers
// ---------------------------------------------------------------------------
__global__ void rmsnorm_pair_kernel(const float* __restrict__ x,
                                    const float* __restrict__ w,
                                    __half* __restrict__ outp) {
    int row = blockIdx.x;
    int tid = threadIdx.x;
    const float4* xr = reinterpret_cast<const float4*>(x + (size_t)row * D);
    float4 v = xr[tid];
    float s = v.x * v.x + v.y * v.y + v.z * v.z + v.w * v.w;
    #pragma unroll
    for (int o = 16; o > 0; o >>= 1) s += __shfl_xor_sync(0xffffffffu, s, o);
    __shared__ float sm[8];
    if ((tid & 31) == 0) sm[tid >> 5] = s;
    __syncthreads();
    float tot = 0.f;
    #pragma unroll
    for (int i = 0; i < 8; i++) tot += sm[i];
    float scale = rsqrtf(tot * (1.0f / D) + EPS);
    float4 wv = reinterpret_cast<const float4*>(w)[tid];
    float o[4] = { v.x * scale * wv.x, v.y * scale * wv.y,
                   v.z * scale * wv.z, v.w * scale * wv.w };
    __half h[4], l[4];
    #pragma unroll
    for (int i = 0; i < 4; i++) split_h(o[i], h[i], l[i]);
    __half2* hp = reinterpret_cast<__half2*>(outp + (size_t)row * 2 * D + tid * 4);
    __half2* lp = reinterpret_cast<__half2*>(outp + (size_t)row * 2 * D + D + tid * 4);
    hp[0] = __halves2half2(h[0], h[1]); hp[1] = __halves2half2(h[2], h[3]);
    lp[0] = __halves2half2(l[0], l[1]); lp[1] = __halves2half2(l[2], l[3]);
}

__global__ void rmsnorm_hi_kernel(const float* __restrict__ x,
                                  const float* __restrict__ w,
                                  __half* __restrict__ outh) {
    int row = blockIdx.x;
    int tid = threadIdx.x;
    const float4* xr = reinterpret_cast<const float4*>(x + (size_t)row * D);
    float4 v = xr[tid];
    float s = v.x * v.x + v.y * v.y + v.z * v.z + v.w * v.w;
    #pragma unroll
    for (int o = 16; o > 0; o >>= 1) s += __shfl_xor_sync(0xffffffffu, s, o);
    __shared__ float sm[8];
    if ((tid & 31) == 0) sm[tid >> 5] = s;
    __syncthreads();
    float tot = 0.f;
    #pragma unroll
    for (int i = 0; i < 8; i++) tot += sm[i];
    float scale = rsqrtf(tot * (1.0f / D) + EPS);
    float4 wv = reinterpret_cast<const float4*>(w)[tid];
    __half2* hp = reinterpret_cast<__half2*>(outh + (size_t)row * D + tid * 4);
    hp[0] = __halves2half2(__float2half_rn(v.x * scale * wv.x),
                           __float2half_rn(v.y * scale * wv.y));
    hp[1] = __halves2half2(__float2half_rn(v.z * scale * wv.z),
                           __float2half_rn(v.w * scale * wv.w));
}

// Weight fp32 -> fp16 hi-only (same shape)
__global__ void whi_kernel(const float* __restrict__ W,
                           __half* __restrict__ out) {
    size_t g = ((size_t)blockIdx.x * blockDim.x + threadIdx.x) * 4;
    float4 v = *reinterpret_cast<const float4*>(W + g);
    __half2* o = reinterpret_cast<__half2*>(out + g);
    o[0] = __halves2half2(__float2half_rn(v.x), __float2half_rn(v.y));
    o[1] = __halves2half2(__float2half_rn(v.z), __float2half_rn(v.w));
}

// ---------------------------------------------------------------------------
// Depthwise causal conv (K=4) -> fp32 conv + fp16 pair
// ---------------------------------------------------------------------------
__global__ void conv_kernel(const float* __restrict__ conv_buf,
                            const float* __restrict__ conv_w,
                            const float* __restrict__ conv_b) {
    size_t g = (size_t)blockIdx.x * blockDim.x + threadIdx.x;
    int d = (int)(g % D);
    int m = (int)(g / D);
    int b = m / T;
    int t = m % T;
    float4 cw = reinterpret_cast<const float4*>(conv_w)[d];
    float wk[4] = { cw.x, cw.y, cw.z, cw.w };
    float acc = conv_b[d];
    #pragma unroll
    for (int k = 0; k < 4; k++) {
        int j = t + k;
        float src = (j < 3) ? conv_buf[((size_t)b * 3 + j) * D + d]
                            : g_b1[((size_t)b * T + (j - 3)) * D + d];
        acc = fmaf(src, wk[k], acc);
    }
    g_conv[g] = acc;
    __half h, l;
    split_h(acc, h, l);
    g_conv_p[(size_t)m * 2 * D + d] = h;
    g_conv_p[(size_t)m * 2 * D + D + d] = l;
}

__global__ void convbuf_out_kernel(float* __restrict__ out) {
    int idx = blockIdx.x * blockDim.x + threadIdx.x;
    int d = idx % D;
    int j = (idx / D) % 3;
    int b = idx / (3 * D);
    out[idx] = g_b1[((size_t)b * T + (T - 3 + j)) * D + d];
}

__global__ void au_kernel(const float* __restrict__ log_lambda) {
    size_t g = (size_t)blockIdx.x * blockDim.x + threadIdx.x;
    int d = (int)(g % D);
    float ll = log_lambda[d];
    float ls = -log1pf(expf(-ll));
    float r = g_r[g];
    float i = g_i[g];
    float c = g_conv[g];
    float a = expf(C_EXP * r * ls);
    float gate = sqrtf(fmaxf((1.0f - a) * (1.0f + a), 1e-6f));
    g_au[g] = make_float2(a, gate * (i * c));
}

__global__ void scan_kernel(const float* __restrict__ h0, float* __restrict__ out_h) {
    int g = blockIdx.x * blockDim.x + threadIdx.x;
    int d = g % D;
    int b = g / D;
    float h = h0[g];
    const float2* au = g_au + (size_t)b * T * D + d;
    float* o = g_b1out + (size_t)b * T * D + d;
    #pragma unroll 8
    for (int t = 0; t < T; t++) {
        float2 v = au[(size_t)t * D];
        h = fmaf(v.x, h, v.y);
        o[(size_t)t * D] = h;
    }
    out_h[g] = h;
}

// ---------------------------------------------------------------------------
// Launch
// ---------------------------------------------------------------------------
extern "C" void kernel_launch(void* const* d_in, const int* in_sizes, int n_in,
                              void* d_out, int out_size) {
    const float* x_seq      = (const float*)d_in[0];
    const float* h0         = (const float*)d_in[1];
    const float* conv_buf   = (const float*)d_in[2];
    const float* norm1_w    = (const float*)d_in[3];
    const float* W1         = (const float*)d_in[4];
    const float* conv_w     = (const float*)d_in[5];
    const float* conv_b     = (const float*)d_in[6];
    const float* Wa         = (const float*)d_in[7];
    const float* ba         = (const float*)d_in[8];
    const float* Wx         = (const float*)d_in[9];
    const float* bx         = (const float*)d_in[10];
    const float* log_lambda = (const float*)d_in[11];
    const float* W2         = (const float*)d_in[12];
    const float* Wout       = (const float*)d_in[13];
    const float* norm2_w    = (const float*)d_in[14];
    const float* Wg         = (const float*)d_in[15];
    const float* Wu         = (const float*)d_in[16];
    const float* Wo         = (const float*)d_in[17];

    float* out_x2 = (float*)d_out;
    float* out_h  = out_x2 + (size_t)M * D;
    float* out_cb = out_h + (size_t)B * D;

    __half *p_normed, *p_convp, *p_prodh, *p_n2h, *p_acth, *p_gh;
    __half *p_w1, *p_wa, *p_wx, *p_w2, *p_wout, *p_wg, *p_wu, *p_wo;
    float *p_b1, *p_r, *p_i, *p_b1out, *p_x1;
    cudaGetSymbolAddress((void**)&p_normed, g_normed_p);
    cudaGetSymbolAddress((void**)&p_convp,  g_conv_p);
    cudaGetSymbolAddress((void**)&p_prodh,  g_prod_h);
    cudaGetSymbolAddress((void**)&p_n2h,    g_n2_h);
    cudaGetSymbolAddress((void**)&p_acth,   g_act_h);
    cudaGetSymbolAddress((void**)&p_gh,     g_gh);
    cudaGetSymbolAddress((void**)&p_w1,     g_w1h);
    cudaGetSymbolAddress((void**)&p_wa,     g_wah);
    cudaGetSymbolAddress((void**)&p_wx,     g_wxh);
    cudaGetSymbolAddress((void**)&p_w2,     g_w2h);
    cudaGetSymbolAddress((void**)&p_wout,   g_wouth);
    cudaGetSymbolAddress((void**)&p_wg,     g_wgh);
    cudaGetSymbolAddress((void**)&p_wu,     g_wuh);
    cudaGetSymbolAddress((void**)&p_wo,     g_woh);
    cudaGetSymbolAddress((void**)&p_b1,     g_b1);
    cudaGetSymbolAddress((void**)&p_r,      g_r);
    cudaGetSymbolAddress((void**)&p_i,      g_i);
    cudaGetSymbolAddress((void**)&p_b1out,  g_b1out);
    cudaGetSymbolAddress((void**)&p_x1,     g_x1);

    auto k2Plain  = gemm_mma<2, 0, 0, false, 0, false>;  // b1 -> fp32
    auto k2Sig    = gemm_mma<2, 1, 0, true,  0, false>;  // r, i -> fp32
    auto k1GeluMH = gemm_mma<1, 2, 2, false, 2, false>;  // gelu(b2)*b1out -> prod_h
    auto k1Add    = gemm_mma<1, 0, 1, false, 0, false>;  // x1, x2 (fp32 res add)
    auto k1GeluH  = gemm_mma<1, 2, 0, false, 2, false>;  // g -> fp16
    auto k1MulHH  = gemm_mma<1, 0, 2, false, 2, true>;   // act = (n2@Wu)*g_h -> fp16
    constexpr int SM1 = StageCfg<1>::SMEM;   // 65536
    constexpr int SM2 = StageCfg<2>::SMEM;   // 98304
    cudaFuncSetAttribute(k2Plain,  cudaFuncAttributeMaxDynamicSharedMemorySize, SM2);
    cudaFuncSetAttribute(k2Sig,    cudaFuncAttributeMaxDynamicSharedMemorySize, SM2);
    cudaFuncSetAttribute(k1GeluMH, cudaFuncAttributeMaxDynamicSharedMemorySize, SM1);
    cudaFuncSetAttribute(k1Add,    cudaFuncAttributeMaxDynamicSharedMemorySize, SM1);
    cudaFuncSetAttribute(k1GeluH,  cudaFuncAttributeMaxDynamicSharedMemorySize, SM1);
    cudaFuncSetAttribute(k1MulHH,  cudaFuncAttributeMaxDynamicSharedMemorySize, SM1);

    dim3 gD(D / 128, M / 128);     // (8, 128)
    dim3 gH(H / 128, M / 128);     // (32, 128)
    int ewBlocks = (int)(((size_t)M * D) / 256);

    // Launch order: b1 GEMM is launch #6 (ncu -s 5 -c 1 captures it).
    rmsnorm_pair_kernel<<<M, 256>>>(x_seq, norm1_w, p_normed);           // 1
    whi_kernel<<<(D * D) / 1024, 256>>>(W1, p_w1);                       // 2
    whi_kernel<<<(D * D) / 1024, 256>>>(Wa, p_wa);                       // 3
    whi_kernel<<<(D * D) / 1024, 256>>>(Wx, p_wx);                       // 4
    whi_kernel<<<(D * D) / 1024, 256>>>(W2, p_w2);                       // 5

    // 6: b1 = normed @ W1^T  (2-term)
    k2Plain<<<gD, 256, SM2>>>(p_normed, p_w1, 2 * D, D, D, 32,
                              nullptr, nullptr, p_b1, nullptr, D, 0);

    conv_kernel<<<ewBlocks, 256>>>(conv_buf, conv_w, conv_b);
    convbuf_out_kernel<<<(B * 3 * D) / 256, 256>>>(out_cb);

    // r, i  (2-term: conv pair x W hi)
    k2Sig<<<gD, 256, SM2>>>(p_convp, p_wa, 2 * D, D, D, 32,
                            ba, nullptr, p_r, nullptr, D, 0);
    k2Sig<<<gD, 256, SM2>>>(p_convp, p_wx, 2 * D, D, D, 32,
                            bx, nullptr, p_i, nullptr, D, 0);

    au_kernel<<<ewBlocks, 256>>>(log_lambda);
    scan_kernel<<<(B * D) / 256, 256>>>(h0, out_h);

    whi_kernel<<<(D * D) / 1024, 256>>>(Wout, p_wout);
    whi_kernel<<<(H * D) / 1024, 256>>>(Wg,   p_wg);
    whi_kernel<<<(H * D) / 1024, 256>>>(Wu,   p_wu);
    whi_kernel<<<(D * H) / 1024, 256>>>(Wo,   p_wo);

    // prod = gelu(normed @ W2^T) * b1out  -> fp16 (fused b2+prod)
    k1GeluMH<<<gD, 256, SM1>>>(p_normed, p_w2, 2 * D, D, D, 32,
                               nullptr, p_b1out, nullptr, p_prodh, D, D);

    // x1 = x_seq + prod @ Wout^T
    k1Add<<<gD, 256, SM1>>>(p_prodh, p_wout, D, D, D, 32,
                            nullptr, x_seq, p_x1, nullptr, D, 0);

    // n2 (hi only)
    rmsnorm_hi_kernel<<<M, 256>>>(p_x1, norm2_w, p_n2h);

    // g = gelu(n2 @ Wg^T) -> fp16; act = (n2 @ Wu^T) * g -> fp16
    k1GeluH<<<gH, 256, SM1>>>(p_n2h, p_wg, D, D, D, 32,
                              nullptr, nullptr, nullptr, p_gh, H, H);
    k1MulHH<<<gH, 256, SM1>>>(p_n2h, p_wu, D, D, D, 32,
                              nullptr, p_gh, nullptr, p_acth, H, H);

    // x2 = x1 + act @ Wo^T
    k1Add<<<gD, 256, SM1>>>(p_acth, p_wo, H, H, H, 128,
                            nullptr, p_x1, out_x2, nullptr, D, 0);
}

// round 11
// speedup vs baseline: 5.7071x; 1.1151x over previous
#include <cuda_runtime.h>
#include <cuda_fp16.h>
#include <math.h>
#include <stdint.h>

// ---------------------------------------------------------------------------
// GriffinTemporalBlock on GB300 (classic mma.sync fp16 path).
// All GEMMs 1-term plain fp16 (A_hi x B_hi).  a/u computation fused into the
// i-GEMM epilogue; single fused weight-conversion kernel.
// B=16, T=1024, D=1024, H=4096.
// ---------------------------------------------------------------------------

constexpr int B = 16;
constexpr int T = 1024;
constexpr int D = 1024;
constexpr int H = 4096;
constexpr int M = B * T;               // 16384
constexpr float EPS = 1.1920929e-07f;
constexpr float C_EXP = 8.0f;

// ----- scratch (static device globals) -------------------------------------
__device__ __half g_normed_h[(size_t)M * D];
__device__ __half g_conv_h  [(size_t)M * D];
__device__ __half g_prod_h  [(size_t)M * D];
__device__ __half g_n2_h    [(size_t)M * D];
__device__ __half g_act_h   [(size_t)M * H];
__device__ __half g_gh      [(size_t)M * H];

__device__ __half g_w1h  [(size_t)D * D];
__device__ __half g_wah  [(size_t)D * D];
__device__ __half g_wxh  [(size_t)D * D];
__device__ __half g_w2h  [(size_t)D * D];
__device__ __half g_wouth[(size_t)D * D];
__device__ __half g_wgh  [(size_t)H * D];
__device__ __half g_wuh  [(size_t)H * D];
__device__ __half g_woh  [(size_t)D * H];

__device__ float  g_b1   [(size_t)M * D];
__device__ float  g_conv [(size_t)M * D];
__device__ float  g_r    [(size_t)M * D];
__device__ __align__(16) float2 g_au [(size_t)M * D];
__device__ float  g_b1out[(size_t)M * D];
__device__ float  g_x1   [(size_t)M * D];

// ---------------------------------------------------------------------------
// helpers
// ---------------------------------------------------------------------------
__device__ __forceinline__ uint32_t smem_u32(const void* p) {
    uint32_t a;
    asm("{ .reg .u64 t; cvta.to.shared.u64 t, %1; cvt.u32.u64 %0, t; }"
        : "=r"(a) : "l"(p));
    return a;
}

#define CP_ASYNC16(dst, src) \
    asm volatile("cp.async.cg.shared.global [%0], [%1], 16;" :: "r"(dst), "l"(src) : "memory")
#define CP_COMMIT() asm volatile("cp.async.commit_group;" ::: "memory")
#define CP_WAIT2()  asm volatile("cp.async.wait_group 2;" ::: "memory")

#define LDSM4(R, addr) \
    asm volatile("ldmatrix.sync.aligned.m8n8.x4.shared.b16 {%0,%1,%2,%3}, [%4];" \
        : "=r"((R)[0]), "=r"((R)[1]), "=r"((R)[2]), "=r"((R)[3]) : "r"(addr))

#define MMA_F16(d, a, b0v, b1v) \
    asm volatile("mma.sync.aligned.m16n8k16.row.col.f32.f16.f16.f32 " \
        "{%0,%1,%2,%3}, {%4,%5,%6,%7}, {%8,%9}, {%0,%1,%2,%3};" \
        : "+f"((d)[0]), "+f"((d)[1]), "+f"((d)[2]), "+f"((d)[3]) \
        : "r"((a)[0]), "r"((a)[1]), "r"((a)[2]), "r"((a)[3]), "r"(b0v), "r"(b1v))

__device__ __forceinline__ float act_sigmoid(float x) { return 1.0f / (1.0f + expf(-x)); }
__device__ __forceinline__ float act_gelu(float x)    { return 0.5f * x * (1.0f + erff(x * 0.70710678118654752f)); }

// ---------------------------------------------------------------------------
// mma.sync GEMM, 1-term fp16 (A hi x B hi).  Block 128x128, BK=32, 8 warps
// (64x32 warp tiles), 4-stage cp.async pipeline, SW64 tiles (128 rows x 64B).
// ACT: 0 none, 1 sigmoid, 2 gelu.  RESOP: 0 none, 1 add, 2 mul.
// OUTMODE: 0 fp32 Cf (ld N), 2 fp16 Cp (ld ldOut).  RESHALF: res fp16.
// AUFUSE: epilogue computes i=sigmoid(acc+bias), reads r (res) and conv
// (aux1), log_lambda (aux2), writes (a, u) float2 pairs into Cau.
// ---------------------------------------------------------------------------
constexpr int ABYTES = 8192;
constexpr int BBYTES = 8192;
constexpr int STAGE  = ABYTES + BBYTES;        // 16384
constexpr int SMEM_B = 4 * STAGE;              // 65536

__device__ __forceinline__ void produce_stage(uint32_t sb,
        const __half* Ab, const __half* Bb,
        int ldA, int ldB, int j, int tid) {
    int k0 = j * 32;
    uint32_t stage = sb + (uint32_t)(j & 3) * STAGE;
    #pragma unroll
    for (int ch = 0; ch < 4; ch++) {
        int c = tid + (ch << 8);                   // 0..1023
        int r = c >> 2, q = c & 3;
        int qq = q ^ ((r >> 1) & 3);               // SW64
        if (c < 512) {
            CP_ASYNC16(stage + (uint32_t)(r * 64 + qq * 16),
                       Ab + (size_t)r * ldA + k0 + q * 8);
        } else {
            int rr = r - 128;
            int qq2 = q ^ ((rr >> 1) & 3);
            CP_ASYNC16(stage + (uint32_t)ABYTES + (uint32_t)(rr * 64 + qq2 * 16),
                       Bb + (size_t)rr * ldB + k0 + q * 8);
        }
    }
    CP_COMMIT();
}

template <int ACT, int RESOP, bool BIAS, int OUTMODE, bool RESHALF, bool AUFUSE>
__global__ void __launch_bounds__(256)
gemm_mma(const __half* __restrict__ A, const __half* __restrict__ Bw,
         int ldA, int ldB, int iters,
         const float* __restrict__ bias, const void* __restrict__ res,
         float* __restrict__ Cf, __half* __restrict__ Cp,
         int N, int ldOut,
         const float* __restrict__ aux1, const float* __restrict__ aux2,
         float2* __restrict__ Cau) {
    extern __shared__ char smem[];
    uint32_t sb = smem_u32(smem);
    int tid = threadIdx.x;
    int wid = tid >> 5, lid = tid & 31;
    int wm = wid >> 2, wn = wid & 3;               // warp grid 2x4
    int lr = lid & 15, lc = lid >> 4;

    int bm = blockIdx.y, bn = blockIdx.x;
    const __half* Ab = A  + (size_t)(bm * 128) * ldA;
    const __half* Bb = Bw + (size_t)(bn * 128) * ldB;

    float acc[4][4][4];
    #pragma unroll
    for (int i = 0; i < 4; i++)
        #pragma unroll
        for (int j = 0; j < 4; j++)
            #pragma unroll
            for (int q = 0; q < 4; q++) acc[i][j][q] = 0.f;

    produce_stage(sb, Ab, Bb, ldA, ldB, 0, tid);
    produce_stage(sb, Ab, Bb, ldA, ldB, 1, tid);
    produce_stage(sb, Ab, Bb, ldA, ldB, 2, tid);

    for (int it = 0; it < iters; ++it) {
        CP_WAIT2();
        __syncthreads();
        uint32_t sa  = sb + (uint32_t)(it & 3) * STAGE;
        uint32_t sbt = sa + (uint32_t)ABYTES;

        #pragma unroll
        for (int kk = 0; kk < 2; kk++) {
            int chunk = kk * 2 + lc;
            uint32_t a[4][4];
            #pragma unroll
            for (int mf = 0; mf < 4; mf++) {
                int row = wm * 64 + mf * 16 + lr;
                int qq = chunk ^ ((row >> 1) & 3);
                LDSM4(a[mf], sa + (uint32_t)(row * 64 + qq * 16));
            }
            uint32_t bb[2][4];
            #pragma unroll
            for (int nf2 = 0; nf2 < 2; nf2++) {
                int row = wn * 32 + nf2 * 16 + lr;
                int qq = chunk ^ ((row >> 1) & 3);
                LDSM4(bb[nf2], sbt + (uint32_t)(row * 64 + qq * 16));
            }
            #pragma unroll
            for (int mf = 0; mf < 4; mf++)
                #pragma unroll
                for (int nf = 0; nf < 4; nf++) {
                    int n2 = nf >> 1, sel = nf & 1;
                    MMA_F16(acc[mf][nf], a[mf], bb[n2][sel], bb[n2][2 + sel]);
                }
        }
        __syncthreads();
        int j = it + 3;
        if (j < iters) produce_stage(sb, Ab, Bb, ldA, ldB, j, tid);
        else           CP_COMMIT();
    }

    // epilogue
    int er = lid >> 2;
    int ec = (lid & 3) * 2;
    #pragma unroll
    for (int mf = 0; mf < 4; mf++) {
        #pragma unroll
        for (int nf = 0; nf < 4; nf++) {
            float* cc = acc[mf][nf];
            int row0 = bm * 128 + wm * 64 + mf * 16 + er;
            int col  = bn * 128 + wn * 32 + nf * 8 + ec;
            #pragma unroll
            for (int half = 0; half < 2; half++) {
                int row = row0 + half * 8;
                float v0 = cc[half * 2 + 0];
                float v1 = cc[half * 2 + 1];
                if (BIAS) { v0 += bias[col]; v1 += bias[col + 1]; }
                if (AUFUSE) {
                    float i0 = act_sigmoid(v0), i1 = act_sigmoid(v1);
                    size_t idx = (size_t)row * N + col;
                    float r0 = ((const float*)res)[idx];
                    float r1 = ((const float*)res)[idx + 1];
                    float c0 = aux1[idx], c1 = aux1[idx + 1];
                    float ll0 = aux2[col], ll1 = aux2[col + 1];
                    float ls0 = -log1pf(expf(-ll0));
                    float ls1 = -log1pf(expf(-ll1));
                    float a0 = expf(C_EXP * r0 * ls0);
                    float a1 = expf(C_EXP * r1 * ls1);
                    float gt0 = sqrtf(fmaxf((1.0f - a0) * (1.0f + a0), 1e-6f));
                    float gt1 = sqrtf(fmaxf((1.0f - a1) * (1.0f + a1), 1e-6f));
                    Cau[idx]     = make_float2(a0, gt0 * (i0 * c0));
                    Cau[idx + 1] = make_float2(a1, gt1 * (i1 * c1));
                    continue;
                }
                if (ACT == 1) { v0 = act_sigmoid(v0); v1 = act_sigmoid(v1); }
                if (ACT == 2) { v0 = act_gelu(v0);    v1 = act_gelu(v1); }
                if (RESOP != 0) {
                    float r0, r1;
                    if (RESHALF) {
                        __half2 rv = *reinterpret_cast<const __half2*>(
                            (const __half*)res + (size_t)row * N + col);
                        r0 = __half2float(__low2half(rv));
                        r1 = __half2float(__high2half(rv));
                    } else {
                        float2 rv = *reinterpret_cast<const float2*>(
                            (const float*)res + (size_t)row * N + col);
                        r0 = rv.x; r1 = rv.y;
                    }
                    if (RESOP == 1) { v0 += r0; v1 += r1; }
                    else            { v0 *= r0; v1 *= r1; }
                }
                if (OUTMODE == 2) {
                    *reinterpret_cast<__half2*>(Cp + (size_t)row * ldOut + col) =
                        __halves2half2(__float2half_rn(v0), __float2half_rn(v1));
                } else {
                    *reinterpret_cast<float2*>(Cf + (size_t)row * N + col) = make_float2(v0, v1);
                }
            }
        }
    }
}

// ---------------------------------------------------------------------------
// RMSNorm -> fp16 hi
// ---------------------------------------------------------------------------
__global__ void rmsnorm_hi_kernel(const float* __restrict__ x,
                                  const float* __restrict__ w,
                                  __half* __restrict__ outh) {
    int row = blockIdx.x;
    int tid = threadIdx.x;
    const float4* xr = reinterpret_cast<const float4*>(x + (size_t)row * D);
    float4 v = xr[tid];
    float s = v.x * v.x + v.y * v.y + v.z * v.z + v.w * v.w;
    #pragma unroll
    for (int o = 16; o > 0; o >>= 1) s += __shfl_xor_sync(0xffffffffu, s, o);
    __shared__ float sm[8];
    if ((tid & 31) == 0) sm[tid >> 5] = s;
    __syncthreads();
    float tot = 0.f;
    #pragma unroll
    for (int i = 0; i < 8; i++) tot += sm[i];
    float scale = rsqrtf(tot * (1.0f / D) + EPS);
    float4 wv = reinterpret_cast<const float4*>(w)[tid];
    __half2* hp = reinterpret_cast<__half2*>(outh + (size_t)row * D + tid * 4);
    hp[0] = __halves2half2(__float2half_rn(v.x * scale * wv.x),
                           __float2half_rn(v.y * scale * wv.y));
    hp[1] = __halves2half2(__float2half_rn(v.z * scale * wv.z),
                           __float2half_rn(v.w * scale * wv.w));
}

// ---------------------------------------------------------------------------
// Fused weight conversion: all 8 weights fp32 -> fp16 in one launch.
// Segments (in float4 chunks): 5 x D*D/4, then 3 x H*D/4.
// ---------------------------------------------------------------------------
constexpr size_t WCH_S = (size_t)D * D / 4;     // 262144
constexpr size_t WCH_L = (size_t)H * D / 4;     // 1048576
constexpr size_t WCH_TOTAL = 5 * WCH_S + 3 * WCH_L;   // 4456448

__global__ void whi_all_kernel(const float* __restrict__ W1,
                               const float* __restrict__ Wa,
                               const float* __restrict__ Wx,
                               const float* __restrict__ W2,
                               const float* __restrict__ Wout,
                               const float* __restrict__ Wg,
                               const float* __restrict__ Wu,
                               const float* __restrict__ Wo) {
    size_t c = (size_t)blockIdx.x * blockDim.x + threadIdx.x;
    if (c >= WCH_TOTAL) return;
    const float* src;
    __half* dst;
    size_t off;
    if (c < 5 * WCH_S) {
        int seg = (int)(c / WCH_S);
        off = c % WCH_S;
        src = (seg == 0) ? W1 : (seg == 1) ? Wa : (seg == 2) ? Wx
            : (seg == 3) ? W2 : Wout;
        dst = (seg == 0) ? g_w1h : (seg == 1) ? g_wah : (seg == 2) ? g_wxh
            : (seg == 3) ? g_w2h : g_wouth;
    } else {
        size_t c2 = c - 5 * WCH_S;
        int seg = (int)(c2 / WCH_L);
        off = c2 % WCH_L;
        src = (seg == 0) ? Wg : (seg == 1) ? Wu : Wo;
        dst = (seg == 0) ? g_wgh : (seg == 1) ? g_wuh : g_woh;
    }
    float4 v = reinterpret_cast<const float4*>(src)[off];
    __half2* o = reinterpret_cast<__half2*>(dst + off * 4);
    o[0] = __halves2half2(__float2half_rn(v.x), __float2half_rn(v.y));
    o[1] = __halves2half2(__float2half_rn(v.z), __float2half_rn(v.w));
}

// ---------------------------------------------------------------------------
// Depthwise causal conv (K=4) -> fp32 conv + fp16 hi
// ---------------------------------------------------------------------------
__global__ void conv_kernel(const float* __restrict__ conv_buf,
                            const float* __restrict__ conv_w,
                            const float* __restrict__ conv_b) {
    size_t g = (size_t)blockIdx.x * blockDim.x + threadIdx.x;
    int d = (int)(g % D);
    int m = (int)(g / D);
    int b = m / T;
    int t = m % T;
    float4 cw = reinterpret_cast<const float4*>(conv_w)[d];
    float wk[4] = { cw.x, cw.y, cw.z, cw.w };
    float acc = conv_b[d];
    #pragma unroll
    for (int k = 0; k < 4; k++) {
        int j = t + k;
        float src = (j < 3) ? conv_buf[((size_t)b * 3 + j) * D + d]
                            : g_b1[((size_t)b * T + (j - 3)) * D + d];
        acc = fmaf(src, wk[k], acc);
    }
    g_conv[g] = acc;
    g_conv_h[g] = __float2half_rn(acc);
}

__global__ void convbuf_out_kernel(float* __restrict__ out) {
    int idx = blockIdx.x * blockDim.x + threadIdx.x;
    int d = idx % D;
    int j = (idx / D) % 3;
    int b = idx / (3 * D);
    out[idx] = g_b1[((size_t)b * T + (T - 3 + j)) * D + d];
}

__global__ void scan_kernel(const float* __restrict__ h0, float* __restrict__ out_h) {
    int g = blockIdx.x * blockDim.x + threadIdx.x;
    int d = g % D;
    int b = g / D;
    float h = h0[g];
    const float2* au = g_au + (size_t)b * T * D + d;
    float* o = g_b1out + (size_t)b * T * D + d;
    #pragma unroll 8
    for (int t = 0; t < T; t++) {
        float2 v = au[(size_t)t * D];
        h = fmaf(v.x, h, v.y);
        o[(size_t)t * D] = h;
    }
    out_h[g] = h;
}

// ---------------------------------------------------------------------------
// Launch
// ---------------------------------------------------------------------------
extern "C" void kernel_launch(void* const* d_in, const int* in_sizes, int n_in,
                              void* d_out, int out_size) {
    const float* x_seq      = (const float*)d_in[0];
    const float* h0         = (const float*)d_in[1];
    const float* conv_buf   = (const float*)d_in[2];
    const float* norm1_w    = (const float*)d_in[3];
    const float* W1         = (const float*)d_in[4];
    const float* conv_w     = (const float*)d_in[5];
    const float* conv_b     = (const float*)d_in[6];
    const float* Wa         = (const float*)d_in[7];
    const float* ba         = (const float*)d_in[8];
    const float* Wx         = (const float*)d_in[9];
    const float* bx         = (const float*)d_in[10];
    const float* log_lambda = (const float*)d_in[11];
    const float* W2         = (const float*)d_in[12];
    const float* Wout       = (const float*)d_in[13];
    const float* norm2_w    = (const float*)d_in[14];
    const float* Wg         = (const float*)d_in[15];
    const float* Wu         = (const float*)d_in[16];
    const float* Wo         = (const float*)d_in[17];

    float* out_x2 = (float*)d_out;
    float* out_h  = out_x2 + (size_t)M * D;
    float* out_cb = out_h + (size_t)B * D;

    __half *p_normed, *p_convh, *p_prodh, *p_n2h, *p_acth, *p_gh;
    __half *p_w1, *p_wa, *p_wx, *p_w2, *p_wout, *p_wg, *p_wu, *p_wo;
    float *p_b1, *p_conv, *p_r, *p_b1out, *p_x1;
    float2 *p_au;
    cudaGetSymbolAddress((void**)&p_normed, g_normed_h);
    cudaGetSymbolAddress((void**)&p_convh,  g_conv_h);
    cudaGetSymbolAddress((void**)&p_prodh,  g_prod_h);
    cudaGetSymbolAddress((void**)&p_n2h,    g_n2_h);
    cudaGetSymbolAddress((void**)&p_acth,   g_act_h);
    cudaGetSymbolAddress((void**)&p_gh,     g_gh);
    cudaGetSymbolAddress((void**)&p_w1,     g_w1h);
    cudaGetSymbolAddress((void**)&p_wa,     g_wah);
    cudaGetSymbolAddress((void**)&p_wx,     g_wxh);
    cudaGetSymbolAddress((void**)&p_w2,     g_w2h);
    cudaGetSymbolAddress((void**)&p_wout,   g_wouth);
    cudaGetSymbolAddress((void**)&p_wg,     g_wgh);
    cudaGetSymbolAddress((void**)&p_wu,     g_wuh);
    cudaGetSymbolAddress((void**)&p_wo,     g_woh);
    cudaGetSymbolAddress((void**)&p_b1,     g_b1);
    cudaGetSymbolAddress((void**)&p_conv,   g_conv);
    cudaGetSymbolAddress((void**)&p_r,      g_r);
    cudaGetSymbolAddress((void**)&p_au,     g_au);
    cudaGetSymbolAddress((void**)&p_b1out,  g_b1out);
    cudaGetSymbolAddress((void**)&p_x1,     g_x1);

    auto kPlain  = gemm_mma<0, 0, false, 0, false, false>;  // b1 -> fp32
    auto kSig    = gemm_mma<1, 0, true,  0, false, false>;  // r -> fp32
    auto kAU     = gemm_mma<0, 0, true,  0, false, true>;   // i + a/u fused
    auto kGeluMH = gemm_mma<2, 2, false, 2, false, false>;  // gelu(b2)*b1out -> prod_h
    auto kAdd    = gemm_mma<0, 1, false, 0, false, false>;  // x1, x2
    auto kGeluH  = gemm_mma<2, 0, false, 2, false, false>;  // g -> fp16
    auto kMulHH  = gemm_mma<0, 2, false, 2, true,  false>;  // act = (n2@Wu)*g_h
    cudaFuncSetAttribute(kPlain,  cudaFuncAttributeMaxDynamicSharedMemorySize, SMEM_B);
    cudaFuncSetAttribute(kSig,    cudaFuncAttributeMaxDynamicSharedMemorySize, SMEM_B);
    cudaFuncSetAttribute(kAU,     cudaFuncAttributeMaxDynamicSharedMemorySize, SMEM_B);
    cudaFuncSetAttribute(kGeluMH, cudaFuncAttributeMaxDynamicSharedMemorySize, SMEM_B);
    cudaFuncSetAttribute(kAdd,    cudaFuncAttributeMaxDynamicSharedMemorySize, SMEM_B);
    cudaFuncSetAttribute(kGeluH,  cudaFuncAttributeMaxDynamicSharedMemorySize, SMEM_B);
    cudaFuncSetAttribute(kMulHH,  cudaFuncAttributeMaxDynamicSharedMemorySize, SMEM_B);

    dim3 gD(D / 128, M / 128);     // (8, 128)
    dim3 gH(H / 128, M / 128);     // (32, 128)
    int ewBlocks = (int)(((size_t)M * D) / 256);

    // 1. normed = rmsnorm(x_seq) -> fp16
    rmsnorm_hi_kernel<<<M, 256>>>(x_seq, norm1_w, p_normed);
    // 2. all weight conversions fused
    whi_all_kernel<<<(int)((WCH_TOTAL + 255) / 256), 256>>>(W1, Wa, Wx, W2, Wout, Wg, Wu, Wo);
    // 3. b1 = normed @ W1^T -> fp32
    kPlain<<<gD, 256, SMEM_B>>>(p_normed, p_w1, D, D, 32,
                                nullptr, nullptr, p_b1, nullptr, D, 0,
                                nullptr, nullptr, nullptr);
    // 4. conv
    conv_kernel<<<ewBlocks, 256>>>(conv_buf, conv_w, conv_b);
    // 5. conv_buf out
    convbuf_out_kernel<<<(B * 3 * D) / 256, 256>>>(out_cb);
    // 6. r = sigmoid(conv @ Wa^T + ba) -> fp32   (ncu -s 5 -c 1 lands here)
    kSig<<<gD, 256, SMEM_B>>>(p_convh, p_wa, D, D, 32,
                              ba, nullptr, p_r, nullptr, D, 0,
                              nullptr, nullptr, nullptr);
    // 7. i-GEMM with fused a/u: writes g_au
    kAU<<<gD, 256, SMEM_B>>>(p_convh, p_wx, D, D, 32,
                             bx, p_r, nullptr, nullptr, D, 0,
                             p_conv, log_lambda, p_au);
    // 8. scan -> b1out, out_h
    scan_kernel<<<(B * D) / 256, 256>>>(h0, out_h);
    // 9. prod = gelu(normed @ W2^T) * b1out -> fp16
    kGeluMH<<<gD, 256, SMEM_B>>>(p_normed, p_w2, D, D, 32,
                                 nullptr, p_b1out, nullptr, p_prodh, D, D,
                                 nullptr, nullptr, nullptr);
    // 10. x1 = x_seq + prod @ Wout^T -> fp32
    kAdd<<<gD, 256, SMEM_B>>>(p_prodh, p_wout, D, D, 32,
                              nullptr, x_seq, p_x1, nullptr, D, 0,
                              nullptr, nullptr, nullptr);
    // 11. n2 = rmsnorm(x1) -> fp16
    rmsnorm_hi_kernel<<<M, 256>>>(p_x1, norm2_w, p_n2h);
    // 12. g = gelu(n2 @ Wg^T) -> fp16
    kGeluH<<<gH, 256, SMEM_B>>>(p_n2h, p_wg, D, D, 32,
                                nullptr, nullptr, nullptr, p_gh, H, H,
                                nullptr, nullptr, nullptr);
    // 13. act = (n2 @ Wu^T) * g -> fp16
    kMulHH<<<gH, 256, SMEM_B>>>(p_n2h, p_wu, D, D, 32,
                                nullptr, p_gh, nullptr, p_acth, H, H,
                                nullptr, nullptr, nullptr);
    // 14. x2 = x1 + act @ Wo^T -> out
    kAdd<<<gD, 256, SMEM_B>>>(p_acth, p_wo, H, H, 128,
                              nullptr, p_x1, out_x2, nullptr, D, 0,
                              nullptr, nullptr, nullptr);
}

// round 12
// speedup vs baseline: 6.8343x; 1.1975x over previous
#include <cuda_runtime.h>
#include <cuda_fp16.h>
#include <math.h>
#include <stdint.h>

// ---------------------------------------------------------------------------
// GriffinTemporalBlock on GB300 (classic mma.sync fp16 path).
// All GEMMs 1-term fp16.  Dual-GEMM kernels for (r,i)->a/u and (Wg,Wu)->act.
// Rolling-window conv, 8-segment parallel scan.
// B=16, T=1024, D=1024, H=4096.
// ---------------------------------------------------------------------------

constexpr int B = 16;
constexpr int T = 1024;
constexpr int D = 1024;
constexpr int H = 4096;
constexpr int M = B * T;               // 16384
constexpr float EPS = 1.1920929e-07f;
constexpr float C_EXP = 8.0f;

constexpr int SC = 8;                  // scan segments
constexpr int SL = T / SC;             // 128

// ----- scratch (static device globals) -------------------------------------
__device__ __half g_normed_h[(size_t)M * D];
__device__ __half g_conv_h  [(size_t)M * D];
__device__ __half g_prod_h  [(size_t)M * D];
__device__ __half g_n2_h    [(size_t)M * D];
__device__ __half g_act_h   [(size_t)M * H];

__device__ __half g_w1h  [(size_t)D * D];
__device__ __half g_wah  [(size_t)D * D];
__device__ __half g_wxh  [(size_t)D * D];
__device__ __half g_w2h  [(size_t)D * D];
__device__ __half g_wouth[(size_t)D * D];
__device__ __half g_wgh  [(size_t)H * D];
__device__ __half g_wuh  [(size_t)H * D];
__device__ __half g_woh  [(size_t)D * H];

__device__ float  g_b1   [(size_t)M * D];
__device__ float  g_conv [(size_t)M * D];
__device__ __align__(16) float2 g_au [(size_t)M * D];
__device__ float  g_b1out[(size_t)M * D];
__device__ float  g_x1   [(size_t)M * D];
__device__ __align__(16) float2 g_seg[(size_t)B * SC * D];   // per-segment (A, U)
__device__ float  g_hstart[(size_t)B * SC * D];

// ---------------------------------------------------------------------------
// helpers
// ---------------------------------------------------------------------------
__device__ __forceinline__ uint32_t smem_u32(const void* p) {
    uint32_t a;
    asm("{ .reg .u64 t; cvta.to.shared.u64 t, %1; cvt.u32.u64 %0, t; }"
        : "=r"(a) : "l"(p));
    return a;
}

#define CP_ASYNC16(dst, src) \
    asm volatile("cp.async.cg.shared.global [%0], [%1], 16;" :: "r"(dst), "l"(src) : "memory")
#define CP_COMMIT() asm volatile("cp.async.commit_group;" ::: "memory")
#define CP_WAIT2()  asm volatile("cp.async.wait_group 2;" ::: "memory")

#define LDSM4(R, addr) \
    asm volatile("ldmatrix.sync.aligned.m8n8.x4.shared.b16 {%0,%1,%2,%3}, [%4];" \
        : "=r"((R)[0]), "=r"((R)[1]), "=r"((R)[2]), "=r"((R)[3]) : "r"(addr))

#define MMA_F16(d, a, b0v, b1v) \
    asm volatile("mma.sync.aligned.m16n8k16.row.col.f32.f16.f16.f32 " \
        "{%0,%1,%2,%3}, {%4,%5,%6,%7}, {%8,%9}, {%0,%1,%2,%3};" \
        : "+f"((d)[0]), "+f"((d)[1]), "+f"((d)[2]), "+f"((d)[3]) \
        : "r"((a)[0]), "r"((a)[1]), "r"((a)[2]), "r"((a)[3]), "r"(b0v), "r"(b1v))

__device__ __forceinline__ float act_sigmoid(float x) { return 1.0f / (1.0f + expf(-x)); }
__device__ __forceinline__ float act_gelu(float x)    { return 0.5f * x * (1.0f + erff(x * 0.70710678118654752f)); }

// ---------------------------------------------------------------------------
// Single GEMM (as round 10): 128x128 block, BK=32, 8 warps, SW64 tiles.
// ---------------------------------------------------------------------------
constexpr int ABYTES = 8192;
constexpr int STAGE  = 16384;
constexpr int SMEM_B = 4 * STAGE;              // 65536

__device__ __forceinline__ void produce_stage(uint32_t sb,
        const __half* Ab, const __half* Bb,
        int ldA, int ldB, int j, int tid) {
    int k0 = j * 32;
    uint32_t stage = sb + (uint32_t)(j & 3) * STAGE;
    #pragma unroll
    for (int ch = 0; ch < 4; ch++) {
        int c = tid + (ch << 8);                   // 0..1023
        int r = c >> 2, q = c & 3;
        if (c < 512) {
            int qq = q ^ ((r >> 1) & 3);           // SW64
            CP_ASYNC16(stage + (uint32_t)(r * 64 + qq * 16),
                       Ab + (size_t)r * ldA + k0 + q * 8);
        } else {
            int rr = r - 128;
            int qq2 = q ^ ((rr >> 1) & 3);
            CP_ASYNC16(stage + (uint32_t)ABYTES + (uint32_t)(rr * 64 + qq2 * 16),
                       Bb + (size_t)rr * ldB + k0 + q * 8);
        }
    }
    CP_COMMIT();
}

template <int ACT, int RESOP, bool BIAS, int OUTMODE, bool RESHALF>
__global__ void __launch_bounds__(256)
gemm_mma(const __half* __restrict__ A, const __half* __restrict__ Bw,
         int ldA, int ldB, int iters,
         const float* __restrict__ bias, const void* __restrict__ res,
         float* __restrict__ Cf, __half* __restrict__ Cp,
         int N, int ldOut) {
    extern __shared__ char smem[];
    uint32_t sb = smem_u32(smem);
    int tid = threadIdx.x;
    int wid = tid >> 5, lid = tid & 31;
    int wm = wid >> 2, wn = wid & 3;
    int lr = lid & 15, lc = lid >> 4;

    int bm = blockIdx.y, bn = blockIdx.x;
    const __half* Ab = A  + (size_t)(bm * 128) * ldA;
    const __half* Bb = Bw + (size_t)(bn * 128) * ldB;

    float acc[4][4][4];
    #pragma unroll
    for (int i = 0; i < 4; i++)
        #pragma unroll
        for (int j = 0; j < 4; j++)
            #pragma unroll
            for (int q = 0; q < 4; q++) acc[i][j][q] = 0.f;

    produce_stage(sb, Ab, Bb, ldA, ldB, 0, tid);
    produce_stage(sb, Ab, Bb, ldA, ldB, 1, tid);
    produce_stage(sb, Ab, Bb, ldA, ldB, 2, tid);

    for (int it = 0; it < iters; ++it) {
        CP_WAIT2();
        __syncthreads();
        uint32_t sa  = sb + (uint32_t)(it & 3) * STAGE;
        uint32_t sbt = sa + (uint32_t)ABYTES;

        #pragma unroll
        for (int kk = 0; kk < 2; kk++) {
            int chunk = kk * 2 + lc;
            uint32_t a[4][4];
            #pragma unroll
            for (int mf = 0; mf < 4; mf++) {
                int row = wm * 64 + mf * 16 + lr;
                int qq = chunk ^ ((row >> 1) & 3);
                LDSM4(a[mf], sa + (uint32_t)(row * 64 + qq * 16));
            }
            uint32_t bb[2][4];
            #pragma unroll
            for (int nf2 = 0; nf2 < 2; nf2++) {
                int row = wn * 32 + nf2 * 16 + lr;
                int qq = chunk ^ ((row >> 1) & 3);
                LDSM4(bb[nf2], sbt + (uint32_t)(row * 64 + qq * 16));
            }
            #pragma unroll
            for (int mf = 0; mf < 4; mf++)
                #pragma unroll
                for (int nf = 0; nf < 4; nf++) {
                    int n2 = nf >> 1, sel = nf & 1;
                    MMA_F16(acc[mf][nf], a[mf], bb[n2][sel], bb[n2][2 + sel]);
                }
        }
        __syncthreads();
        int j = it + 3;
        if (j < iters) produce_stage(sb, Ab, Bb, ldA, ldB, j, tid);
        else           CP_COMMIT();
    }

    int er = lid >> 2;
    int ec = (lid & 3) * 2;
    #pragma unroll
    for (int mf = 0; mf < 4; mf++) {
        #pragma unroll
        for (int nf = 0; nf < 4; nf++) {
            float* cc = acc[mf][nf];
            int row0 = bm * 128 + wm * 64 + mf * 16 + er;
            int col  = bn * 128 + wn * 32 + nf * 8 + ec;
            #pragma unroll
            for (int half = 0; half < 2; half++) {
                int row = row0 + half * 8;
                float v0 = cc[half * 2 + 0];
                float v1 = cc[half * 2 + 1];
                if (BIAS) { v0 += bias[col]; v1 += bias[col + 1]; }
                if (ACT == 1) { v0 = act_sigmoid(v0); v1 = act_sigmoid(v1); }
                if (ACT == 2) { v0 = act_gelu(v0);    v1 = act_gelu(v1); }
                if (RESOP != 0) {
                    float r0, r1;
                    if (RESHALF) {
                        __half2 rv = *reinterpret_cast<const __half2*>(
                            (const __half*)res + (size_t)row * N + col);
                        r0 = __half2float(__low2half(rv));
                        r1 = __half2float(__high2half(rv));
                    } else {
                        float2 rv = *reinterpret_cast<const float2*>(
                            (const float*)res + (size_t)row * N + col);
                        r0 = rv.x; r1 = rv.y;
                    }
                    if (RESOP == 1) { v0 += r0; v1 += r1; }
                    else            { v0 *= r0; v1 *= r1; }
                }
                if (OUTMODE == 2) {
                    *reinterpret_cast<__half2*>(Cp + (size_t)row * ldOut + col) =
                        __halves2half2(__float2half_rn(v0), __float2half_rn(v1));
                } else {
                    *reinterpret_cast<float2*>(Cf + (size_t)row * N + col) = make_float2(v0, v1);
                }
            }
        }
    }
}

// ---------------------------------------------------------------------------
// Dual GEMM: BM=64, BN=128, BK=32, 8 warps (warp tile 32x32), shared A,
// two B operands, two accumulators.  4-stage pipeline, stage = A(4KB)+
// B1(8KB)+B2(8KB) = 20KB.
// EPI 0: a/u epilogue (r=sig(acc1+b1as), i=sig(acc2+b2as), conv=aux1,
//        log_lambda=aux2) -> Cau float2.
// EPI 1: gelu(acc1)*acc2 -> Cp fp16 (ld N).
// ---------------------------------------------------------------------------
constexpr int D_ABYTES = 4096;
constexpr int D_BBYTES = 8192;
constexpr int D_STAGE  = D_ABYTES + 2 * D_BBYTES;   // 20480
constexpr int D_SMEM   = 4 * D_STAGE;               // 81920

__device__ __forceinline__ void produce_stage_dual(uint32_t sb,
        const __half* Ab, const __half* B1b, const __half* B2b,
        int ldA, int ldB, int j, int tid) {
    int k0 = j * 32;
    uint32_t stage = sb + (uint32_t)(j & 3) * D_STAGE;
    #pragma unroll
    for (int ch = 0; ch < 5; ch++) {
        int c = tid + (ch << 8);                   // 0..1279
        if (c < 256) {                             // A: 64 rows
            int r = c >> 2, q = c & 3;
            int qq = q ^ ((r >> 1) & 3);
            CP_ASYNC16(stage + (uint32_t)(r * 64 + qq * 16),
                       Ab + (size_t)r * ldA + k0 + q * 8);
        } else if (c < 768) {                      // B1: 128 rows
            int cc = c - 256;
            int r = cc >> 2, q = cc & 3;
            int qq = q ^ ((r >> 1) & 3);
            CP_ASYNC16(stage + (uint32_t)D_ABYTES + (uint32_t)(r * 64 + qq * 16),
                       B1b + (size_t)r * ldB + k0 + q * 8);
        } else {                                   // B2: 128 rows
            int cc = c - 768;
            int r = cc >> 2, q = cc & 3;
            int qq = q ^ ((r >> 1) & 3);
            CP_ASYNC16(stage + (uint32_t)(D_ABYTES + D_BBYTES)
                             + (uint32_t)(r * 64 + qq * 16),
                       B2b + (size_t)r * ldB + k0 + q * 8);
        }
    }
    CP_COMMIT();
}

template <int EPI>
__global__ void __launch_bounds__(256)
dual_gemm(const __half* __restrict__ A,
          const __half* __restrict__ B1, const __half* __restrict__ B2,
          int ldA, int ldB, int iters,
          const float* __restrict__ bias1, const float* __restrict__ bias2,
          const float* __restrict__ aux1, const float* __restrict__ aux2,
          float2* __restrict__ Cau, __half* __restrict__ Cp, int N) {
    extern __shared__ char smem[];
    uint32_t sb = smem_u32(smem);
    int tid = threadIdx.x;
    int wid = tid >> 5, lid = tid & 31;
    int wm = wid >> 2, wn = wid & 3;               // 2x4 over 64x128
    int lr = lid & 15, lc = lid >> 4;

    int bm = blockIdx.y, bn = blockIdx.x;
    const __half* Ab  = A  + (size_t)(bm * 64) * ldA;
    const __half* B1b = B1 + (size_t)(bn * 128) * ldB;
    const __half* B2b = B2 + (size_t)(bn * 128) * ldB;

    float acc1[2][4][4], acc2[2][4][4];
    #pragma unroll
    for (int i = 0; i < 2; i++)
        #pragma unroll
        for (int j = 0; j < 4; j++)
            #pragma unroll
            for (int q = 0; q < 4; q++) { acc1[i][j][q] = 0.f; acc2[i][j][q] = 0.f; }

    produce_stage_dual(sb, Ab, B1b, B2b, ldA, ldB, 0, tid);
    produce_stage_dual(sb, Ab, B1b, B2b, ldA, ldB, 1, tid);
    produce_stage_dual(sb, Ab, B1b, B2b, ldA, ldB, 2, tid);

    for (int it = 0; it < iters; ++it) {
        CP_WAIT2();
        __syncthreads();
        uint32_t sa  = sb + (uint32_t)(it & 3) * D_STAGE;
        uint32_t sb1 = sa + (uint32_t)D_ABYTES;
        uint32_t sb2 = sb1 + (uint32_t)D_BBYTES;

        #pragma unroll
        for (int kk = 0; kk < 2; kk++) {
            int chunk = kk * 2 + lc;
            uint32_t a[2][4];
            #pragma unroll
            for (int mf = 0; mf < 2; mf++) {
                int row = wm * 32 + mf * 16 + lr;
                int qq = chunk ^ ((row >> 1) & 3);
                LDSM4(a[mf], sa + (uint32_t)(row * 64 + qq * 16));
            }
            uint32_t b1f[2][4], b2f[2][4];
            #pragma unroll
            for (int nf2 = 0; nf2 < 2; nf2++) {
                int row = wn * 32 + nf2 * 16 + lr;
                int qq = chunk ^ ((row >> 1) & 3);
                LDSM4(b1f[nf2], sb1 + (uint32_t)(row * 64 + qq * 16));
                LDSM4(b2f[nf2], sb2 + (uint32_t)(row * 64 + qq * 16));
            }
            #pragma unroll
            for (int mf = 0; mf < 2; mf++)
                #pragma unroll
                for (int nf = 0; nf < 4; nf++) {
                    int n2 = nf >> 1, sel = nf & 1;
                    MMA_F16(acc1[mf][nf], a[mf], b1f[n2][sel], b1f[n2][2 + sel]);
                    MMA_F16(acc2[mf][nf], a[mf], b2f[n2][sel], b2f[n2][2 + sel]);
                }
        }
        __syncthreads();
        int j = it + 3;
        if (j < iters) produce_stage_dual(sb, Ab, B1b, B2b, ldA, ldB, j, tid);
        else           CP_COMMIT();
    }

    int er = lid >> 2;
    int ec = (lid & 3) * 2;
    #pragma unroll
    for (int mf = 0; mf < 2; mf++) {
        #pragma unroll
        for (int nf = 0; nf < 4; nf++) {
            float* c1 = acc1[mf][nf];
            float* c2 = acc2[mf][nf];
            int row0 = bm * 64 + wm * 32 + mf * 16 + er;
            int col  = bn * 128 + wn * 32 + nf * 8 + ec;
            #pragma unroll
            for (int half = 0; half < 2; half++) {
                int row = row0 + half * 8;
                float v0 = c1[half * 2 + 0], v1 = c1[half * 2 + 1];
                float w0 = c2[half * 2 + 0], w1 = c2[half * 2 + 1];
                if (EPI == 0) {
                    float r0 = act_sigmoid(v0 + bias1[col]);
                    float r1 = act_sigmoid(v1 + bias1[col + 1]);
                    float i0 = act_sigmoid(w0 + bias2[col]);
                    float i1 = act_sigmoid(w1 + bias2[col + 1]);
                    size_t idx = (size_t)row * N + col;
                    float cv0 = aux1[idx], cv1 = aux1[idx + 1];
                    float ll0 = aux2[col], ll1 = aux2[col + 1];
                    float ls0 = -log1pf(expf(-ll0));
                    float ls1 = -log1pf(expf(-ll1));
                    float a0 = expf(C_EXP * r0 * ls0);
                    float a1 = expf(C_EXP * r1 * ls1);
                    float gt0 = sqrtf(fmaxf((1.0f - a0) * (1.0f + a0), 1e-6f));
                    float gt1 = sqrtf(fmaxf((1.0f - a1) * (1.0f + a1), 1e-6f));
                    Cau[idx]     = make_float2(a0, gt0 * (i0 * cv0));
                    Cau[idx + 1] = make_float2(a1, gt1 * (i1 * cv1));
                } else {
                    float p0 = act_gelu(v0) * w0;
                    float p1 = act_gelu(v1) * w1;
                    *reinterpret_cast<__half2*>(Cp + (size_t)row * N + col) =
                        __halves2half2(__float2half_rn(p0), __float2half_rn(p1));
                }
            }
        }
    }
}

// ---------------------------------------------------------------------------
// RMSNorm -> fp16
// ---------------------------------------------------------------------------
__global__ void rmsnorm_hi_kernel(const float* __restrict__ x,
                                  const float* __restrict__ w,
                                  __half* __restrict__ outh) {
    int row = blockIdx.x;
    int tid = threadIdx.x;
    const float4* xr = reinterpret_cast<const float4*>(x + (size_t)row * D);
    float4 v = xr[tid];
    float s = v.x * v.x + v.y * v.y + v.z * v.z + v.w * v.w;
    #pragma unroll
    for (int o = 16; o > 0; o >>= 1) s += __shfl_xor_sync(0xffffffffu, s, o);
    __shared__ float sm[8];
    if ((tid & 31) == 0) sm[tid >> 5] = s;
    __syncthreads();
    float tot = 0.f;
    #pragma unroll
    for (int i = 0; i < 8; i++) tot += sm[i];
    float scale = rsqrtf(tot * (1.0f / D) + EPS);
    float4 wv = reinterpret_cast<const float4*>(w)[tid];
    __half2* hp = reinterpret_cast<__half2*>(outh + (size_t)row * D + tid * 4);
    hp[0] = __halves2half2(__float2half_rn(v.x * scale * wv.x),
                           __float2half_rn(v.y * scale * wv.y));
    hp[1] = __halves2half2(__float2half_rn(v.z * scale * wv.z),
                           __float2half_rn(v.w * scale * wv.w));
}

// ---------------------------------------------------------------------------
// Fused weight conversion (8 weights, 1 launch)
// ---------------------------------------------------------------------------
constexpr size_t WCH_S = (size_t)D * D / 4;
constexpr size_t WCH_L = (size_t)H * D / 4;
constexpr size_t WCH_TOTAL = 5 * WCH_S + 3 * WCH_L;

__global__ void whi_all_kernel(const float* __restrict__ W1,
                               const float* __restrict__ Wa,
                               const float* __restrict__ Wx,
                               const float* __restrict__ W2,
                               const float* __restrict__ Wout,
                               const float* __restrict__ Wg,
                               const float* __restrict__ Wu,
                               const float* __restrict__ Wo) {
    size_t c = (size_t)blockIdx.x * blockDim.x + threadIdx.x;
    if (c >= WCH_TOTAL) return;
    const float* src;
    __half* dst;
    size_t off;
    if (c < 5 * WCH_S) {
        int seg = (int)(c / WCH_S);
        off = c % WCH_S;
        src = (seg == 0) ? W1 : (seg == 1) ? Wa : (seg == 2) ? Wx
            : (seg == 3) ? W2 : Wout;
        dst = (seg == 0) ? g_w1h : (seg == 1) ? g_wah : (seg == 2) ? g_wxh
            : (seg == 3) ? g_w2h : g_wouth;
    } else {
        size_t c2 = c - 5 * WCH_S;
        int seg = (int)(c2 / WCH_L);
        off = c2 % WCH_L;
        src = (seg == 0) ? Wg : (seg == 1) ? Wu : Wo;
        dst = (seg == 0) ? g_wgh : (seg == 1) ? g_wuh : g_woh;
    }
    float4 v = reinterpret_cast<const float4*>(src)[off];
    __half2* o = reinterpret_cast<__half2*>(dst + off * 4);
    o[0] = __halves2half2(__float2half_rn(v.x), __float2half_rn(v.y));
    o[1] = __halves2half2(__float2half_rn(v.z), __float2half_rn(v.w));
}

// ---------------------------------------------------------------------------
// Conv (rolling window, fused conv_buf output).  grid (T/16, B), 256 thr.
// Each thread: one float4 of d, walks 16 t-steps.
// ---------------------------------------------------------------------------
__device__ __forceinline__ float4 f4fma(float4 a, float4 b, float4 c) {
    return make_float4(fmaf(a.x, b.x, c.x), fmaf(a.y, b.y, c.y),
                       fmaf(a.z, b.z, c.z), fmaf(a.w, b.w, c.w));
}

__global__ void conv_kernel(const float* __restrict__ conv_buf,
                            const float* __restrict__ conv_w,
                            const float* __restrict__ conv_b,
                            float* __restrict__ out_cb) {
    int b   = blockIdx.y;
    int tc0 = blockIdx.x * 16;
    int d   = threadIdx.x * 4;

    // conv_w rows d..d+3 (each float4) -> transpose to per-k float4s
    float4 cwr0 = reinterpret_cast<const float4*>(conv_w)[d + 0];
    float4 cwr1 = reinterpret_cast<const float4*>(conv_w)[d + 1];
    float4 cwr2 = reinterpret_cast<const float4*>(conv_w)[d + 2];
    float4 cwr3 = reinterpret_cast<const float4*>(conv_w)[d + 3];
    float4 w0 = make_float4(cwr0.x, cwr1.x, cwr2.x, cwr3.x);
    float4 w1 = make_float4(cwr0.y, cwr1.y, cwr2.y, cwr3.y);
    float4 w2 = make_float4(cwr0.z, cwr1.z, cwr2.z, cwr3.z);
    float4 w3 = make_float4(cwr0.w, cwr1.w, cwr2.w, cwr3.w);
    float4 cb = *reinterpret_cast<const float4*>(conv_b + d);

    const float* b1base = g_b1 + (size_t)b * T * D;
    float4 p3, p2, p1;
    if (tc0 == 0) {
        p3 = *reinterpret_cast<const float4*>(conv_buf + ((size_t)b * 3 + 0) * D + d);
        p2 = *reinterpret_cast<const float4*>(conv_buf + ((size_t)b * 3 + 1) * D + d);
        p1 = *reinterpret_cast<const float4*>(conv_buf + ((size_t)b * 3 + 2) * D + d);
    } else {
        p3 = *reinterpret_cast<const float4*>(b1base + (size_t)(tc0 - 3) * D + d);
        p2 = *reinterpret_cast<const float4*>(b1base + (size_t)(tc0 - 2) * D + d);
        p1 = *reinterpret_cast<const float4*>(b1base + (size_t)(tc0 - 1) * D + d);
    }

    #pragma unroll
    for (int tt = 0; tt < 16; tt++) {
        int t = tc0 + tt;
        float4 cur = *reinterpret_cast<const float4*>(b1base + (size_t)t * D + d);
        float4 o = cb;
        o = f4fma(w0, p3, o);
        o = f4fma(w1, p2, o);
        o = f4fma(w2, p1, o);
        o = f4fma(w3, cur, o);
        size_t gidx = ((size_t)b * T + t) * D + d;
        *reinterpret_cast<float4*>(g_conv + gidx) = o;
        __half2* hp = reinterpret_cast<__half2*>(g_conv_h + gidx);
        hp[0] = __halves2half2(__float2half_rn(o.x), __float2half_rn(o.y));
        hp[1] = __halves2half2(__float2half_rn(o.z), __float2half_rn(o.w));
        if (t >= T - 3) {
            *reinterpret_cast<float4*>(out_cb + ((size_t)b * 3 + (t - (T - 3))) * D + d) = cur;
        }
        p3 = p2; p2 = p1; p1 = cur;
    }
}

// ---------------------------------------------------------------------------
// Parallel scan (8 segments, 3 passes)
// ---------------------------------------------------------------------------
__global__ void scan_seg_kernel() {
    int g = blockIdx.x * blockDim.x + threadIdx.x;   // B*SC*D
    int d = g % D;
    int c = (g / D) % SC;
    int b = g / (SC * D);
    const float2* au = g_au + ((size_t)b * T + (size_t)c * SL) * D + d;
    float A = 1.0f, U = 0.0f;
    #pragma unroll 8
    for (int t = 0; t < SL; t++) {
        float2 v = au[(size_t)t * D];
        A *= v.x;
        U = fmaf(v.x, U, v.y);
    }
    g_seg[g] = make_float2(A, U);
}

__global__ void scan_combine_kernel(const float* __restrict__ h0,
                                    float* __restrict__ out_h) {
    int g = blockIdx.x * blockDim.x + threadIdx.x;   // B*D
    int d = g % D;
    int b = g / D;
    float h = h0[g];
    #pragma unroll
    for (int c = 0; c < SC; c++) {
        size_t si = ((size_t)b * SC + c) * D + d;
        g_hstart[si] = h;
        float2 s = g_seg[si];
        h = fmaf(s.x, h, s.y);
    }
    out_h[g] = h;
}

__global__ void scan_emit_kernel() {
    int g = blockIdx.x * blockDim.x + threadIdx.x;   // B*SC*D
    int d = g % D;
    int c = (g / D) % SC;
    int b = g / (SC * D);
    const float2* au = g_au + ((size_t)b * T + (size_t)c * SL) * D + d;
    float* o = g_b1out + ((size_t)b * T + (size_t)c * SL) * D + d;
    float h = g_hstart[g];
    #pragma unroll 8
    for (int t = 0; t < SL; t++) {
        float2 v = au[(size_t)t * D];
        h = fmaf(v.x, h, v.y);
        o[(size_t)t * D] = h;
    }
}

// ---------------------------------------------------------------------------
// Launch
// ---------------------------------------------------------------------------
extern "C" void kernel_launch(void* const* d_in, const int* in_sizes, int n_in,
                              void* d_out, int out_size) {
    const float* x_seq      = (const float*)d_in[0];
    const float* h0         = (const float*)d_in[1];
    const float* conv_buf   = (const float*)d_in[2];
    const float* norm1_w    = (const float*)d_in[3];
    const float* W1         = (const float*)d_in[4];
    const float* conv_w     = (const float*)d_in[5];
    const float* conv_b     = (const float*)d_in[6];
    const float* Wa         = (const float*)d_in[7];
    const float* ba         = (const float*)d_in[8];
    const float* Wx         = (const float*)d_in[9];
    const float* bx         = (const float*)d_in[10];
    const float* log_lambda = (const float*)d_in[11];
    const float* W2         = (const float*)d_in[12];
    const float* Wout       = (const float*)d_in[13];
    const float* norm2_w    = (const float*)d_in[14];
    const float* Wg         = (const float*)d_in[15];
    const float* Wu         = (const float*)d_in[16];
    const float* Wo         = (const float*)d_in[17];

    float* out_x2 = (float*)d_out;
    float* out_h  = out_x2 + (size_t)M * D;
    float* out_cb = out_h + (size_t)B * D;

    __half *p_normed, *p_convh, *p_prodh, *p_n2h, *p_acth;
    __half *p_w1, *p_wa, *p_wx, *p_w2, *p_wout, *p_wg, *p_wu, *p_wo;
    float *p_b1, *p_conv, *p_b1out, *p_x1;
    float2 *p_au;
    cudaGetSymbolAddress((void**)&p_normed, g_normed_h);
    cudaGetSymbolAddress((void**)&p_convh,  g_conv_h);
    cudaGetSymbolAddress((void**)&p_prodh,  g_prod_h);
    cudaGetSymbolAddress((void**)&p_n2h,    g_n2_h);
    cudaGetSymbolAddress((void**)&p_acth,   g_act_h);
    cudaGetSymbolAddress((void**)&p_w1,     g_w1h);
    cudaGetSymbolAddress((void**)&p_wa,     g_wah);
    cudaGetSymbolAddress((void**)&p_wx,     g_wxh);
    cudaGetSymbolAddress((void**)&p_w2,     g_w2h);
    cudaGetSymbolAddress((void**)&p_wout,   g_wouth);
    cudaGetSymbolAddress((void**)&p_wg,     g_wgh);
    cudaGetSymbolAddress((void**)&p_wu,     g_wuh);
    cudaGetSymbolAddress((void**)&p_wo,     g_woh);
    cudaGetSymbolAddress((void**)&p_b1,     g_b1);
    cudaGetSymbolAddress((void**)&p_conv,   g_conv);
    cudaGetSymbolAddress((void**)&p_au,     g_au);
    cudaGetSymbolAddress((void**)&p_b1out,  g_b1out);
    cudaGetSymbolAddress((void**)&p_x1,     g_x1);

    auto kPlain  = gemm_mma<0, 0, false, 0, false>;  // b1 -> fp32
    auto kGeluMH = gemm_mma<2, 2, false, 2, false>;  // gelu(b2)*b1out -> prod_h
    auto kAdd    = gemm_mma<0, 1, false, 0, false>;  // x1, x2
    auto kDualAU = dual_gemm<0>;
    auto kDualGU = dual_gemm<1>;
    cudaFuncSetAttribute(kPlain,  cudaFuncAttributeMaxDynamicSharedMemorySize, SMEM_B);
    cudaFuncSetAttribute(kGeluMH, cudaFuncAttributeMaxDynamicSharedMemorySize, SMEM_B);
    cudaFuncSetAttribute(kAdd,    cudaFuncAttributeMaxDynamicSharedMemorySize, SMEM_B);
    cudaFuncSetAttribute(kDualAU, cudaFuncAttributeMaxDynamicSharedMemorySize, D_SMEM);
    cudaFuncSetAttribute(kDualGU, cudaFuncAttributeMaxDynamicSharedMemorySize, D_SMEM);

    dim3 gD(D / 128, M / 128);       // (8, 128)
    dim3 gDd(D / 128, M / 64);       // (8, 256)  dual D
    dim3 gHd(H / 128, M / 64);       // (32, 256) dual H

    // 1. normed = rmsnorm(x_seq) -> fp16
    rmsnorm_hi_kernel<<<M, 256>>>(x_seq, norm1_w, p_normed);
    // 2. weight conversions
    whi_all_kernel<<<(int)((WCH_TOTAL + 255) / 256), 256>>>(W1, Wa, Wx, W2, Wout, Wg, Wu, Wo);
    // 3. b1 = normed @ W1^T -> fp32
    kPlain<<<gD, 256, SMEM_B>>>(p_normed, p_w1, D, D, 32,
                                nullptr, nullptr, p_b1, nullptr, D, 0);
    // 4. conv (rolling window, fused out_cb)
    conv_kernel<<<dim3(T / 16, B), 256>>>(conv_buf, conv_w, conv_b, out_cb);
    // 5. dual r/i GEMM + a/u epilogue -> g_au
    kDualAU<<<gDd, 256, D_SMEM>>>(p_convh, p_wa, p_wx, D, D, 32,
                                  ba, bx, p_conv, log_lambda, p_au, nullptr, D);
    // 6-8. parallel scan
    scan_seg_kernel<<<(B * SC * D) / 256, 256>>>();
    scan_combine_kernel<<<(B * D) / 256, 256>>>(h0, out_h);
    scan_emit_kernel<<<(B * SC * D) / 256, 256>>>();
    // 9. prod = gelu(normed @ W2^T) * b1out -> fp16
    kGeluMH<<<gD, 256, SMEM_B>>>(p_normed, p_w2, D, D, 32,
                                 nullptr, p_b1out, nullptr, p_prodh, D, D);
    // 10. x1 = x_seq + prod @ Wout^T -> fp32
    kAdd<<<gD, 256, SMEM_B>>>(p_prodh, p_wout, D, D, 32,
                              nullptr, x_seq, p_x1, nullptr, D, 0);
    // 11. n2 = rmsnorm(x1) -> fp16
    rmsnorm_hi_kernel<<<M, 256>>>(p_x1, norm2_w, p_n2h);
    // 12. dual Wg/Wu GEMM + gelu-mul epilogue -> act_h
    kDualGU<<<gHd, 256, D_SMEM>>>(p_n2h, p_wg, p_wu, D, D, 32,
                                  nullptr, nullptr, nullptr, nullptr,
                                  nullptr, p_acth, H);
    // 13. x2 = x1 + act @ Wo^T -> out
    kAdd<<<gD, 256, SMEM_B>>>(p_acth, p_wo, H, H, 128,
                              nullptr, p_x1, out_x2, nullptr, D, 0);
}

// round 13
// speedup vs baseline: 7.0039x; 1.0248x over previous
#include <cuda_runtime.h>
#include <cuda_fp16.h>
#include <math.h>
#include <stdint.h>

// ---------------------------------------------------------------------------
// GriffinTemporalBlock on GB300 (classic mma.sync fp16 path).
// All GEMMs 1-term fp16.  Dual-GEMMs for (r,i)->a/u and (Wg,Wu)->act.
// conv stored fp16-only; b2*h product fused in-place into scan_emit.
// B=16, T=1024, D=1024, H=4096.
// ---------------------------------------------------------------------------

constexpr int B = 16;
constexpr int T = 1024;
constexpr int D = 1024;
constexpr int H = 4096;
constexpr int M = B * T;               // 16384
constexpr float EPS = 1.1920929e-07f;
constexpr float C_EXP = 8.0f;

constexpr int SC = 8;                  // scan segments
constexpr int SL = T / SC;             // 128

// ----- scratch (static device globals) -------------------------------------
__device__ __half g_normed_h[(size_t)M * D];
__device__ __half g_conv_h  [(size_t)M * D];
__device__ __half g_prod_h  [(size_t)M * D];   // gelu(b2), then in-place *h
__device__ __half g_n2_h    [(size_t)M * D];
__device__ __half g_act_h   [(size_t)M * H];

__device__ __half g_w1h  [(size_t)D * D];
__device__ __half g_wah  [(size_t)D * D];
__device__ __half g_wxh  [(size_t)D * D];
__device__ __half g_w2h  [(size_t)D * D];
__device__ __half g_wouth[(size_t)D * D];
__device__ __half g_wgh  [(size_t)H * D];
__device__ __half g_wuh  [(size_t)H * D];
__device__ __half g_woh  [(size_t)D * H];

__device__ float  g_b1   [(size_t)M * D];
__device__ __align__(16) float2 g_au [(size_t)M * D];
__device__ float  g_x1   [(size_t)M * D];
__device__ __align__(16) float2 g_seg[(size_t)B * SC * D];
__device__ float  g_hstart[(size_t)B * SC * D];

// ---------------------------------------------------------------------------
// helpers
// ---------------------------------------------------------------------------
__device__ __forceinline__ uint32_t smem_u32(const void* p) {
    uint32_t a;
    asm("{ .reg .u64 t; cvta.to.shared.u64 t, %1; cvt.u32.u64 %0, t; }"
        : "=r"(a) : "l"(p));
    return a;
}

#define CP_ASYNC16(dst, src) \
    asm volatile("cp.async.cg.shared.global [%0], [%1], 16;" :: "r"(dst), "l"(src) : "memory")
#define CP_COMMIT() asm volatile("cp.async.commit_group;" ::: "memory")
#define CP_WAIT2()  asm volatile("cp.async.wait_group 2;" ::: "memory")

#define LDSM4(R, addr) \
    asm volatile("ldmatrix.sync.aligned.m8n8.x4.shared.b16 {%0,%1,%2,%3}, [%4];" \
        : "=r"((R)[0]), "=r"((R)[1]), "=r"((R)[2]), "=r"((R)[3]) : "r"(addr))

#define MMA_F16(d, a, b0v, b1v) \
    asm volatile("mma.sync.aligned.m16n8k16.row.col.f32.f16.f16.f32 " \
        "{%0,%1,%2,%3}, {%4,%5,%6,%7}, {%8,%9}, {%0,%1,%2,%3};" \
        : "+f"((d)[0]), "+f"((d)[1]), "+f"((d)[2]), "+f"((d)[3]) \
        : "r"((a)[0]), "r"((a)[1]), "r"((a)[2]), "r"((a)[3]), "r"(b0v), "r"(b1v))

__device__ __forceinline__ float act_sigmoid(float x) { return 1.0f / (1.0f + expf(-x)); }
__device__ __forceinline__ float act_gelu(float x)    { return 0.5f * x * (1.0f + erff(x * 0.70710678118654752f)); }

// ---------------------------------------------------------------------------
// Single GEMM: 128x128 block, BK=32, 8 warps, SW64 tiles, 4-stage pipeline.
// ---------------------------------------------------------------------------
constexpr int ABYTES = 8192;
constexpr int STAGE  = 16384;
constexpr int SMEM_B = 4 * STAGE;              // 65536

__device__ __forceinline__ void produce_stage(uint32_t sb,
        const __half* Ab, const __half* Bb,
        int ldA, int ldB, int j, int tid) {
    int k0 = j * 32;
    uint32_t stage = sb + (uint32_t)(j & 3) * STAGE;
    #pragma unroll
    for (int ch = 0; ch < 4; ch++) {
        int c = tid + (ch << 8);                   // 0..1023
        int r = c >> 2, q = c & 3;
        if (c < 512) {
            int qq = q ^ ((r >> 1) & 3);           // SW64
            CP_ASYNC16(stage + (uint32_t)(r * 64 + qq * 16),
                       Ab + (size_t)r * ldA + k0 + q * 8);
        } else {
            int rr = r - 128;
            int qq2 = q ^ ((rr >> 1) & 3);
            CP_ASYNC16(stage + (uint32_t)ABYTES + (uint32_t)(rr * 64 + qq2 * 16),
                       Bb + (size_t)rr * ldB + k0 + q * 8);
        }
    }
    CP_COMMIT();
}

template <int ACT, int RESOP, bool BIAS, int OUTMODE, bool RESHALF>
__global__ void __launch_bounds__(256)
gemm_mma(const __half* __restrict__ A, const __half* __restrict__ Bw,
         int ldA, int ldB, int iters,
         const float* __restrict__ bias, const void* __restrict__ res,
         float* __restrict__ Cf, __half* __restrict__ Cp,
         int N, int ldOut) {
    extern __shared__ char smem[];
    uint32_t sb = smem_u32(smem);
    int tid = threadIdx.x;
    int wid = tid >> 5, lid = tid & 31;
    int wm = wid >> 2, wn = wid & 3;
    int lr = lid & 15, lc = lid >> 4;

    int bm = blockIdx.y, bn = blockIdx.x;
    const __half* Ab = A  + (size_t)(bm * 128) * ldA;
    const __half* Bb = Bw + (size_t)(bn * 128) * ldB;

    float acc[4][4][4];
    #pragma unroll
    for (int i = 0; i < 4; i++)
        #pragma unroll
        for (int j = 0; j < 4; j++)
            #pragma unroll
            for (int q = 0; q < 4; q++) acc[i][j][q] = 0.f;

    produce_stage(sb, Ab, Bb, ldA, ldB, 0, tid);
    produce_stage(sb, Ab, Bb, ldA, ldB, 1, tid);
    produce_stage(sb, Ab, Bb, ldA, ldB, 2, tid);

    for (int it = 0; it < iters; ++it) {
        CP_WAIT2();
        __syncthreads();
        uint32_t sa  = sb + (uint32_t)(it & 3) * STAGE;
        uint32_t sbt = sa + (uint32_t)ABYTES;

        #pragma unroll
        for (int kk = 0; kk < 2; kk++) {
            int chunk = kk * 2 + lc;
            uint32_t a[4][4];
            #pragma unroll
            for (int mf = 0; mf < 4; mf++) {
                int row = wm * 64 + mf * 16 + lr;
                int qq = chunk ^ ((row >> 1) & 3);
                LDSM4(a[mf], sa + (uint32_t)(row * 64 + qq * 16));
            }
            uint32_t bb[2][4];
            #pragma unroll
            for (int nf2 = 0; nf2 < 2; nf2++) {
                int row = wn * 32 + nf2 * 16 + lr;
                int qq = chunk ^ ((row >> 1) & 3);
                LDSM4(bb[nf2], sbt + (uint32_t)(row * 64 + qq * 16));
            }
            #pragma unroll
            for (int mf = 0; mf < 4; mf++)
                #pragma unroll
                for (int nf = 0; nf < 4; nf++) {
                    int n2 = nf >> 1, sel = nf & 1;
                    MMA_F16(acc[mf][nf], a[mf], bb[n2][sel], bb[n2][2 + sel]);
                }
        }
        __syncthreads();
        int j = it + 3;
        if (j < iters) produce_stage(sb, Ab, Bb, ldA, ldB, j, tid);
        else           CP_COMMIT();
    }

    int er = lid >> 2;
    int ec = (lid & 3) * 2;
    #pragma unroll
    for (int mf = 0; mf < 4; mf++) {
        #pragma unroll
        for (int nf = 0; nf < 4; nf++) {
            float* cc = acc[mf][nf];
            int row0 = bm * 128 + wm * 64 + mf * 16 + er;
            int col  = bn * 128 + wn * 32 + nf * 8 + ec;
            #pragma unroll
            for (int half = 0; half < 2; half++) {
                int row = row0 + half * 8;
                float v0 = cc[half * 2 + 0];
                float v1 = cc[half * 2 + 1];
                if (BIAS) { v0 += bias[col]; v1 += bias[col + 1]; }
                if (ACT == 1) { v0 = act_sigmoid(v0); v1 = act_sigmoid(v1); }
                if (ACT == 2) { v0 = act_gelu(v0);    v1 = act_gelu(v1); }
                if (RESOP != 0) {
                    float r0, r1;
                    if (RESHALF) {
                        __half2 rv = *reinterpret_cast<const __half2*>(
                            (const __half*)res + (size_t)row * N + col);
                        r0 = __half2float(__low2half(rv));
                        r1 = __half2float(__high2half(rv));
                    } else {
                        float2 rv = *reinterpret_cast<const float2*>(
                            (const float*)res + (size_t)row * N + col);
                        r0 = rv.x; r1 = rv.y;
                    }
                    if (RESOP == 1) { v0 += r0; v1 += r1; }
                    else            { v0 *= r0; v1 *= r1; }
                }
                if (OUTMODE == 2) {
                    *reinterpret_cast<__half2*>(Cp + (size_t)row * ldOut + col) =
                        __halves2half2(__float2half_rn(v0), __float2half_rn(v1));
                } else {
                    *reinterpret_cast<float2*>(Cf + (size_t)row * N + col) = make_float2(v0, v1);
                }
            }
        }
    }
}

// ---------------------------------------------------------------------------
// Dual GEMM: BM=64, BN=128, BK=32, 8 warps, shared A, two B, two accums.
// EPI 0: a/u epilogue (conv read as fp16 aux1) -> Cau float2.
// EPI 1: gelu(acc1)*acc2 -> Cp fp16.
// ---------------------------------------------------------------------------
constexpr int D_ABYTES = 4096;
constexpr int D_BBYTES = 8192;
constexpr int D_STAGE  = D_ABYTES + 2 * D_BBYTES;   // 20480
constexpr int D_SMEM   = 4 * D_STAGE;               // 81920

__device__ __forceinline__ void produce_stage_dual(uint32_t sb,
        const __half* Ab, const __half* B1b, const __half* B2b,
        int ldA, int ldB, int j, int tid) {
    int k0 = j * 32;
    uint32_t stage = sb + (uint32_t)(j & 3) * D_STAGE;
    #pragma unroll
    for (int ch = 0; ch < 5; ch++) {
        int c = tid + (ch << 8);                   // 0..1279
        if (c < 256) {
            int r = c >> 2, q = c & 3;
            int qq = q ^ ((r >> 1) & 3);
            CP_ASYNC16(stage + (uint32_t)(r * 64 + qq * 16),
                       Ab + (size_t)r * ldA + k0 + q * 8);
        } else if (c < 768) {
            int cc = c - 256;
            int r = cc >> 2, q = cc & 3;
            int qq = q ^ ((r >> 1) & 3);
            CP_ASYNC16(stage + (uint32_t)D_ABYTES + (uint32_t)(r * 64 + qq * 16),
                       B1b + (size_t)r * ldB + k0 + q * 8);
        } else {
            int cc = c - 768;
            int r = cc >> 2, q = cc & 3;
            int qq = q ^ ((r >> 1) & 3);
            CP_ASYNC16(stage + (uint32_t)(D_ABYTES + D_BBYTES)
                             + (uint32_t)(r * 64 + qq * 16),
                       B2b + (size_t)r * ldB + k0 + q * 8);
        }
    }
    CP_COMMIT();
}

template <int EPI>
__global__ void __launch_bounds__(256)
dual_gemm(const __half* __restrict__ A,
          const __half* __restrict__ B1, const __half* __restrict__ B2,
          int ldA, int ldB, int iters,
          const float* __restrict__ bias1, const float* __restrict__ bias2,
          const __half* __restrict__ aux1, const float* __restrict__ aux2,
          float2* __restrict__ Cau, __half* __restrict__ Cp, int N) {
    extern __shared__ char smem[];
    uint32_t sb = smem_u32(smem);
    int tid = threadIdx.x;
    int wid = tid >> 5, lid = tid & 31;
    int wm = wid >> 2, wn = wid & 3;               // 2x4 over 64x128
    int lr = lid & 15, lc = lid >> 4;

    int bm = blockIdx.y, bn = blockIdx.x;
    const __half* Ab  = A  + (size_t)(bm * 64) * ldA;
    const __half* B1b = B1 + (size_t)(bn * 128) * ldB;
    const __half* B2b = B2 + (size_t)(bn * 128) * ldB;

    float acc1[2][4][4], acc2[2][4][4];
    #pragma unroll
    for (int i = 0; i < 2; i++)
        #pragma unroll
        for (int j = 0; j < 4; j++)
            #pragma unroll
            for (int q = 0; q < 4; q++) { acc1[i][j][q] = 0.f; acc2[i][j][q] = 0.f; }

    produce_stage_dual(sb, Ab, B1b, B2b, ldA, ldB, 0, tid);
    produce_stage_dual(sb, Ab, B1b, B2b, ldA, ldB, 1, tid);
    produce_stage_dual(sb, Ab, B1b, B2b, ldA, ldB, 2, tid);

    for (int it = 0; it < iters; ++it) {
        CP_WAIT2();
        __syncthreads();
        uint32_t sa  = sb + (uint32_t)(it & 3) * D_STAGE;
        uint32_t sb1 = sa + (uint32_t)D_ABYTES;
        uint32_t sb2 = sb1 + (uint32_t)D_BBYTES;

        #pragma unroll
        for (int kk = 0; kk < 2; kk++) {
            int chunk = kk * 2 + lc;
            uint32_t a[2][4];
            #pragma unroll
            for (int mf = 0; mf < 2; mf++) {
                int row = wm * 32 + mf * 16 + lr;
                int qq = chunk ^ ((row >> 1) & 3);
                LDSM4(a[mf], sa + (uint32_t)(row * 64 + qq * 16));
            }
            uint32_t b1f[2][4], b2f[2][4];
            #pragma unroll
            for (int nf2 = 0; nf2 < 2; nf2++) {
                int row = wn * 32 + nf2 * 16 + lr;
                int qq = chunk ^ ((row >> 1) & 3);
                LDSM4(b1f[nf2], sb1 + (uint32_t)(row * 64 + qq * 16));
                LDSM4(b2f[nf2], sb2 + (uint32_t)(row * 64 + qq * 16));
            }
            #pragma unroll
            for (int mf = 0; mf < 2; mf++)
                #pragma unroll
                for (int nf = 0; nf < 4; nf++) {
                    int n2 = nf >> 1, sel = nf & 1;
                    MMA_F16(acc1[mf][nf], a[mf], b1f[n2][sel], b1f[n2][2 + sel]);
                    MMA_F16(acc2[mf][nf], a[mf], b2f[n2][sel], b2f[n2][2 + sel]);
                }
        }
        __syncthreads();
        int j = it + 3;
        if (j < iters) produce_stage_dual(sb, Ab, B1b, B2b, ldA, ldB, j, tid);
        else           CP_COMMIT();
    }

    int er = lid >> 2;
    int ec = (lid & 3) * 2;
    #pragma unroll
    for (int mf = 0; mf < 2; mf++) {
        #pragma unroll
        for (int nf = 0; nf < 4; nf++) {
            float* c1 = acc1[mf][nf];
            float* c2 = acc2[mf][nf];
            int row0 = bm * 64 + wm * 32 + mf * 16 + er;
            int col  = bn * 128 + wn * 32 + nf * 8 + ec;
            #pragma unroll
            for (int half = 0; half < 2; half++) {
                int row = row0 + half * 8;
                float v0 = c1[half * 2 + 0], v1 = c1[half * 2 + 1];
                float w0 = c2[half * 2 + 0], w1 = c2[half * 2 + 1];
                if (EPI == 0) {
                    float r0 = act_sigmoid(v0 + bias1[col]);
                    float r1 = act_sigmoid(v1 + bias1[col + 1]);
                    float i0 = act_sigmoid(w0 + bias2[col]);
                    float i1 = act_sigmoid(w1 + bias2[col + 1]);
                    size_t idx = (size_t)row * N + col;
                    __half2 cvh = *reinterpret_cast<const __half2*>(aux1 + idx);
                    float cv0 = __half2float(__low2half(cvh));
                    float cv1 = __half2float(__high2half(cvh));
                    float ll0 = aux2[col], ll1 = aux2[col + 1];
                    float ls0 = -log1pf(expf(-ll0));
                    float ls1 = -log1pf(expf(-ll1));
                    float a0 = expf(C_EXP * r0 * ls0);
                    float a1 = expf(C_EXP * r1 * ls1);
                    float gt0 = sqrtf(fmaxf((1.0f - a0) * (1.0f + a0), 1e-6f));
                    float gt1 = sqrtf(fmaxf((1.0f - a1) * (1.0f + a1), 1e-6f));
                    Cau[idx]     = make_float2(a0, gt0 * (i0 * cv0));
                    Cau[idx + 1] = make_float2(a1, gt1 * (i1 * cv1));
                } else {
                    float p0 = act_gelu(v0) * w0;
                    float p1 = act_gelu(v1) * w1;
                    *reinterpret_cast<__half2*>(Cp + (size_t)row * N + col) =
                        __halves2half2(__float2half_rn(p0), __float2half_rn(p1));
                }
            }
        }
    }
}

// ---------------------------------------------------------------------------
// RMSNorm -> fp16
// ---------------------------------------------------------------------------
__global__ void rmsnorm_hi_kernel(const float* __restrict__ x,
                                  const float* __restrict__ w,
                                  __half* __restrict__ outh) {
    int row = blockIdx.x;
    int tid = threadIdx.x;
    const float4* xr = reinterpret_cast<const float4*>(x + (size_t)row * D);
    float4 v = xr[tid];
    float s = v.x * v.x + v.y * v.y + v.z * v.z + v.w * v.w;
    #pragma unroll
    for (int o = 16; o > 0; o >>= 1) s += __shfl_xor_sync(0xffffffffu, s, o);
    __shared__ float sm[8];
    if ((tid & 31) == 0) sm[tid >> 5] = s;
    __syncthreads();
    float tot = 0.f;
    #pragma unroll
    for (int i = 0; i < 8; i++) tot += sm[i];
    float scale = rsqrtf(tot * (1.0f / D) + EPS);
    float4 wv = reinterpret_cast<const float4*>(w)[tid];
    __half2* hp = reinterpret_cast<__half2*>(outh + (size_t)row * D + tid * 4);
    hp[0] = __halves2half2(__float2half_rn(v.x * scale * wv.x),
                           __float2half_rn(v.y * scale * wv.y));
    hp[1] = __halves2half2(__float2half_rn(v.z * scale * wv.z),
                           __float2half_rn(v.w * scale * wv.w));
}

// ---------------------------------------------------------------------------
// Fused weight conversion (8 weights, 1 launch)
// ---------------------------------------------------------------------------
constexpr size_t WCH_S = (size_t)D * D / 4;
constexpr size_t WCH_L = (size_t)H * D / 4;
constexpr size_t WCH_TOTAL = 5 * WCH_S + 3 * WCH_L;

__global__ void whi_all_kernel(const float* __restrict__ W1,
                               const float* __restrict__ Wa,
                               const float* __restrict__ Wx,
                               const float* __restrict__ W2,
                               const float* __restrict__ Wout,
                               const float* __restrict__ Wg,
                               const float* __restrict__ Wu,
                               const float* __restrict__ Wo) {
    size_t c = (size_t)blockIdx.x * blockDim.x + threadIdx.x;
    if (c >= WCH_TOTAL) return;
    const float* src;
    __half* dst;
    size_t off;
    if (c < 5 * WCH_S) {
        int seg = (int)(c / WCH_S);
        off = c % WCH_S;
        src = (seg == 0) ? W1 : (seg == 1) ? Wa : (seg == 2) ? Wx
            : (seg == 3) ? W2 : Wout;
        dst = (seg == 0) ? g_w1h : (seg == 1) ? g_wah : (seg == 2) ? g_wxh
            : (seg == 3) ? g_w2h : g_wouth;
    } else {
        size_t c2 = c - 5 * WCH_S;
        int seg = (int)(c2 / WCH_L);
        off = c2 % WCH_L;
        src = (seg == 0) ? Wg : (seg == 1) ? Wu : Wo;
        dst = (seg == 0) ? g_wgh : (seg == 1) ? g_wuh : g_woh;
    }
    float4 v = reinterpret_cast<const float4*>(src)[off];
    __half2* o = reinterpret_cast<__half2*>(dst + off * 4);
    o[0] = __halves2half2(__float2half_rn(v.x), __float2half_rn(v.y));
    o[1] = __halves2half2(__float2half_rn(v.z), __float2half_rn(v.w));
}

// ---------------------------------------------------------------------------
// Conv (rolling window, fp16-only output, fused conv_buf out)
// ---------------------------------------------------------------------------
__device__ __forceinline__ float4 f4fma(float4 a, float4 b, float4 c) {
    return make_float4(fmaf(a.x, b.x, c.x), fmaf(a.y, b.y, c.y),
                       fmaf(a.z, b.z, c.z), fmaf(a.w, b.w, c.w));
}

__global__ void conv_kernel(const float* __restrict__ conv_buf,
                            const float* __restrict__ conv_w,
                            const float* __restrict__ conv_b,
                            float* __restrict__ out_cb) {
    int b   = blockIdx.y;
    int tc0 = blockIdx.x * 16;
    int d   = threadIdx.x * 4;

    float4 cwr0 = reinterpret_cast<const float4*>(conv_w)[d + 0];
    float4 cwr1 = reinterpret_cast<const float4*>(conv_w)[d + 1];
    float4 cwr2 = reinterpret_cast<const float4*>(conv_w)[d + 2];
    float4 cwr3 = reinterpret_cast<const float4*>(conv_w)[d + 3];
    float4 w0 = make_float4(cwr0.x, cwr1.x, cwr2.x, cwr3.x);
    float4 w1 = make_float4(cwr0.y, cwr1.y, cwr2.y, cwr3.y);
    float4 w2 = make_float4(cwr0.z, cwr1.z, cwr2.z, cwr3.z);
    float4 w3 = make_float4(cwr0.w, cwr1.w, cwr2.w, cwr3.w);
    float4 cb = *reinterpret_cast<const float4*>(conv_b + d);

    const float* b1base = g_b1 + (size_t)b * T * D;
    float4 p3, p2, p1;
    if (tc0 == 0) {
        p3 = *reinterpret_cast<const float4*>(conv_buf + ((size_t)b * 3 + 0) * D + d);
        p2 = *reinterpret_cast<const float4*>(conv_buf + ((size_t)b * 3 + 1) * D + d);
        p1 = *reinterpret_cast<const float4*>(conv_buf + ((size_t)b * 3 + 2) * D + d);
    } else {
        p3 = *reinterpret_cast<const float4*>(b1base + (size_t)(tc0 - 3) * D + d);
        p2 = *reinterpret_cast<const float4*>(b1base + (size_t)(tc0 - 2) * D + d);
        p1 = *reinterpret_cast<const float4*>(b1base + (size_t)(tc0 - 1) * D + d);
    }

    #pragma unroll
    for (int tt = 0; tt < 16; tt++) {
        int t = tc0 + tt;
        float4 cur = *reinterpret_cast<const float4*>(b1base + (size_t)t * D + d);
        float4 o = cb;
        o = f4fma(w0, p3, o);
        o = f4fma(w1, p2, o);
        o = f4fma(w2, p1, o);
        o = f4fma(w3, cur, o);
        size_t gidx = ((size_t)b * T + t) * D + d;
        __half2* hp = reinterpret_cast<__half2*>(g_conv_h + gidx);
        hp[0] = __halves2half2(__float2half_rn(o.x), __float2half_rn(o.y));
        hp[1] = __halves2half2(__float2half_rn(o.z), __float2half_rn(o.w));
        if (t >= T - 3) {
            *reinterpret_cast<float4*>(out_cb + ((size_t)b * 3 + (t - (T - 3))) * D + d) = cur;
        }
        p3 = p2; p2 = p1; p1 = cur;
    }
}

// ---------------------------------------------------------------------------
// Parallel scan (8 segments, 3 passes); emit fuses prod = h * gelu_b2 in-place.
// ---------------------------------------------------------------------------
__global__ void scan_seg_kernel() {
    int g = blockIdx.x * blockDim.x + threadIdx.x;   // B*SC*D
    int d = g % D;
    int c = (g / D) % SC;
    int b = g / (SC * D);
    const float2* au = g_au + ((size_t)b * T + (size_t)c * SL) * D + d;
    float A = 1.0f, U = 0.0f;
    #pragma unroll 8
    for (int t = 0; t < SL; t++) {
        float2 v = au[(size_t)t * D];
        A *= v.x;
        U = fmaf(v.x, U, v.y);
    }
    g_seg[g] = make_float2(A, U);
}

__global__ void scan_combine_kernel(const float* __restrict__ h0,
                                    float* __restrict__ out_h) {
    int g = blockIdx.x * blockDim.x + threadIdx.x;   // B*D
    int d = g % D;
    int b = g / D;
    float h = h0[g];
    #pragma unroll
    for (int c = 0; c < SC; c++) {
        size_t si = ((size_t)b * SC + c) * D + d;
        g_hstart[si] = h;
        float2 s = g_seg[si];
        h = fmaf(s.x, h, s.y);
    }
    out_h[g] = h;
}

__global__ void scan_emit_kernel() {
    int g = blockIdx.x * blockDim.x + threadIdx.x;   // B*SC*D
    int d = g % D;
    int c = (g / D) % SC;
    int b = g / (SC * D);
    size_t base = ((size_t)b * T + (size_t)c * SL) * D + d;
    const float2* au = g_au + base;
    __half* p = g_prod_h + base;
    float h = g_hstart[g];
    #pragma unroll 8
    for (int t = 0; t < SL; t++) {
        float2 v = au[(size_t)t * D];
        h = fmaf(v.x, h, v.y);
        float b2v = __half2float(p[(size_t)t * D]);
        p[(size_t)t * D] = __float2half_rn(h * b2v);
    }
}

// ---------------------------------------------------------------------------
// Launch
// ---------------------------------------------------------------------------
extern "C" void kernel_launch(void* const* d_in, const int* in_sizes, int n_in,
                              void* d_out, int out_size) {
    const float* x_seq      = (const float*)d_in[0];
    const float* h0         = (const float*)d_in[1];
    const float* conv_buf   = (const float*)d_in[2];
    const float* norm1_w    = (const float*)d_in[3];
    const float* W1         = (const float*)d_in[4];
    const float* conv_w     = (const float*)d_in[5];
    const float* conv_b     = (const float*)d_in[6];
    const float* Wa         = (const float*)d_in[7];
    const float* ba         = (const float*)d_in[8];
    const float* Wx         = (const float*)d_in[9];
    const float* bx         = (const float*)d_in[10];
    const float* log_lambda = (const float*)d_in[11];
    const float* W2         = (const float*)d_in[12];
    const float* Wout       = (const float*)d_in[13];
    const float* norm2_w    = (const float*)d_in[14];
    const float* Wg         = (const float*)d_in[15];
    const float* Wu         = (const float*)d_in[16];
    const float* Wo         = (const float*)d_in[17];

    float* out_x2 = (float*)d_out;
    float* out_h  = out_x2 + (size_t)M * D;
    float* out_cb = out_h + (size_t)B * D;

    __half *p_normed, *p_convh, *p_prodh, *p_n2h, *p_acth;
    __half *p_w1, *p_wa, *p_wx, *p_w2, *p_wout, *p_wg, *p_wu, *p_wo;
    float *p_b1, *p_x1;
    float2 *p_au;
    cudaGetSymbolAddress((void**)&p_normed, g_normed_h);
    cudaGetSymbolAddress((void**)&p_convh,  g_conv_h);
    cudaGetSymbolAddress((void**)&p_prodh,  g_prod_h);
    cudaGetSymbolAddress((void**)&p_n2h,    g_n2_h);
    cudaGetSymbolAddress((void**)&p_acth,   g_act_h);
    cudaGetSymbolAddress((void**)&p_w1,     g_w1h);
    cudaGetSymbolAddress((void**)&p_wa,     g_wah);
    cudaGetSymbolAddress((void**)&p_wx,     g_wxh);
    cudaGetSymbolAddress((void**)&p_w2,     g_w2h);
    cudaGetSymbolAddress((void**)&p_wout,   g_wouth);
    cudaGetSymbolAddress((void**)&p_wg,     g_wgh);
    cudaGetSymbolAddress((void**)&p_wu,     g_wuh);
    cudaGetSymbolAddress((void**)&p_wo,     g_woh);
    cudaGetSymbolAddress((void**)&p_b1,     g_b1);
    cudaGetSymbolAddress((void**)&p_au,     g_au);
    cudaGetSymbolAddress((void**)&p_x1,     g_x1);

    auto kPlain  = gemm_mma<0, 0, false, 0, false>;  // b1 -> fp32
    auto kGeluH  = gemm_mma<2, 0, false, 2, false>;  // gelu(b2) -> fp16
    auto kAdd    = gemm_mma<0, 1, false, 0, false>;  // x1, x2
    auto kDualAU = dual_gemm<0>;
    auto kDualGU = dual_gemm<1>;
    cudaFuncSetAttribute(kPlain,  cudaFuncAttributeMaxDynamicSharedMemorySize, SMEM_B);
    cudaFuncSetAttribute(kGeluH,  cudaFuncAttributeMaxDynamicSharedMemorySize, SMEM_B);
    cudaFuncSetAttribute(kAdd,    cudaFuncAttributeMaxDynamicSharedMemorySize, SMEM_B);
    cudaFuncSetAttribute(kDualAU, cudaFuncAttributeMaxDynamicSharedMemorySize, D_SMEM);
    cudaFuncSetAttribute(kDualGU, cudaFuncAttributeMaxDynamicSharedMemorySize, D_SMEM);

    dim3 gD(D / 128, M / 128);       // (8, 128)
    dim3 gDd(D / 128, M / 64);       // (8, 256)
    dim3 gHd(H / 128, M / 64);       // (32, 256)

    // 1. normed = rmsnorm(x_seq) -> fp16
    rmsnorm_hi_kernel<<<M, 256>>>(x_seq, norm1_w, p_normed);
    // 2. weight conversions
    whi_all_kernel<<<(int)((WCH_TOTAL + 255) / 256), 256>>>(W1, Wa, Wx, W2, Wout, Wg, Wu, Wo);
    // 3. b1 = normed @ W1^T -> fp32
    kPlain<<<gD, 256, SMEM_B>>>(p_normed, p_w1, D, D, 32,
                                nullptr, nullptr, p_b1, nullptr, D, 0);
    // 4. b2h = gelu(normed @ W2^T) -> fp16 (into prod buffer)
    kGeluH<<<gD, 256, SMEM_B>>>(p_normed, p_w2, D, D, 32,
                                nullptr, nullptr, nullptr, p_prodh, D, D);
    // 5. conv (fp16 out, fused out_cb)
    conv_kernel<<<dim3(T / 16, B), 256>>>(conv_buf, conv_w, conv_b, out_cb);
    // 6. dual r/i GEMM + a/u epilogue -> g_au
    kDualAU<<<gDd, 256, D_SMEM>>>(p_convh, p_wa, p_wx, D, D, 32,
                                  ba, bx, p_convh, log_lambda, p_au, nullptr, D);
    // 7-9. parallel scan; emit fuses prod = h * b2h (in-place)
    scan_seg_kernel<<<(B * SC * D) / 256, 256>>>();
    scan_combine_kernel<<<(B * D) / 256, 256>>>(h0, out_h);
    scan_emit_kernel<<<(B * SC * D) / 256, 256>>>();
    // 10. x1 = x_seq + prod @ Wout^T -> fp32
    kAdd<<<gD, 256, SMEM_B>>>(p_prodh, p_wout, D, D, 32,
                              nullptr, x_seq, p_x1, nullptr, D, 0);
    // 11. n2 = rmsnorm(x1) -> fp16
    rmsnorm_hi_kernel<<<M, 256>>>(p_x1, norm2_w, p_n2h);
    // 12. dual Wg/Wu GEMM + gelu-mul epilogue -> act_h
    kDualGU<<<gHd, 256, D_SMEM>>>(p_n2h, p_wg, p_wu, D, D, 32,
                                  nullptr, nullptr, nullptr, nullptr,
                                  nullptr, p_acth, H);
    // 13. x2 = x1 + act @ Wo^T -> out
    kAdd<<<gD, 256, SMEM_B>>>(p_acth, p_wo, H, H, 128,
                              nullptr, p_x1, out_x2, nullptr, D, 0);
}